// round 10
// baseline (speedup 1.0000x reference)
#include <cuda_runtime.h>
#include <cuda_bf16.h>
#include <cstdint>
#include <math.h>

#define Bsz   8
#define Lseq  2048
#define Hdim  512
#define Nst   64
#define NROW  (Bsz*Lseq)          // 16384
#define BLH   (Bsz*Lseq*Hdim)     // 8388608
#define HH    (Hdim*Hdim)
#define HN    (Hdim*Nst)
#define KDSZ  (Hdim*2049)

// ----------------- device scratch (no allocations allowed) ------------------
__device__ float  g_x [BLH];
__device__ float  g_h [BLH];
__device__ float  g_ht[BLH];
__device__ float  g_yt[BLH];
__device__ float  g_v [BLH];
__device__ float  g_z1[BLH];
__device__ float2 g_ar[Hdim*Lseq];
__device__ float2 g_KdL[4*KDSZ];
__device__ float2 g_twA[1024];
__device__ float2 g_twB[2048];
__device__ __nv_bfloat16 g_a0[BLH];
__device__ __nv_bfloat16 g_a1[BLH];
__device__ __nv_bfloat16 g_b0[BLH];
__device__ __nv_bfloat16 g_b1[BLH];
__device__ __nv_bfloat16 g_wt0[12*HH];
__device__ __nv_bfloat16 g_wt1[12*HH];

// ----------------- helpers --------------------------------------------------
__device__ __forceinline__ float2 cadd(float2 a, float2 b){ return make_float2(a.x+b.x, a.y+b.y); }
__device__ __forceinline__ float2 csub(float2 a, float2 b){ return make_float2(a.x-b.x, a.y-b.y); }
__device__ __forceinline__ float2 cmul(float2 a, float2 b){ return make_float2(a.x*b.x-a.y*b.y, a.x*b.y+a.y*b.x); }
__device__ __forceinline__ float frcp_fast(float x){ float y; asm("rcp.approx.f32 %0, %1;" : "=f"(y) : "f"(x)); return y; }
__device__ __forceinline__ float gelu_f(float x){
  float u = 0.7978845608028654f*(x + 0.044715f*x*x*x);
  float e = __expf(2.f*u);
  float t = 1.f - 2.f/(e + 1.f);          // tanh(u), saturates correctly
  return 0.5f*x*(1.0f + t);
}
__device__ __forceinline__ float sigm_f(float x){ return 1.0f/(1.0f + __expf(-x)); }

__device__ __forceinline__ uint32_t smem_u32(const void* p){
  uint32_t a;
  asm("{ .reg .u64 t; cvta.to.shared.u64 t, %1; cvt.u32.u64 %0, t; }" : "=r"(a) : "l"(p));
  return a;
}
__device__ __forceinline__ void cp16(uint32_t saddr, const void* g){
  asm volatile("cp.async.ca.shared.global [%0], [%1], 16;" :: "r"(saddr), "l"(g));
}
#define CP_COMMIT() asm volatile("cp.async.commit_group;" ::: "memory")

__device__ __forceinline__ void ldsm4(uint32_t* r, uint32_t addr){
  asm volatile("ldmatrix.sync.aligned.m8n8.x4.shared.b16 {%0,%1,%2,%3}, [%4];"
    : "=r"(r[0]), "=r"(r[1]), "=r"(r[2]), "=r"(r[3]) : "r"(addr));
}
__device__ __forceinline__ void mma16816(float* c, const uint32_t* a, const uint32_t* b){
  asm volatile("mma.sync.aligned.m16n8k16.row.col.f32.bf16.bf16.f32 "
    "{%0,%1,%2,%3}, {%4,%5,%6,%7}, {%8,%9}, {%0,%1,%2,%3};"
    : "+f"(c[0]), "+f"(c[1]), "+f"(c[2]), "+f"(c[3])
    : "r"(a[0]), "r"(a[1]), "r"(a[2]), "r"(a[3]), "r"(b[0]), "r"(b[1]));
}

// ----------------- twiddle init ---------------------------------------------
__global__ void init_tw_kernel(){
  int i = blockIdx.x*256 + threadIdx.x;
  if (i < 1024){
    float a = (float)(6.283185307179586/2048.0) * (float)i;
    float s, c; sincosf(a, &s, &c);
    g_twA[i] = make_float2(c, -s);
  }
  if (i < 2048){
    float a = (float)(3.141592653589793/2048.0) * (float)i;
    float s, c; sincosf(a, &s, &c);
    g_twB[i] = make_float2(c, -s);
  }
}

// ----------------- layernorm: xin -> g_h (+ optional bf16 split) ------------
__global__ __launch_bounds__(256) void ln_kernel(const float* __restrict__ xin,
                                                 const float* __restrict__ sc,
                                                 const float* __restrict__ bi,
                                                 int wsplit){
  int warp = threadIdx.x >> 5, lane = threadIdx.x & 31;
  size_t row = (size_t)blockIdx.x*8 + warp;
  const float4* xr = (const float4*)(xin + row*Hdim);
  float4 v[4];
  float s = 0.f, s2 = 0.f;
  #pragma unroll
  for (int i = 0; i < 4; i++){
    float4 t = xr[lane + 32*i];
    v[i] = t;
    s  += t.x + t.y + t.z + t.w;
    s2 += t.x*t.x + t.y*t.y + t.z*t.z + t.w*t.w;
  }
  #pragma unroll
  for (int o = 16; o; o >>= 1){
    s  += __shfl_xor_sync(0xffffffffu, s,  o);
    s2 += __shfl_xor_sync(0xffffffffu, s2, o);
  }
  float mean = s*(1.f/Hdim);
  float var  = s2*(1.f/Hdim) - mean*mean;
  float inv  = rsqrtf(var + 1e-6f);
  float4* orow = (float4*)(g_h + row*Hdim);
  const float4* s4 = (const float4*)sc;
  const float4* b4 = (const float4*)bi;
  #pragma unroll
  for (int i = 0; i < 4; i++){
    int ci = lane + 32*i;
    float4 sv = s4[ci], bv = b4[ci], t = v[i], o;
    o.x = (t.x-mean)*inv*sv.x + bv.x;
    o.y = (t.y-mean)*inv*sv.y + bv.y;
    o.z = (t.z-mean)*inv*sv.z + bv.z;
    o.w = (t.w-mean)*inv*sv.w + bv.w;
    orow[ci] = o;
    if (wsplit){
      size_t gi = row*Hdim + ci*4;
      __nv_bfloat16 h0 = __float2bfloat16_rn(o.x);
      __nv_bfloat16 h1 = __float2bfloat16_rn(o.y);
      __nv_bfloat16 h2 = __float2bfloat16_rn(o.z);
      __nv_bfloat16 h3 = __float2bfloat16_rn(o.w);
      __nv_bfloat162 p0; p0.x = h0; p0.y = h1;
      __nv_bfloat162 p1; p1.x = h2; p1.y = h3;
      *(__nv_bfloat162*)(g_a0 + gi)     = p0;
      *(__nv_bfloat162*)(g_a0 + gi + 2) = p1;
      __nv_bfloat162 q0, q1;
      q0.x = __float2bfloat16_rn(o.x - __bfloat162float(h0));
      q0.y = __float2bfloat16_rn(o.y - __bfloat162float(h1));
      q1.x = __float2bfloat16_rn(o.z - __bfloat162float(h2));
      q1.y = __float2bfloat16_rn(o.w - __bfloat162float(h3));
      *(__nv_bfloat162*)(g_a1 + gi)     = q0;
      *(__nv_bfloat162*)(g_a1 + gi + 2) = q1;
    }
  }
}

// ----------------- transposes -----------------------------------------------
__global__ void transpose_fwd_kernel(){
  __shared__ float tile[32][33];
  int b  = blockIdx.z;
  int h0 = blockIdx.x*32;
  int l0 = blockIdx.y*32;
  int tx = threadIdx.x, ty = threadIdx.y;
  const float* in = g_h + (size_t)b*Lseq*Hdim;
  float* out = g_ht + (size_t)b*Hdim*Lseq;
  #pragma unroll
  for (int j = 0; j < 32; j += 8)
    tile[ty+j][tx] = in[(size_t)(l0+ty+j)*Hdim + h0 + tx];
  __syncthreads();
  #pragma unroll
  for (int j = 0; j < 32; j += 8)
    out[(size_t)(h0+ty+j)*Lseq + l0 + tx] = tile[tx][ty+j];
}

__global__ void transpose_bwd_kernel(const float* __restrict__ D){
  __shared__ float tile[32][33];
  int b  = blockIdx.z;
  int h0 = blockIdx.x*32;
  int l0 = blockIdx.y*32;
  int tx = threadIdx.x, ty = threadIdx.y;
  const float* in = g_yt + (size_t)b*Hdim*Lseq;
  float* out = g_v + (size_t)b*Lseq*Hdim;
  const float* hbuf = g_h + (size_t)b*Lseq*Hdim;
  #pragma unroll
  for (int j = 0; j < 32; j += 8)
    tile[ty+j][tx] = in[(size_t)(h0+ty+j)*Lseq + l0 + tx];
  __syncthreads();
  size_t boff = (size_t)b*Lseq*Hdim;
  #pragma unroll
  for (int j = 0; j < 32; j += 8){
    size_t idx = (size_t)(l0+ty+j)*Hdim + h0 + tx;
    float y = tile[tx][ty+j] + D[h0+tx]*hbuf[idx];
    float g = gelu_f(y);
    out[idx] = g;
    __nv_bfloat16 hi = __float2bfloat16_rn(g);
    float r = g - __bfloat162float(hi);
    g_a0[boff + idx] = hi;
    g_a1[boff + idx] = __float2bfloat16_rn(r);
  }
}

// ----------------- weight transpose + split ----------------------------------
__global__ void wprep_kernel(const float* __restrict__ W, int widx){
  __shared__ float tile[32][33];
  int n0 = blockIdx.x*32, k0 = blockIdx.y*32;
  int tx = threadIdx.x, ty = threadIdx.y;
  #pragma unroll
  for (int j = 0; j < 32; j += 8)
    tile[ty+j][tx] = W[(size_t)(k0+ty+j)*Hdim + n0 + tx];
  __syncthreads();
  size_t base = (size_t)widx*HH;
  #pragma unroll
  for (int j = 0; j < 32; j += 8){
    float a = tile[tx][ty+j];
    size_t o = base + (size_t)(n0+ty+j)*Hdim + k0 + tx;
    __nv_bfloat16 hi = __float2bfloat16_rn(a);
    g_wt0[o] = hi;
    g_wt1[o] = __float2bfloat16_rn(a - __bfloat162float(hi));
  }
}

// ----------------- Cauchy kernel (prep fused in) -----------------------------
__global__ __launch_bounds__(256) void cauchy_kernel(
    const float* __restrict__ Lre, const float* __restrict__ Lim,
    const float* __restrict__ Pre, const float* __restrict__ Pim,
    const float* __restrict__ Bre, const float* __restrict__ Bim,
    const float* __restrict__ Cre, const float* __restrict__ Cim,
    const float* __restrict__ logstep){
  __shared__ float4 spk01[Nst];
  __shared__ float4 spk23[Nst];
  __shared__ float2 slam [Nst];
  __shared__ float  s2step;
  int tid = threadIdx.x;
  int h = blockIdx.y;
  int l = blockIdx.x*256 + tid;
  if (tid < Nst){
    int i = h*Nst + tid;
    float pr = Pre[i], pi = Pim[i];
    float br = Bre[i], bi = Bim[i];
    float cr = Cre[i], ci = Cim[i];
    spk01[tid] = make_float4(cr*br + ci*bi, cr*bi - ci*br,
                             cr*pr + ci*pi, cr*pi - ci*pr);
    spk23[tid] = make_float4(pr*br + pi*bi, pr*bi - pi*br,
                             pr*pr + pi*pi, 0.f);
    slam [tid] = make_float2(fminf(Lre[i], -1e-4f), Lim[i]);
  }
  if (tid == 0) s2step = 2.f*expf(-logstep[h]);
  __syncthreads();
  float t   = tanf((float)(3.141592653589793/2048.0)*(float)l);
  float gim = s2step*t;
  float k00r=0.f,k00i=0.f,k01r=0.f,k01i=0.f,k10r=0.f,k10i=0.f,k11r=0.f,k11i=0.f;
  #pragma unroll 8
  for (int n = 0; n < Nst; n++){
    float2 lam = slam[n];
    float dre = -lam.x;
    float dim = gim - lam.y;
    float inv = frcp_fast(dre*dre + dim*dim);
    float ir  =  dre*inv;
    float ii  = -dim*inv;
    float4 w01 = spk01[n];
    float4 w23 = spk23[n];
    k00r += w01.x*ir - w01.y*ii;  k00i += w01.x*ii + w01.y*ir;
    k01r += w01.z*ir - w01.w*ii;  k01i += w01.z*ii + w01.w*ir;
    k10r += w23.x*ir - w23.y*ii;  k10i += w23.x*ii + w23.y*ir;
    k11r += w23.z*ir;             k11i += w23.z*ii;
  }
  float denr = 1.f + k11r, deni = k11i;
  float dinv = frcp_fast(denr*denr + deni*deni);
  float qr = denr*dinv, qi = -deni*dinv;
  float mr = k01r*k10r - k01i*k10i;
  float mi = k01r*k10i + k01i*k10r;
  float cr = mr*qr - mi*qi, ci2 = mr*qi + mi*qr;
  float ar = k00r - cr, ai = k00i - ci2;
  g_ar[(size_t)h*Lseq + l] = make_float2(ar - t*ai, ai + t*ar);
}

// ----------------- shared-mem radix-4 Stockham FFT(2048) ---------------------
template<bool INV>
__device__ __forceinline__ float2* fft2048_r4(float2* buf0, float2* buf1,
                                              const float2* stw, int tid){
  float2* src = buf0; float2* dst = buf1;
  #pragma unroll
  for (int st = 0; st < 5; st++){
    int s = 1 << (2*st);
    __syncthreads();
    #pragma unroll
    for (int i = 0; i < 2; i++){
      int idx = tid + 256*i;
      int sp  = idx & ~(s-1);
      float2 a0 = src[idx];
      float2 a1 = src[idx + 512];
      float2 a2 = src[idx + 1024];
      float2 a3 = src[idx + 1536];
      float2 w1 = stw[sp];
      float2 w2 = stw[2*sp];
      if (INV){ w1.y = -w1.y; w2.y = -w2.y; }
      float2 w3 = cmul(w1, w2);
      float2 t0 = cadd(a0, a2), t1 = csub(a0, a2);
      float2 t2 = cadd(a1, a3), t3 = csub(a1, a3);
      float2 b0 = cadd(t0, t2);
      float2 b2 = csub(t0, t2);
      float2 b1, b3;
      if (!INV){
        b1 = make_float2(t1.x + t3.y, t1.y - t3.x);
        b3 = make_float2(t1.x - t3.y, t1.y + t3.x);
      } else {
        b1 = make_float2(t1.x - t3.y, t1.y + t3.x);
        b3 = make_float2(t1.x + t3.y, t1.y - t3.x);
      }
      int j = idx + 3*sp;
      dst[j]       = b0;
      dst[j + s]   = cmul(b1, w1);
      dst[j + 2*s] = cmul(b2, w2);
      dst[j + 3*s] = cmul(b3, w3);
    }
    float2* tp = src; src = dst; dst = tp;
  }
  __syncthreads();
  #pragma unroll
  for (int i = 0; i < 4; i++){
    int idx = tid + 256*i;
    float2 a = src[idx];
    float2 b = src[idx + 1024];
    dst[idx]        = cadd(a, b);
    dst[idx + 1024] = csub(a, b);
  }
  float2* tp = src; src = dst; dst = tp;
  __syncthreads();
  return src;
}

// ----------------- Kd kernel ------------------------------------------------
__global__ __launch_bounds__(256) void kd_kernel(float2* __restrict__ Kd){
  __shared__ float2 sA[2048];
  __shared__ float2 sB[2048];
  __shared__ float2 stw[1024];
  int tid = threadIdx.x;
  int h = blockIdx.x;
  for (int i = tid; i < 1024; i += 256) stw[i] = g_twA[i];
  const float2* ar = g_ar + (size_t)h*Lseq;
  #pragma unroll
  for (int i = 0; i < 8; i++){ int k = tid + 256*i; sA[k] = ar[k]; }
  float2* K = fft2048_r4<true>(sA, sB, stw, tid);
  float2* Ob = (K == sA) ? sB : sA;
  const float sc = 1.f/2048.f;
  #pragma unroll
  for (int i = 0; i < 8; i++){
    int n = tid + 256*i;
    float2 v = make_float2(0.f, 0.f);
    if (n < 1024) v = make_float2(K[2*n].x*sc, K[2*n+1].x*sc);
    Ob[n] = v;
  }
  float2* Zp = fft2048_r4<false>(Ob, K, stw, tid);
  float2* outKd = Kd + (size_t)h*2049;
  #pragma unroll
  for (int i = 0; i < 8; i++){
    int k  = tid + 256*i;
    int kc = (2048 - k) & 2047;
    float2 zk = Zp[k], zc = Zp[kc];
    float2 E  = make_float2(0.5f*(zk.x+zc.x),  0.5f*(zk.y-zc.y));
    float2 Od = make_float2(0.5f*(zk.y+zc.y), -0.5f*(zk.x-zc.x));
    outKd[k] = cadd(E, cmul(g_twB[k], Od));
  }
  if (tid == 0){
    float2 z0 = Zp[0];
    outKd[2048] = make_float2(z0.x - z0.y, 0.f);
  }
}

// ----------------- conv kernel ----------------------------------------------
__global__ __launch_bounds__(256) void conv_kernel(const float2* __restrict__ Kdbase){
  __shared__ float2 sA[2048];
  __shared__ float2 sB[2048];
  __shared__ float2 stw[1024];
  __shared__ float2 sY2048;
  int tid = threadIdx.x;
  int h = blockIdx.x;
  int b = blockIdx.y;
  const float* u = g_ht + ((size_t)b*Hdim + h)*Lseq;
  for (int i = tid; i < 1024; i += 256) stw[i] = g_twA[i];
  #pragma unroll
  for (int i = 0; i < 4; i++){
    int n = tid + 256*i;
    sA[n]        = make_float2(u[2*n], u[2*n+1]);
    sA[n + 1024] = make_float2(0.f, 0.f);
  }
  float2* Z = fft2048_r4<false>(sA, sB, stw, tid);
  float2* O = (Z == sA) ? sB : sA;
  const float2* kd = Kdbase + (size_t)h*2049;
  #pragma unroll
  for (int i = 0; i < 8; i++){
    int k  = tid + 256*i;
    int kc = (2048 - k) & 2047;
    float2 zk = Z[k], zc = Z[kc];
    float2 E  = make_float2(0.5f*(zk.x+zc.x),  0.5f*(zk.y-zc.y));
    float2 Od = make_float2(0.5f*(zk.y+zc.y), -0.5f*(zk.x-zc.x));
    float2 U  = cadd(E, cmul(g_twB[k], Od));
    O[k] = cmul(U, kd[k]);
  }
  if (tid == 0){
    float2 z0 = Z[0];
    float U2048 = z0.x - z0.y;
    float2 kv = kd[2048];
    sY2048 = make_float2(U2048*kv.x, U2048*kv.y);
  }
  __syncthreads();
  #pragma unroll
  for (int i = 0; i < 8; i++){
    int k = tid + 256*i;
    float2 Yk = O[k];
    float2 Yc = (k == 0) ? sY2048 : O[2048 - k];
    float2 Ey = make_float2(0.5f*(Yk.x+Yc.x), 0.5f*(Yk.y-Yc.y));
    float2 Dm = make_float2(0.5f*(Yk.x-Yc.x), 0.5f*(Yk.y+Yc.y));
    float2 tb = g_twB[k];
    float2 Oy = cmul(Dm, make_float2(tb.x, -tb.y));
    Z[k] = make_float2(Ey.x - Oy.y, Ey.y + Oy.x);
  }
  float2* w = fft2048_r4<true>(Z, O, stw, tid);
  float* out = g_yt + ((size_t)b*Hdim + h)*Lseq;
  const float sc = 1.f/2048.f;
  #pragma unroll
  for (int i = 0; i < 4; i++){
    int n = tid + 256*i;
    float2 v = w[n];
    out[2*n]   = v.x*sc;
    out[2*n+1] = v.y*sc;
  }
}

// ----------------- HMMA GEMM: 128x128 tile, bf16x3, K-chunk 64 ---------------
// mode 0: C = acc+bias            mode 1: C = gelu(acc+bias)
// mode 2: C = resid + aux*sigmoid(acc+bias)   mode 3: C = resid + acc+bias
#define TROW    144                     // 128B real (64 bf16) + 16B pad
#define TBYTES  (128*TROW)              // 18432 per tile
#define STAGEB  (4*TBYTES)              // 73728 (A0,A1,B0,B1)
#define SMEM_GEMM (2*STAGEB)            // 147456

__global__ __launch_bounds__(256) void hgemm_kernel(
    const __nv_bfloat16* __restrict__ A0g, const __nv_bfloat16* __restrict__ A1g,
    const __nv_bfloat16* __restrict__ B0g, const __nv_bfloat16* __restrict__ B1g,
    const float* __restrict__ bias, const float* __restrict__ aux,
    const float* __restrict__ resid,
    float* __restrict__ C, int mode,
    __nv_bfloat16* __restrict__ S0, __nv_bfloat16* __restrict__ S1)
{
  extern __shared__ char smem[];
  uint32_t sb = smem_u32(smem);
  int tid = threadIdx.x, wid = tid >> 5, lid = tid & 31;
  int bn = blockIdx.x*128, bm = blockIdx.y*128;
  int mw = wid & 3, nw = wid >> 2;

  int lrow = tid >> 1;                 // 0..127
  int lc0  = (tid & 1)*4;              // col chunks {0..3} or {4..7}

  int arow = lid & 15;
  int aoff = (lid >> 4) * 16;
  int brow = ((lid >> 4) << 3) + (lid & 7);
  int boff = ((lid >> 3) & 1) * 16;

  float acc[2][8][4];
  #pragma unroll
  for (int i = 0; i < 2; i++)
    #pragma unroll
    for (int j = 0; j < 8; j++)
      #pragma unroll
      for (int q = 0; q < 4; q++) acc[i][j][q] = 0.f;

  // prologue: load chunk 0 (K cols 0..63) into stage 0
  #pragma unroll
  for (int j = 0; j < 4; j++){
    int c = lc0 + j;
    uint32_t so = (uint32_t)lrow*TROW + (uint32_t)c*16;
    size_t ga = (size_t)(bm + lrow)*Hdim + c*8;
    size_t gb = (size_t)(bn + lrow)*Hdim + c*8;
    cp16(sb + so,             A0g + ga);
    cp16(sb + TBYTES   + so,  A1g + ga);
    cp16(sb + 2*TBYTES + so,  B0g + gb);
    cp16(sb + 3*TBYTES + so,  B1g + gb);
  }
  CP_COMMIT();

  for (int ch = 0; ch < 8; ch++){
    int st = ch & 1;
    if (ch < 7){
      uint32_t sbase = sb + (st^1)*STAGEB;
      int k0 = (ch+1)*64;
      #pragma unroll
      for (int j = 0; j < 4; j++){
        int c = lc0 + j;
        uint32_t so = (uint32_t)lrow*TROW + (uint32_t)c*16;
        size_t ga = (size_t)(bm + lrow)*Hdim + k0 + c*8;
        size_t gb = (size_t)(bn + lrow)*Hdim + k0 + c*8;
        cp16(sbase + so,             A0g + ga);
        cp16(sbase + TBYTES   + so,  A1g + ga);
        cp16(sbase + 2*TBYTES + so,  B0g + gb);
        cp16(sbase + 3*TBYTES + so,  B1g + gb);
      }
      CP_COMMIT();
      asm volatile("cp.async.wait_group 1;" ::: "memory");
    } else {
      asm volatile("cp.async.wait_group 0;" ::: "memory");
    }
    __syncthreads();

    uint32_t sA0 = sb + st*STAGEB;
    uint32_t sA1 = sA0 + TBYTES;
    uint32_t sB0 = sA0 + 2*TBYTES;
    uint32_t sB1 = sA0 + 3*TBYTES;
    #pragma unroll
    for (int ks = 0; ks < 4; ks++){
      int kb = ks*32;                  // byte offset: K=16 per step
      uint32_t a0f[2][4], a1f[2][4], b0f[4][4], b1f[4][4];
      #pragma unroll
      for (int mi = 0; mi < 2; mi++){
        uint32_t ro = (uint32_t)(mw*32 + mi*16 + arow)*TROW + kb + aoff;
        ldsm4(a0f[mi], sA0 + ro);
        ldsm4(a1f[mi], sA1 + ro);
      }
      #pragma unroll
      for (int nj = 0; nj < 4; nj++){
        uint32_t ro = (uint32_t)(nw*64 + nj*16 + brow)*TROW + kb + boff;
        ldsm4(b0f[nj], sB0 + ro);
        ldsm4(b1f[nj], sB1 + ro);
      }
      #pragma unroll
      for (int mi = 0; mi < 2; mi++){
        #pragma unroll
        for (int nt = 0; nt < 8; nt++){
          int nj = nt >> 1, sub = (nt & 1)*2;
          mma16816(acc[mi][nt], a0f[mi], &b0f[nj][sub]);
          mma16816(acc[mi][nt], a1f[mi], &b0f[nj][sub]);
          mma16816(acc[mi][nt], a0f[mi], &b1f[nj][sub]);
        }
      }
    }
    __syncthreads();
  }

  // epilogue
  int qr = lid >> 2, qc = (lid & 3)*2;
  #pragma unroll
  for (int mi = 0; mi < 2; mi++){
    #pragma unroll
    for (int hf = 0; hf < 2; hf++){
      int row = bm + mw*32 + mi*16 + hf*8 + qr;
      float* crow = C + (size_t)row*Hdim;
      const float* xrow = aux + (size_t)row*Hdim;
      const float* rrow = resid + (size_t)row*Hdim;
      #pragma unroll
      for (int nt = 0; nt < 8; nt++){
        int col = bn + nw*64 + nt*8 + qc;
        float2 bv = *(const float2*)(bias + col);
        float v0 = acc[mi][nt][hf*2+0] + bv.x;
        float v1 = acc[mi][nt][hf*2+1] + bv.y;
        float2 o;
        if (mode == 0){
          o = make_float2(v0, v1);
        } else if (mode == 1){
          o = make_float2(gelu_f(v0), gelu_f(v1));
        } else if (mode == 2){
          float2 rv = *(const float2*)(rrow + col);
          float2 av = *(const float2*)(xrow + col);
          o.x = rv.x + av.x*sigm_f(v0);
          o.y = rv.y + av.y*sigm_f(v1);
        } else {
          float2 rv = *(const float2*)(rrow + col);
          o = make_float2(rv.x + v0, rv.y + v1);
        }
        *(float2*)(crow + col) = o;
        if (S0){
          size_t gi = (size_t)row*Hdim + col;
          __nv_bfloat16 h0 = __float2bfloat16_rn(o.x);
          __nv_bfloat16 h1 = __float2bfloat16_rn(o.y);
          __nv_bfloat162 p; p.x = h0; p.y = h1;
          *(__nv_bfloat162*)(S0 + gi) = p;
          __nv_bfloat162 q;
          q.x = __float2bfloat16_rn(o.x - __bfloat162float(h0));
          q.y = __float2bfloat16_rn(o.y - __bfloat162float(h1));
          *(__nv_bfloat162*)(S1 + gi) = q;
        }
      }
    }
  }
}

// ----------------- host driver ----------------------------------------------
extern "C" void kernel_launch(void* const* d_in, const int* in_sizes, int n_in,
                              void* d_out, int out_size){
  (void)in_sizes; (void)n_in; (void)out_size;
  const float* x     = (const float*)d_in[0];
  const float* sLre  = (const float*)d_in[1];
  const float* sLim  = (const float*)d_in[2];
  const float* sPre  = (const float*)d_in[3];
  const float* sPim  = (const float*)d_in[4];
  const float* sBre  = (const float*)d_in[5];
  const float* sBim  = (const float*)d_in[6];
  const float* sCre  = (const float*)d_in[7];
  const float* sCim  = (const float*)d_in[8];
  const float* sD    = (const float*)d_in[9];
  const float* sLog  = (const float*)d_in[10];
  const float* sb_ls = (const float*)d_in[11];
  const float* sb_lb = (const float*)d_in[12];
  const float* sb_W1 = (const float*)d_in[13];
  const float* sb_b1 = (const float*)d_in[14];
  const float* sb_W2 = (const float*)d_in[15];
  const float* sb_b2 = (const float*)d_in[16];
  const float* bk_ls = (const float*)d_in[17];
  const float* bk_lb = (const float*)d_in[18];
  const float* bk_W1 = (const float*)d_in[19];
  const float* bk_b1 = (const float*)d_in[20];
  const float* bk_W2 = (const float*)d_in[21];
  const float* bk_b2 = (const float*)d_in[22];
  float* out = (float*)d_out;

  float *p_x, *p_z1;
  float2* p_kd;
  __nv_bfloat16 *p_a0, *p_a1, *p_b0, *p_b1, *p_wt0, *p_wt1;
  cudaGetSymbolAddress((void**)&p_x,   g_x);
  cudaGetSymbolAddress((void**)&p_z1,  g_z1);
  cudaGetSymbolAddress((void**)&p_kd,  g_KdL);
  cudaGetSymbolAddress((void**)&p_a0,  g_a0);
  cudaGetSymbolAddress((void**)&p_a1,  g_a1);
  cudaGetSymbolAddress((void**)&p_b0,  g_b0);
  cudaGetSymbolAddress((void**)&p_b1,  g_b1);
  cudaGetSymbolAddress((void**)&p_wt0, g_wt0);
  cudaGetSymbolAddress((void**)&p_wt1, g_wt1);

  cudaFuncSetAttribute(hgemm_kernel, cudaFuncAttributeMaxDynamicSharedMemorySize, SMEM_GEMM);

  cudaStream_t s2;
  cudaStreamCreateWithFlags(&s2, cudaStreamNonBlocking);
  cudaEvent_t evStart, evKd[4], evW[4], evWB[2];
  cudaEventCreateWithFlags(&evStart, cudaEventDisableTiming);
  for (int i = 0; i < 4; i++){
    cudaEventCreateWithFlags(&evKd[i], cudaEventDisableTiming);
    cudaEventCreateWithFlags(&evW[i],  cudaEventDisableTiming);
  }
  for (int b = 0; b < 2; b++) cudaEventCreateWithFlags(&evWB[b], cudaEventDisableTiming);

  dim3 wgrid(16, 16);
  dim3 tblk(32, 8);
  dim3 tgrid(Hdim/32, Lseq/32, Bsz);
  dim3 ggrid(Hdim/128, NROW/128);

  init_tw_kernel<<<8, 256>>>();
  cudaEventRecord(evStart, 0);
  cudaStreamWaitEvent(s2, evStart, 0);

  cauchy_kernel<<<dim3(Lseq/256, Hdim), 256, 0, s2>>>(
      sLre, sLim, sPre, sPim, sBre, sBim, sCre, sCim, sLog);
  ln_kernel<<<NROW/8, 256>>>(x, sb_ls, sb_lb, 0);
  transpose_fwd_kernel<<<tgrid, tblk>>>();
  kd_kernel<<<Hdim, 256, 0, s2>>>(p_kd);                         // node 5 (profiled)
  cudaEventRecord(evKd[0], s2);
  wprep_kernel<<<wgrid, tblk, 0, s2>>>(sb_W1, 0);
  wprep_kernel<<<wgrid, tblk, 0, s2>>>(sb_W2, 4);
  cudaEventRecord(evW[0], s2);
  for (int i = 1; i < 4; i++){
    cauchy_kernel<<<dim3(Lseq/256, Hdim), 256, 0, s2>>>(
        sLre + i*HN, sLim + i*HN, sPre + i*HN, sPim + i*HN,
        sBre + i*HN, sBim + i*HN, sCre + i*HN, sCim + i*HN, sLog + i*Hdim);
    kd_kernel<<<Hdim, 256, 0, s2>>>(p_kd + (size_t)i*KDSZ);
    cudaEventRecord(evKd[i], s2);
    wprep_kernel<<<wgrid, tblk, 0, s2>>>(sb_W1 + (size_t)i*HH, i);
    wprep_kernel<<<wgrid, tblk, 0, s2>>>(sb_W2 + (size_t)i*HH, 4 + i);
    cudaEventRecord(evW[i], s2);
  }
  for (int b = 0; b < 2; b++){
    wprep_kernel<<<wgrid, tblk, 0, s2>>>(bk_W1 + (size_t)b*HH, 8 + b);
    wprep_kernel<<<wgrid, tblk, 0, s2>>>(bk_W2 + (size_t)b*HH, 10 + b);
    cudaEventRecord(evWB[b], s2);
  }

  for (int b = 0; b < 2; b++){
    for (int li = 0; li < 2; li++){
      int i = b*2 + li;
      if (i > 0){
        ln_kernel<<<NROW/8, 256>>>(p_x, sb_ls + i*Hdim, sb_lb + i*Hdim, 0);
        transpose_fwd_kernel<<<tgrid, tblk>>>();
      }
      cudaStreamWaitEvent(0, evKd[i], 0);
      conv_kernel<<<dim3(Hdim, Bsz), 256>>>(p_kd + (size_t)i*KDSZ);
      transpose_bwd_kernel<<<tgrid, tblk>>>(sD + i*Hdim);
      cudaStreamWaitEvent(0, evW[i], 0);
      hgemm_kernel<<<ggrid, 256, SMEM_GEMM>>>(p_a0, p_a1,
          p_wt0 + (size_t)i*HH, p_wt1 + (size_t)i*HH,
          sb_b1 + i*Hdim, p_z1, p_z1, p_z1, 0, nullptr, nullptr);
      const float* res = (i == 0) ? x : p_x;
      hgemm_kernel<<<ggrid, 256, SMEM_GEMM>>>(p_a0, p_a1,
          p_wt0 + (size_t)(4+i)*HH, p_wt1 + (size_t)(4+i)*HH,
          sb_b2 + i*Hdim, p_z1, res, p_x, 2, nullptr, nullptr);
    }
    ln_kernel<<<NROW/8, 256>>>(p_x, bk_ls + b*Hdim, bk_lb + b*Hdim, 1);
    cudaStreamWaitEvent(0, evWB[b], 0);
    hgemm_kernel<<<ggrid, 256, SMEM_GEMM>>>(p_a0, p_a1,
        p_wt0 + (size_t)(8+b)*HH, p_wt1 + (size_t)(8+b)*HH,
        bk_b1 + b*Hdim, p_z1, p_z1, p_z1, 1, p_b0, p_b1);
    float* Cfinal = (b == 1) ? out : p_x;
    hgemm_kernel<<<ggrid, 256, SMEM_GEMM>>>(p_b0, p_b1,
        p_wt0 + (size_t)(10+b)*HH, p_wt1 + (size_t)(10+b)*HH,
        bk_b2 + b*Hdim, p_z1, p_x, Cfinal, 3, nullptr, nullptr);
  }
}

// round 11
// speedup vs baseline: 1.0015x; 1.0015x over previous
#include <cuda_runtime.h>
#include <cuda_bf16.h>
#include <cstdint>
#include <math.h>

#define Bsz   8
#define Lseq  2048
#define Hdim  512
#define Nst   64
#define NROW  (Bsz*Lseq)          // 16384
#define BLH   (Bsz*Lseq*Hdim)     // 8388608
#define HH    (Hdim*Hdim)
#define HN    (Hdim*Nst)
#define KDSZ  (Hdim*2049)

// ----------------- device scratch (no allocations allowed) ------------------
__device__ float  g_x [BLH];
__device__ float  g_h [BLH];
__device__ float  g_ht[BLH];
__device__ float  g_yt[BLH];
__device__ float  g_v [BLH];
__device__ float  g_z1[BLH];
__device__ float2 g_ar[Hdim*Lseq];
__device__ float2 g_KdL[4*KDSZ];
__device__ float2 g_twA[1024];
__device__ float2 g_twB[2048];
__device__ __nv_bfloat16 g_a0[BLH];
__device__ __nv_bfloat16 g_a1[BLH];
__device__ __nv_bfloat16 g_b0[BLH];
__device__ __nv_bfloat16 g_b1[BLH];
__device__ __nv_bfloat16 g_wt0[12*HH];
__device__ __nv_bfloat16 g_wt1[12*HH];

// ----------------- helpers --------------------------------------------------
__device__ __forceinline__ float2 cadd(float2 a, float2 b){ return make_float2(a.x+b.x, a.y+b.y); }
__device__ __forceinline__ float2 csub(float2 a, float2 b){ return make_float2(a.x-b.x, a.y-b.y); }
__device__ __forceinline__ float2 cmul(float2 a, float2 b){ return make_float2(a.x*b.x-a.y*b.y, a.x*b.y+a.y*b.x); }
__device__ __forceinline__ float frcp_fast(float x){ float y; asm("rcp.approx.f32 %0, %1;" : "=f"(y) : "f"(x)); return y; }
__device__ __forceinline__ float gelu_f(float x){
  float u = 0.7978845608028654f*(x + 0.044715f*x*x*x);
  float e = __expf(2.f*u);
  float t = 1.f - 2.f/(e + 1.f);          // tanh(u), saturates correctly
  return 0.5f*x*(1.0f + t);
}
__device__ __forceinline__ float sigm_f(float x){ return 1.0f/(1.0f + __expf(-x)); }

__device__ __forceinline__ uint32_t smem_u32(const void* p){
  uint32_t a;
  asm("{ .reg .u64 t; cvta.to.shared.u64 t, %1; cvt.u32.u64 %0, t; }" : "=r"(a) : "l"(p));
  return a;
}
__device__ __forceinline__ void cp16(uint32_t saddr, const void* g){
  asm volatile("cp.async.ca.shared.global [%0], [%1], 16;" :: "r"(saddr), "l"(g));
}
#define CP_COMMIT() asm volatile("cp.async.commit_group;" ::: "memory")

__device__ __forceinline__ void ldsm4(uint32_t* r, uint32_t addr){
  asm volatile("ldmatrix.sync.aligned.m8n8.x4.shared.b16 {%0,%1,%2,%3}, [%4];"
    : "=r"(r[0]), "=r"(r[1]), "=r"(r[2]), "=r"(r[3]) : "r"(addr));
}
__device__ __forceinline__ void mma16816(float* c, const uint32_t* a, const uint32_t* b){
  asm volatile("mma.sync.aligned.m16n8k16.row.col.f32.bf16.bf16.f32 "
    "{%0,%1,%2,%3}, {%4,%5,%6,%7}, {%8,%9}, {%0,%1,%2,%3};"
    : "+f"(c[0]), "+f"(c[1]), "+f"(c[2]), "+f"(c[3])
    : "r"(a[0]), "r"(a[1]), "r"(a[2]), "r"(a[3]), "r"(b[0]), "r"(b[1]));
}

// ----------------- twiddle init ---------------------------------------------
__global__ void init_tw_kernel(){
  int i = blockIdx.x*256 + threadIdx.x;
  if (i < 1024){
    float a = (float)(6.283185307179586/2048.0) * (float)i;
    float s, c; sincosf(a, &s, &c);
    g_twA[i] = make_float2(c, -s);
  }
  if (i < 2048){
    float a = (float)(3.141592653589793/2048.0) * (float)i;
    float s, c; sincosf(a, &s, &c);
    g_twB[i] = make_float2(c, -s);
  }
}

// ----------------- layernorm: xin -> g_h (+ optional bf16 split) ------------
__global__ __launch_bounds__(256) void ln_kernel(const float* __restrict__ xin,
                                                 const float* __restrict__ sc,
                                                 const float* __restrict__ bi,
                                                 int wsplit){
  int warp = threadIdx.x >> 5, lane = threadIdx.x & 31;
  size_t row = (size_t)blockIdx.x*8 + warp;
  const float4* xr = (const float4*)(xin + row*Hdim);
  float4 v[4];
  float s = 0.f, s2 = 0.f;
  #pragma unroll
  for (int i = 0; i < 4; i++){
    float4 t = xr[lane + 32*i];
    v[i] = t;
    s  += t.x + t.y + t.z + t.w;
    s2 += t.x*t.x + t.y*t.y + t.z*t.z + t.w*t.w;
  }
  #pragma unroll
  for (int o = 16; o; o >>= 1){
    s  += __shfl_xor_sync(0xffffffffu, s,  o);
    s2 += __shfl_xor_sync(0xffffffffu, s2, o);
  }
  float mean = s*(1.f/Hdim);
  float var  = s2*(1.f/Hdim) - mean*mean;
  float inv  = rsqrtf(var + 1e-6f);
  float4* orow = (float4*)(g_h + row*Hdim);
  const float4* s4 = (const float4*)sc;
  const float4* b4 = (const float4*)bi;
  #pragma unroll
  for (int i = 0; i < 4; i++){
    int ci = lane + 32*i;
    float4 sv = s4[ci], bv = b4[ci], t = v[i], o;
    o.x = (t.x-mean)*inv*sv.x + bv.x;
    o.y = (t.y-mean)*inv*sv.y + bv.y;
    o.z = (t.z-mean)*inv*sv.z + bv.z;
    o.w = (t.w-mean)*inv*sv.w + bv.w;
    orow[ci] = o;
    if (wsplit){
      size_t gi = row*Hdim + ci*4;
      __nv_bfloat16 h0 = __float2bfloat16_rn(o.x);
      __nv_bfloat16 h1 = __float2bfloat16_rn(o.y);
      __nv_bfloat16 h2 = __float2bfloat16_rn(o.z);
      __nv_bfloat16 h3 = __float2bfloat16_rn(o.w);
      __nv_bfloat162 p0; p0.x = h0; p0.y = h1;
      __nv_bfloat162 p1; p1.x = h2; p1.y = h3;
      *(__nv_bfloat162*)(g_a0 + gi)     = p0;
      *(__nv_bfloat162*)(g_a0 + gi + 2) = p1;
      __nv_bfloat162 q0, q1;
      q0.x = __float2bfloat16_rn(o.x - __bfloat162float(h0));
      q0.y = __float2bfloat16_rn(o.y - __bfloat162float(h1));
      q1.x = __float2bfloat16_rn(o.z - __bfloat162float(h2));
      q1.y = __float2bfloat16_rn(o.w - __bfloat162float(h3));
      *(__nv_bfloat162*)(g_a1 + gi)     = q0;
      *(__nv_bfloat162*)(g_a1 + gi + 2) = q1;
    }
  }
}

// ----------------- transposes -----------------------------------------------
__global__ void transpose_fwd_kernel(){
  __shared__ float tile[32][33];
  int b  = blockIdx.z;
  int h0 = blockIdx.x*32;
  int l0 = blockIdx.y*32;
  int tx = threadIdx.x, ty = threadIdx.y;
  const float* in = g_h + (size_t)b*Lseq*Hdim;
  float* out = g_ht + (size_t)b*Hdim*Lseq;
  #pragma unroll
  for (int j = 0; j < 32; j += 8)
    tile[ty+j][tx] = in[(size_t)(l0+ty+j)*Hdim + h0 + tx];
  __syncthreads();
  #pragma unroll
  for (int j = 0; j < 32; j += 8)
    out[(size_t)(h0+ty+j)*Lseq + l0 + tx] = tile[tx][ty+j];
}

__global__ void transpose_bwd_kernel(const float* __restrict__ D){
  __shared__ float tile[32][33];
  int b  = blockIdx.z;
  int h0 = blockIdx.x*32;
  int l0 = blockIdx.y*32;
  int tx = threadIdx.x, ty = threadIdx.y;
  const float* in = g_yt + (size_t)b*Hdim*Lseq;
  float* out = g_v + (size_t)b*Lseq*Hdim;
  const float* hbuf = g_h + (size_t)b*Lseq*Hdim;
  #pragma unroll
  for (int j = 0; j < 32; j += 8)
    tile[ty+j][tx] = in[(size_t)(h0+ty+j)*Lseq + l0 + tx];
  __syncthreads();
  size_t boff = (size_t)b*Lseq*Hdim;
  #pragma unroll
  for (int j = 0; j < 32; j += 8){
    size_t idx = (size_t)(l0+ty+j)*Hdim + h0 + tx;
    float y = tile[tx][ty+j] + D[h0+tx]*hbuf[idx];
    float g = gelu_f(y);
    out[idx] = g;
    __nv_bfloat16 hi = __float2bfloat16_rn(g);
    float r = g - __bfloat162float(hi);
    g_a0[boff + idx] = hi;
    g_a1[boff + idx] = __float2bfloat16_rn(r);
  }
}

// ----------------- weight transpose + split ----------------------------------
__global__ void wprep_kernel(const float* __restrict__ W, int widx){
  __shared__ float tile[32][33];
  int n0 = blockIdx.x*32, k0 = blockIdx.y*32;
  int tx = threadIdx.x, ty = threadIdx.y;
  #pragma unroll
  for (int j = 0; j < 32; j += 8)
    tile[ty+j][tx] = W[(size_t)(k0+ty+j)*Hdim + n0 + tx];
  __syncthreads();
  size_t base = (size_t)widx*HH;
  #pragma unroll
  for (int j = 0; j < 32; j += 8){
    float a = tile[tx][ty+j];
    size_t o = base + (size_t)(n0+ty+j)*Hdim + k0 + tx;
    __nv_bfloat16 hi = __float2bfloat16_rn(a);
    g_wt0[o] = hi;
    g_wt1[o] = __float2bfloat16_rn(a - __bfloat162float(hi));
  }
}

// ----------------- Cauchy kernel (prep fused in) -----------------------------
__global__ __launch_bounds__(256) void cauchy_kernel(
    const float* __restrict__ Lre, const float* __restrict__ Lim,
    const float* __restrict__ Pre, const float* __restrict__ Pim,
    const float* __restrict__ Bre, const float* __restrict__ Bim,
    const float* __restrict__ Cre, const float* __restrict__ Cim,
    const float* __restrict__ logstep){
  __shared__ float4 spk01[Nst];
  __shared__ float4 spk23[Nst];
  __shared__ float2 slam [Nst];
  __shared__ float  s2step;
  int tid = threadIdx.x;
  int h = blockIdx.y;
  int l = blockIdx.x*256 + tid;
  if (tid < Nst){
    int i = h*Nst + tid;
    float pr = Pre[i], pi = Pim[i];
    float br = Bre[i], bi = Bim[i];
    float cr = Cre[i], ci = Cim[i];
    spk01[tid] = make_float4(cr*br + ci*bi, cr*bi - ci*br,
                             cr*pr + ci*pi, cr*pi - ci*pr);
    spk23[tid] = make_float4(pr*br + pi*bi, pr*bi - pi*br,
                             pr*pr + pi*pi, 0.f);
    slam [tid] = make_float2(fminf(Lre[i], -1e-4f), Lim[i]);
  }
  if (tid == 0) s2step = 2.f*expf(-logstep[h]);
  __syncthreads();
  float t   = tanf((float)(3.141592653589793/2048.0)*(float)l);
  float gim = s2step*t;
  float k00r=0.f,k00i=0.f,k01r=0.f,k01i=0.f,k10r=0.f,k10i=0.f,k11r=0.f,k11i=0.f;
  #pragma unroll 8
  for (int n = 0; n < Nst; n++){
    float2 lam = slam[n];
    float dre = -lam.x;
    float dim = gim - lam.y;
    float inv = frcp_fast(dre*dre + dim*dim);
    float ir  =  dre*inv;
    float ii  = -dim*inv;
    float4 w01 = spk01[n];
    float4 w23 = spk23[n];
    k00r += w01.x*ir - w01.y*ii;  k00i += w01.x*ii + w01.y*ir;
    k01r += w01.z*ir - w01.w*ii;  k01i += w01.z*ii + w01.w*ir;
    k10r += w23.x*ir - w23.y*ii;  k10i += w23.x*ii + w23.y*ir;
    k11r += w23.z*ir;             k11i += w23.z*ii;
  }
  float denr = 1.f + k11r, deni = k11i;
  float dinv = frcp_fast(denr*denr + deni*deni);
  float qr = denr*dinv, qi = -deni*dinv;
  float mr = k01r*k10r - k01i*k10i;
  float mi = k01r*k10i + k01i*k10r;
  float cr = mr*qr - mi*qi, ci2 = mr*qi + mi*qr;
  float ar = k00r - cr, ai = k00i - ci2;
  g_ar[(size_t)h*Lseq + l] = make_float2(ar - t*ai, ai + t*ar);
}

// ----------------- shared-mem radix-4 Stockham FFT(2048) ---------------------
template<bool INV>
__device__ __forceinline__ float2* fft2048_r4(float2* buf0, float2* buf1,
                                              const float2* stw, int tid){
  float2* src = buf0; float2* dst = buf1;
  #pragma unroll
  for (int st = 0; st < 5; st++){
    int s = 1 << (2*st);
    __syncthreads();
    #pragma unroll
    for (int i = 0; i < 2; i++){
      int idx = tid + 256*i;
      int sp  = idx & ~(s-1);
      float2 a0 = src[idx];
      float2 a1 = src[idx + 512];
      float2 a2 = src[idx + 1024];
      float2 a3 = src[idx + 1536];
      float2 w1 = stw[sp];
      float2 w2 = stw[2*sp];
      if (INV){ w1.y = -w1.y; w2.y = -w2.y; }
      float2 w3 = cmul(w1, w2);
      float2 t0 = cadd(a0, a2), t1 = csub(a0, a2);
      float2 t2 = cadd(a1, a3), t3 = csub(a1, a3);
      float2 b0 = cadd(t0, t2);
      float2 b2 = csub(t0, t2);
      float2 b1, b3;
      if (!INV){
        b1 = make_float2(t1.x + t3.y, t1.y - t3.x);
        b3 = make_float2(t1.x - t3.y, t1.y + t3.x);
      } else {
        b1 = make_float2(t1.x - t3.y, t1.y + t3.x);
        b3 = make_float2(t1.x + t3.y, t1.y - t3.x);
      }
      int j = idx + 3*sp;
      dst[j]       = b0;
      dst[j + s]   = cmul(b1, w1);
      dst[j + 2*s] = cmul(b2, w2);
      dst[j + 3*s] = cmul(b3, w3);
    }
    float2* tp = src; src = dst; dst = tp;
  }
  __syncthreads();
  #pragma unroll
  for (int i = 0; i < 4; i++){
    int idx = tid + 256*i;
    float2 a = src[idx];
    float2 b = src[idx + 1024];
    dst[idx]        = cadd(a, b);
    dst[idx + 1024] = csub(a, b);
  }
  float2* tp = src; src = dst; dst = tp;
  __syncthreads();
  return src;
}

// ----------------- Kd kernel ------------------------------------------------
__global__ __launch_bounds__(256) void kd_kernel(float2* __restrict__ Kd){
  __shared__ float2 sA[2048];
  __shared__ float2 sB[2048];
  __shared__ float2 stw[1024];
  int tid = threadIdx.x;
  int h = blockIdx.x;
  for (int i = tid; i < 1024; i += 256) stw[i] = g_twA[i];
  const float2* ar = g_ar + (size_t)h*Lseq;
  #pragma unroll
  for (int i = 0; i < 8; i++){ int k = tid + 256*i; sA[k] = ar[k]; }
  float2* K = fft2048_r4<true>(sA, sB, stw, tid);
  float2* Ob = (K == sA) ? sB : sA;
  const float sc = 1.f/2048.f;
  #pragma unroll
  for (int i = 0; i < 8; i++){
    int n = tid + 256*i;
    float2 v = make_float2(0.f, 0.f);
    if (n < 1024) v = make_float2(K[2*n].x*sc, K[2*n+1].x*sc);
    Ob[n] = v;
  }
  float2* Zp = fft2048_r4<false>(Ob, K, stw, tid);
  float2* outKd = Kd + (size_t)h*2049;
  #pragma unroll
  for (int i = 0; i < 8; i++){
    int k  = tid + 256*i;
    int kc = (2048 - k) & 2047;
    float2 zk = Zp[k], zc = Zp[kc];
    float2 E  = make_float2(0.5f*(zk.x+zc.x),  0.5f*(zk.y-zc.y));
    float2 Od = make_float2(0.5f*(zk.y+zc.y), -0.5f*(zk.x-zc.x));
    outKd[k] = cadd(E, cmul(g_twB[k], Od));
  }
  if (tid == 0){
    float2 z0 = Zp[0];
    outKd[2048] = make_float2(z0.x - z0.y, 0.f);
  }
}

// ----------------- conv kernel ----------------------------------------------
__global__ __launch_bounds__(256) void conv_kernel(const float2* __restrict__ Kdbase){
  __shared__ float2 sA[2048];
  __shared__ float2 sB[2048];
  __shared__ float2 stw[1024];
  __shared__ float2 sY2048;
  int tid = threadIdx.x;
  int h = blockIdx.x;
  int b = blockIdx.y;
  const float* u = g_ht + ((size_t)b*Hdim + h)*Lseq;
  for (int i = tid; i < 1024; i += 256) stw[i] = g_twA[i];
  #pragma unroll
  for (int i = 0; i < 4; i++){
    int n = tid + 256*i;
    sA[n]        = make_float2(u[2*n], u[2*n+1]);
    sA[n + 1024] = make_float2(0.f, 0.f);
  }
  float2* Z = fft2048_r4<false>(sA, sB, stw, tid);
  float2* O = (Z == sA) ? sB : sA;
  const float2* kd = Kdbase + (size_t)h*2049;
  #pragma unroll
  for (int i = 0; i < 8; i++){
    int k  = tid + 256*i;
    int kc = (2048 - k) & 2047;
    float2 zk = Z[k], zc = Z[kc];
    float2 E  = make_float2(0.5f*(zk.x+zc.x),  0.5f*(zk.y-zc.y));
    float2 Od = make_float2(0.5f*(zk.y+zc.y), -0.5f*(zk.x-zc.x));
    float2 U  = cadd(E, cmul(g_twB[k], Od));
    O[k] = cmul(U, kd[k]);
  }
  if (tid == 0){
    float2 z0 = Z[0];
    float U2048 = z0.x - z0.y;
    float2 kv = kd[2048];
    sY2048 = make_float2(U2048*kv.x, U2048*kv.y);
  }
  __syncthreads();
  #pragma unroll
  for (int i = 0; i < 8; i++){
    int k = tid + 256*i;
    float2 Yk = O[k];
    float2 Yc = (k == 0) ? sY2048 : O[2048 - k];
    float2 Ey = make_float2(0.5f*(Yk.x+Yc.x), 0.5f*(Yk.y-Yc.y));
    float2 Dm = make_float2(0.5f*(Yk.x-Yc.x), 0.5f*(Yk.y+Yc.y));
    float2 tb = g_twB[k];
    float2 Oy = cmul(Dm, make_float2(tb.x, -tb.y));
    Z[k] = make_float2(Ey.x - Oy.y, Ey.y + Oy.x);
  }
  float2* w = fft2048_r4<true>(Z, O, stw, tid);
  float* out = g_yt + ((size_t)b*Hdim + h)*Lseq;
  const float sc = 1.f/2048.f;
  #pragma unroll
  for (int i = 0; i < 4; i++){
    int n = tid + 256*i;
    float2 v = w[n];
    out[2*n]   = v.x*sc;
    out[2*n+1] = v.y*sc;
  }
}

// ----------------- HMMA GEMM: 128x128 tile, bf16x3, K-chunk 64 ---------------
// mode 0: C = acc+bias            mode 1: C = gelu(acc+bias)
// mode 2: C = resid + aux*sigmoid(acc+bias)   mode 3: C = resid + acc+bias
#define TROW    144                     // 128B real (64 bf16) + 16B pad
#define TBYTES  (128*TROW)              // 18432 per tile
#define STAGEB  (4*TBYTES)              // 73728 (A0,A1,B0,B1)
#define SMEM_GEMM (2*STAGEB)            // 147456

__global__ __launch_bounds__(256) void hgemm_kernel(
    const __nv_bfloat16* __restrict__ A0g, const __nv_bfloat16* __restrict__ A1g,
    const __nv_bfloat16* __restrict__ B0g, const __nv_bfloat16* __restrict__ B1g,
    const float* __restrict__ bias, const float* __restrict__ aux,
    const float* __restrict__ resid,
    float* __restrict__ C, int mode,
    __nv_bfloat16* __restrict__ S0, __nv_bfloat16* __restrict__ S1)
{
  extern __shared__ char smem[];
  uint32_t sb = smem_u32(smem);
  int tid = threadIdx.x, wid = tid >> 5, lid = tid & 31;
  int bn = blockIdx.x*128, bm = blockIdx.y*128;
  int mw = wid & 3, nw = wid >> 2;

  int lrow = tid >> 1;                 // 0..127
  int lc0  = (tid & 1)*4;              // col chunks {0..3} or {4..7}

  int arow = lid & 15;
  int aoff = (lid >> 4) * 16;
  int brow = ((lid >> 4) << 3) + (lid & 7);
  int boff = ((lid >> 3) & 1) * 16;

  float acc[2][8][4];
  #pragma unroll
  for (int i = 0; i < 2; i++)
    #pragma unroll
    for (int j = 0; j < 8; j++)
      #pragma unroll
      for (int q = 0; q < 4; q++) acc[i][j][q] = 0.f;

  // prologue: load chunk 0 (K cols 0..63) into stage 0
  #pragma unroll
  for (int j = 0; j < 4; j++){
    int c = lc0 + j;
    uint32_t so = (uint32_t)lrow*TROW + (uint32_t)c*16;
    size_t ga = (size_t)(bm + lrow)*Hdim + c*8;
    size_t gb = (size_t)(bn + lrow)*Hdim + c*8;
    cp16(sb + so,             A0g + ga);
    cp16(sb + TBYTES   + so,  A1g + ga);
    cp16(sb + 2*TBYTES + so,  B0g + gb);
    cp16(sb + 3*TBYTES + so,  B1g + gb);
  }
  CP_COMMIT();

  for (int ch = 0; ch < 8; ch++){
    int st = ch & 1;
    if (ch < 7){
      uint32_t sbase = sb + (st^1)*STAGEB;
      int k0 = (ch+1)*64;
      #pragma unroll
      for (int j = 0; j < 4; j++){
        int c = lc0 + j;
        uint32_t so = (uint32_t)lrow*TROW + (uint32_t)c*16;
        size_t ga = (size_t)(bm + lrow)*Hdim + k0 + c*8;
        size_t gb = (size_t)(bn + lrow)*Hdim + k0 + c*8;
        cp16(sbase + so,             A0g + ga);
        cp16(sbase + TBYTES   + so,  A1g + ga);
        cp16(sbase + 2*TBYTES + so,  B0g + gb);
        cp16(sbase + 3*TBYTES + so,  B1g + gb);
      }
      CP_COMMIT();
      asm volatile("cp.async.wait_group 1;" ::: "memory");
    } else {
      asm volatile("cp.async.wait_group 0;" ::: "memory");
    }
    __syncthreads();

    uint32_t sA0 = sb + st*STAGEB;
    uint32_t sA1 = sA0 + TBYTES;
    uint32_t sB0 = sA0 + 2*TBYTES;
    uint32_t sB1 = sA0 + 3*TBYTES;
    #pragma unroll
    for (int ks = 0; ks < 4; ks++){
      int kb = ks*32;                  // byte offset: K=16 per step
      uint32_t a0f[2][4], a1f[2][4], b0f[4][4], b1f[4][4];
      #pragma unroll
      for (int mi = 0; mi < 2; mi++){
        uint32_t ro = (uint32_t)(mw*32 + mi*16 + arow)*TROW + kb + aoff;
        ldsm4(a0f[mi], sA0 + ro);
        ldsm4(a1f[mi], sA1 + ro);
      }
      #pragma unroll
      for (int nj = 0; nj < 4; nj++){
        uint32_t ro = (uint32_t)(nw*64 + nj*16 + brow)*TROW + kb + boff;
        ldsm4(b0f[nj], sB0 + ro);
        ldsm4(b1f[nj], sB1 + ro);
      }
      #pragma unroll
      for (int mi = 0; mi < 2; mi++){
        #pragma unroll
        for (int nt = 0; nt < 8; nt++){
          int nj = nt >> 1, sub = (nt & 1)*2;
          mma16816(acc[mi][nt], a0f[mi], &b0f[nj][sub]);
          mma16816(acc[mi][nt], a1f[mi], &b0f[nj][sub]);
          mma16816(acc[mi][nt], a0f[mi], &b1f[nj][sub]);
        }
      }
    }
    __syncthreads();
  }

  // epilogue
  int qr = lid >> 2, qc = (lid & 3)*2;
  #pragma unroll
  for (int mi = 0; mi < 2; mi++){
    #pragma unroll
    for (int hf = 0; hf < 2; hf++){
      int row = bm + mw*32 + mi*16 + hf*8 + qr;
      float* crow = C + (size_t)row*Hdim;
      const float* xrow = aux + (size_t)row*Hdim;
      const float* rrow = resid + (size_t)row*Hdim;
      #pragma unroll
      for (int nt = 0; nt < 8; nt++){
        int col = bn + nw*64 + nt*8 + qc;
        float2 bv = *(const float2*)(bias + col);
        float v0 = acc[mi][nt][hf*2+0] + bv.x;
        float v1 = acc[mi][nt][hf*2+1] + bv.y;
        float2 o;
        if (mode == 0){
          o = make_float2(v0, v1);
        } else if (mode == 1){
          o = make_float2(gelu_f(v0), gelu_f(v1));
        } else if (mode == 2){
          float2 rv = *(const float2*)(rrow + col);
          float2 av = *(const float2*)(xrow + col);
          o.x = rv.x + av.x*sigm_f(v0);
          o.y = rv.y + av.y*sigm_f(v1);
        } else {
          float2 rv = *(const float2*)(rrow + col);
          o = make_float2(rv.x + v0, rv.y + v1);
        }
        *(float2*)(crow + col) = o;
        if (S0){
          size_t gi = (size_t)row*Hdim + col;
          __nv_bfloat16 h0 = __float2bfloat16_rn(o.x);
          __nv_bfloat16 h1 = __float2bfloat16_rn(o.y);
          __nv_bfloat162 p; p.x = h0; p.y = h1;
          *(__nv_bfloat162*)(S0 + gi) = p;
          __nv_bfloat162 q;
          q.x = __float2bfloat16_rn(o.x - __bfloat162float(h0));
          q.y = __float2bfloat16_rn(o.y - __bfloat162float(h1));
          *(__nv_bfloat162*)(S1 + gi) = q;
        }
      }
    }
  }
}

// ----------------- host driver ----------------------------------------------
extern "C" void kernel_launch(void* const* d_in, const int* in_sizes, int n_in,
                              void* d_out, int out_size){
  (void)in_sizes; (void)n_in; (void)out_size;
  const float* x     = (const float*)d_in[0];
  const float* sLre  = (const float*)d_in[1];
  const float* sLim  = (const float*)d_in[2];
  const float* sPre  = (const float*)d_in[3];
  const float* sPim  = (const float*)d_in[4];
  const float* sBre  = (const float*)d_in[5];
  const float* sBim  = (const float*)d_in[6];
  const float* sCre  = (const float*)d_in[7];
  const float* sCim  = (const float*)d_in[8];
  const float* sD    = (const float*)d_in[9];
  const float* sLog  = (const float*)d_in[10];
  const float* sb_ls = (const float*)d_in[11];
  const float* sb_lb = (const float*)d_in[12];
  const float* sb_W1 = (const float*)d_in[13];
  const float* sb_b1 = (const float*)d_in[14];
  const float* sb_W2 = (const float*)d_in[15];
  const float* sb_b2 = (const float*)d_in[16];
  const float* bk_ls = (const float*)d_in[17];
  const float* bk_lb = (const float*)d_in[18];
  const float* bk_W1 = (const float*)d_in[19];
  const float* bk_b1 = (const float*)d_in[20];
  const float* bk_W2 = (const float*)d_in[21];
  const float* bk_b2 = (const float*)d_in[22];
  float* out = (float*)d_out;

  float *p_x, *p_z1;
  float2* p_kd;
  __nv_bfloat16 *p_a0, *p_a1, *p_b0, *p_b1, *p_wt0, *p_wt1;
  cudaGetSymbolAddress((void**)&p_x,   g_x);
  cudaGetSymbolAddress((void**)&p_z1,  g_z1);
  cudaGetSymbolAddress((void**)&p_kd,  g_KdL);
  cudaGetSymbolAddress((void**)&p_a0,  g_a0);
  cudaGetSymbolAddress((void**)&p_a1,  g_a1);
  cudaGetSymbolAddress((void**)&p_b0,  g_b0);
  cudaGetSymbolAddress((void**)&p_b1,  g_b1);
  cudaGetSymbolAddress((void**)&p_wt0, g_wt0);
  cudaGetSymbolAddress((void**)&p_wt1, g_wt1);

  cudaFuncSetAttribute(hgemm_kernel, cudaFuncAttributeMaxDynamicSharedMemorySize, SMEM_GEMM);

  cudaStream_t s2;
  cudaStreamCreateWithFlags(&s2, cudaStreamNonBlocking);
  cudaEvent_t evStart, evKd[4], evW[4], evWB[2];
  cudaEventCreateWithFlags(&evStart, cudaEventDisableTiming);
  for (int i = 0; i < 4; i++){
    cudaEventCreateWithFlags(&evKd[i], cudaEventDisableTiming);
    cudaEventCreateWithFlags(&evW[i],  cudaEventDisableTiming);
  }
  for (int b = 0; b < 2; b++) cudaEventCreateWithFlags(&evWB[b], cudaEventDisableTiming);

  dim3 wgrid(16, 16);
  dim3 tblk(32, 8);
  dim3 tgrid(Hdim/32, Lseq/32, Bsz);
  dim3 ggrid(Hdim/128, NROW/128);

  init_tw_kernel<<<8, 256>>>();
  cudaEventRecord(evStart, 0);
  cudaStreamWaitEvent(s2, evStart, 0);

  cauchy_kernel<<<dim3(Lseq/256, Hdim), 256, 0, s2>>>(
      sLre, sLim, sPre, sPim, sBre, sBim, sCre, sCim, sLog);
  ln_kernel<<<NROW/8, 256>>>(x, sb_ls, sb_lb, 0);
  transpose_fwd_kernel<<<tgrid, tblk>>>();
  kd_kernel<<<Hdim, 256, 0, s2>>>(p_kd);                         // node 5 (profiled)
  cudaEventRecord(evKd[0], s2);
  wprep_kernel<<<wgrid, tblk, 0, s2>>>(sb_W1, 0);
  wprep_kernel<<<wgrid, tblk, 0, s2>>>(sb_W2, 4);
  cudaEventRecord(evW[0], s2);
  for (int i = 1; i < 4; i++){
    cauchy_kernel<<<dim3(Lseq/256, Hdim), 256, 0, s2>>>(
        sLre + i*HN, sLim + i*HN, sPre + i*HN, sPim + i*HN,
        sBre + i*HN, sBim + i*HN, sCre + i*HN, sCim + i*HN, sLog + i*Hdim);
    kd_kernel<<<Hdim, 256, 0, s2>>>(p_kd + (size_t)i*KDSZ);
    cudaEventRecord(evKd[i], s2);
    wprep_kernel<<<wgrid, tblk, 0, s2>>>(sb_W1 + (size_t)i*HH, i);
    wprep_kernel<<<wgrid, tblk, 0, s2>>>(sb_W2 + (size_t)i*HH, 4 + i);
    cudaEventRecord(evW[i], s2);
  }
  for (int b = 0; b < 2; b++){
    wprep_kernel<<<wgrid, tblk, 0, s2>>>(bk_W1 + (size_t)b*HH, 8 + b);
    wprep_kernel<<<wgrid, tblk, 0, s2>>>(bk_W2 + (size_t)b*HH, 10 + b);
    cudaEventRecord(evWB[b], s2);
  }

  for (int b = 0; b < 2; b++){
    for (int li = 0; li < 2; li++){
      int i = b*2 + li;
      if (i > 0){
        ln_kernel<<<NROW/8, 256>>>(p_x, sb_ls + i*Hdim, sb_lb + i*Hdim, 0);
        transpose_fwd_kernel<<<tgrid, tblk>>>();
      }
      cudaStreamWaitEvent(0, evKd[i], 0);
      conv_kernel<<<dim3(Hdim, Bsz), 256>>>(p_kd + (size_t)i*KDSZ);
      transpose_bwd_kernel<<<tgrid, tblk>>>(sD + i*Hdim);
      cudaStreamWaitEvent(0, evW[i], 0);
      hgemm_kernel<<<ggrid, 256, SMEM_GEMM>>>(p_a0, p_a1,
          p_wt0 + (size_t)i*HH, p_wt1 + (size_t)i*HH,
          sb_b1 + i*Hdim, p_z1, p_z1, p_z1, 0, nullptr, nullptr);
      const float* res = (i == 0) ? x : p_x;
      hgemm_kernel<<<ggrid, 256, SMEM_GEMM>>>(p_a0, p_a1,
          p_wt0 + (size_t)(4+i)*HH, p_wt1 + (size_t)(4+i)*HH,
          sb_b2 + i*Hdim, p_z1, res, p_x, 2, nullptr, nullptr);
    }
    ln_kernel<<<NROW/8, 256>>>(p_x, bk_ls + b*Hdim, bk_lb + b*Hdim, 1);
    cudaStreamWaitEvent(0, evWB[b], 0);
    hgemm_kernel<<<ggrid, 256, SMEM_GEMM>>>(p_a0, p_a1,
        p_wt0 + (size_t)(8+b)*HH, p_wt1 + (size_t)(8+b)*HH,
        bk_b1 + b*Hdim, p_z1, p_z1, p_z1, 1, p_b0, p_b1);
    float* Cfinal = (b == 1) ? out : p_x;
    hgemm_kernel<<<ggrid, 256, SMEM_GEMM>>>(p_b0, p_b1,
        p_wt0 + (size_t)(10+b)*HH, p_wt1 + (size_t)(10+b)*HH,
        bk_b2 + b*Hdim, p_z1, p_x, Cfinal, 3, nullptr, nullptr);
  }
}

// round 12
// speedup vs baseline: 1.1973x; 1.1955x over previous
#include <cuda_runtime.h>
#include <cuda_bf16.h>
#include <cstdint>
#include <math.h>

#define Bsz   8
#define Lseq  2048
#define Hdim  512
#define Nst   64
#define NROW  (Bsz*Lseq)          // 16384
#define BLH   (Bsz*Lseq*Hdim)     // 8388608
#define HH    (Hdim*Hdim)
#define HN    (Hdim*Nst)
#define KDSZ  (Hdim*2049)

// ----------------- device scratch (no allocations allowed) ------------------
__device__ float  g_x [BLH];
__device__ float  g_h [BLH];
__device__ float  g_ht[BLH];
__device__ float  g_yt[BLH];
__device__ float  g_v [BLH];
__device__ float  g_z1[BLH];
__device__ float2 g_ar[Hdim*Lseq];
__device__ float2 g_KdL[4*KDSZ];
__device__ float2 g_twA[1024];
__device__ float2 g_twB[2048];
__device__ __nv_bfloat16 g_a0[BLH];
__device__ __nv_bfloat16 g_a1[BLH];
__device__ __nv_bfloat16 g_b0[BLH];
__device__ __nv_bfloat16 g_b1[BLH];
__device__ __nv_bfloat16 g_wt0[12*HH];
__device__ __nv_bfloat16 g_wt1[12*HH];

// ----------------- helpers --------------------------------------------------
__device__ __forceinline__ float2 cadd(float2 a, float2 b){ return make_float2(a.x+b.x, a.y+b.y); }
__device__ __forceinline__ float2 csub(float2 a, float2 b){ return make_float2(a.x-b.x, a.y-b.y); }
__device__ __forceinline__ float2 cmul(float2 a, float2 b){ return make_float2(a.x*b.x-a.y*b.y, a.x*b.y+a.y*b.x); }
__device__ __forceinline__ float frcp_fast(float x){ float y; asm("rcp.approx.f32 %0, %1;" : "=f"(y) : "f"(x)); return y; }
__device__ __forceinline__ float gelu_f(float x){
  float u = 0.7978845608028654f*(x + 0.044715f*x*x*x);
  float e = __expf(2.f*u);
  float t = 1.f - 2.f/(e + 1.f);          // tanh(u), saturates correctly
  return 0.5f*x*(1.0f + t);
}
__device__ __forceinline__ float sigm_f(float x){ return 1.0f/(1.0f + __expf(-x)); }

__device__ __forceinline__ uint32_t smem_u32(const void* p){
  uint32_t a;
  asm("{ .reg .u64 t; cvta.to.shared.u64 t, %1; cvt.u32.u64 %0, t; }" : "=r"(a) : "l"(p));
  return a;
}
__device__ __forceinline__ void cp16(uint32_t saddr, const void* g){
  asm volatile("cp.async.ca.shared.global [%0], [%1], 16;" :: "r"(saddr), "l"(g));
}
#define CP_COMMIT() asm volatile("cp.async.commit_group;" ::: "memory")

__device__ __forceinline__ void ldsm4(uint32_t* r, uint32_t addr){
  asm volatile("ldmatrix.sync.aligned.m8n8.x4.shared.b16 {%0,%1,%2,%3}, [%4];"
    : "=r"(r[0]), "=r"(r[1]), "=r"(r[2]), "=r"(r[3]) : "r"(addr));
}
__device__ __forceinline__ void mma16816(float* c, const uint32_t* a, const uint32_t* b){
  asm volatile("mma.sync.aligned.m16n8k16.row.col.f32.bf16.bf16.f32 "
    "{%0,%1,%2,%3}, {%4,%5,%6,%7}, {%8,%9}, {%0,%1,%2,%3};"
    : "+f"(c[0]), "+f"(c[1]), "+f"(c[2]), "+f"(c[3])
    : "r"(a[0]), "r"(a[1]), "r"(a[2]), "r"(a[3]), "r"(b[0]), "r"(b[1]));
}

// ----------------- twiddle init ---------------------------------------------
__global__ void init_tw_kernel(){
  int i = blockIdx.x*256 + threadIdx.x;
  if (i < 1024){
    float a = (float)(6.283185307179586/2048.0) * (float)i;
    float s, c; sincosf(a, &s, &c);
    g_twA[i] = make_float2(c, -s);
  }
  if (i < 2048){
    float a = (float)(3.141592653589793/2048.0) * (float)i;
    float s, c; sincosf(a, &s, &c);
    g_twB[i] = make_float2(c, -s);
  }
}

// ----------------- layernorm: xin -> g_h (+ optional bf16 split) ------------
__global__ __launch_bounds__(256) void ln_kernel(const float* __restrict__ xin,
                                                 const float* __restrict__ sc,
                                                 const float* __restrict__ bi,
                                                 int wsplit){
  int warp = threadIdx.x >> 5, lane = threadIdx.x & 31;
  size_t row = (size_t)blockIdx.x*8 + warp;
  const float4* xr = (const float4*)(xin + row*Hdim);
  float4 v[4];
  float s = 0.f, s2 = 0.f;
  #pragma unroll
  for (int i = 0; i < 4; i++){
    float4 t = xr[lane + 32*i];
    v[i] = t;
    s  += t.x + t.y + t.z + t.w;
    s2 += t.x*t.x + t.y*t.y + t.z*t.z + t.w*t.w;
  }
  #pragma unroll
  for (int o = 16; o; o >>= 1){
    s  += __shfl_xor_sync(0xffffffffu, s,  o);
    s2 += __shfl_xor_sync(0xffffffffu, s2, o);
  }
  float mean = s*(1.f/Hdim);
  float var  = s2*(1.f/Hdim) - mean*mean;
  float inv  = rsqrtf(var + 1e-6f);
  float4* orow = (float4*)(g_h + row*Hdim);
  const float4* s4 = (const float4*)sc;
  const float4* b4 = (const float4*)bi;
  #pragma unroll
  for (int i = 0; i < 4; i++){
    int ci = lane + 32*i;
    float4 sv = s4[ci], bv = b4[ci], t = v[i], o;
    o.x = (t.x-mean)*inv*sv.x + bv.x;
    o.y = (t.y-mean)*inv*sv.y + bv.y;
    o.z = (t.z-mean)*inv*sv.z + bv.z;
    o.w = (t.w-mean)*inv*sv.w + bv.w;
    orow[ci] = o;
    if (wsplit){
      size_t gi = row*Hdim + ci*4;
      __nv_bfloat16 h0 = __float2bfloat16_rn(o.x);
      __nv_bfloat16 h1 = __float2bfloat16_rn(o.y);
      __nv_bfloat16 h2 = __float2bfloat16_rn(o.z);
      __nv_bfloat16 h3 = __float2bfloat16_rn(o.w);
      __nv_bfloat162 p0; p0.x = h0; p0.y = h1;
      __nv_bfloat162 p1; p1.x = h2; p1.y = h3;
      *(__nv_bfloat162*)(g_a0 + gi)     = p0;
      *(__nv_bfloat162*)(g_a0 + gi + 2) = p1;
      __nv_bfloat162 q0, q1;
      q0.x = __float2bfloat16_rn(o.x - __bfloat162float(h0));
      q0.y = __float2bfloat16_rn(o.y - __bfloat162float(h1));
      q1.x = __float2bfloat16_rn(o.z - __bfloat162float(h2));
      q1.y = __float2bfloat16_rn(o.w - __bfloat162float(h3));
      *(__nv_bfloat162*)(g_a1 + gi)     = q0;
      *(__nv_bfloat162*)(g_a1 + gi + 2) = q1;
    }
  }
}

// ----------------- transposes -----------------------------------------------
__global__ void transpose_fwd_kernel(){
  __shared__ float tile[32][33];
  int b  = blockIdx.z;
  int h0 = blockIdx.x*32;
  int l0 = blockIdx.y*32;
  int tx = threadIdx.x, ty = threadIdx.y;
  const float* in = g_h + (size_t)b*Lseq*Hdim;
  float* out = g_ht + (size_t)b*Hdim*Lseq;
  #pragma unroll
  for (int j = 0; j < 32; j += 8)
    tile[ty+j][tx] = in[(size_t)(l0+ty+j)*Hdim + h0 + tx];
  __syncthreads();
  #pragma unroll
  for (int j = 0; j < 32; j += 8)
    out[(size_t)(h0+ty+j)*Lseq + l0 + tx] = tile[tx][ty+j];
}

__global__ void transpose_bwd_kernel(const float* __restrict__ D){
  __shared__ float tile[32][33];
  int b  = blockIdx.z;
  int h0 = blockIdx.x*32;
  int l0 = blockIdx.y*32;
  int tx = threadIdx.x, ty = threadIdx.y;
  const float* in = g_yt + (size_t)b*Hdim*Lseq;
  float* out = g_v + (size_t)b*Lseq*Hdim;
  const float* hbuf = g_h + (size_t)b*Lseq*Hdim;
  #pragma unroll
  for (int j = 0; j < 32; j += 8)
    tile[ty+j][tx] = in[(size_t)(h0+ty+j)*Lseq + l0 + tx];
  __syncthreads();
  size_t boff = (size_t)b*Lseq*Hdim;
  #pragma unroll
  for (int j = 0; j < 32; j += 8){
    size_t idx = (size_t)(l0+ty+j)*Hdim + h0 + tx;
    float y = tile[tx][ty+j] + D[h0+tx]*hbuf[idx];
    float g = gelu_f(y);
    out[idx] = g;
    __nv_bfloat16 hi = __float2bfloat16_rn(g);
    float r = g - __bfloat162float(hi);
    g_a0[boff + idx] = hi;
    g_a1[boff + idx] = __float2bfloat16_rn(r);
  }
}

// ----------------- weight transpose + split ----------------------------------
__global__ void wprep_kernel(const float* __restrict__ W, int widx){
  __shared__ float tile[32][33];
  int n0 = blockIdx.x*32, k0 = blockIdx.y*32;
  int tx = threadIdx.x, ty = threadIdx.y;
  #pragma unroll
  for (int j = 0; j < 32; j += 8)
    tile[ty+j][tx] = W[(size_t)(k0+ty+j)*Hdim + n0 + tx];
  __syncthreads();
  size_t base = (size_t)widx*HH;
  #pragma unroll
  for (int j = 0; j < 32; j += 8){
    float a = tile[tx][ty+j];
    size_t o = base + (size_t)(n0+ty+j)*Hdim + k0 + tx;
    __nv_bfloat16 hi = __float2bfloat16_rn(a);
    g_wt0[o] = hi;
    g_wt1[o] = __float2bfloat16_rn(a - __bfloat162float(hi));
  }
}

// ----------------- Cauchy kernel (prep fused in) -----------------------------
__global__ __launch_bounds__(256) void cauchy_kernel(
    const float* __restrict__ Lre, const float* __restrict__ Lim,
    const float* __restrict__ Pre, const float* __restrict__ Pim,
    const float* __restrict__ Bre, const float* __restrict__ Bim,
    const float* __restrict__ Cre, const float* __restrict__ Cim,
    const float* __restrict__ logstep){
  __shared__ float4 spk01[Nst];
  __shared__ float4 spk23[Nst];
  __shared__ float2 slam [Nst];
  __shared__ float  s2step;
  int tid = threadIdx.x;
  int h = blockIdx.y;
  int l = blockIdx.x*256 + tid;
  if (tid < Nst){
    int i = h*Nst + tid;
    float pr = Pre[i], pi = Pim[i];
    float br = Bre[i], bi = Bim[i];
    float cr = Cre[i], ci = Cim[i];
    spk01[tid] = make_float4(cr*br + ci*bi, cr*bi - ci*br,
                             cr*pr + ci*pi, cr*pi - ci*pr);
    spk23[tid] = make_float4(pr*br + pi*bi, pr*bi - pi*br,
                             pr*pr + pi*pi, 0.f);
    slam [tid] = make_float2(fminf(Lre[i], -1e-4f), Lim[i]);
  }
  if (tid == 0) s2step = 2.f*expf(-logstep[h]);
  __syncthreads();
  float t   = tanf((float)(3.141592653589793/2048.0)*(float)l);
  float gim = s2step*t;
  float k00r=0.f,k00i=0.f,k01r=0.f,k01i=0.f,k10r=0.f,k10i=0.f,k11r=0.f,k11i=0.f;
  #pragma unroll 8
  for (int n = 0; n < Nst; n++){
    float2 lam = slam[n];
    float dre = -lam.x;
    float dim = gim - lam.y;
    float inv = frcp_fast(dre*dre + dim*dim);
    float ir  =  dre*inv;
    float ii  = -dim*inv;
    float4 w01 = spk01[n];
    float4 w23 = spk23[n];
    k00r += w01.x*ir - w01.y*ii;  k00i += w01.x*ii + w01.y*ir;
    k01r += w01.z*ir - w01.w*ii;  k01i += w01.z*ii + w01.w*ir;
    k10r += w23.x*ir - w23.y*ii;  k10i += w23.x*ii + w23.y*ir;
    k11r += w23.z*ir;             k11i += w23.z*ii;
  }
  float denr = 1.f + k11r, deni = k11i;
  float dinv = frcp_fast(denr*denr + deni*deni);
  float qr = denr*dinv, qi = -deni*dinv;
  float mr = k01r*k10r - k01i*k10i;
  float mi = k01r*k10i + k01i*k10r;
  float cr = mr*qr - mi*qi, ci2 = mr*qi + mi*qr;
  float ar = k00r - cr, ai = k00i - ci2;
  g_ar[(size_t)h*Lseq + l] = make_float2(ar - t*ai, ai + t*ar);
}

// ----------------- shared-mem radix-4 Stockham FFT(2048) ---------------------
template<bool INV>
__device__ __forceinline__ float2* fft2048_r4(float2* buf0, float2* buf1,
                                              const float2* stw, int tid){
  float2* src = buf0; float2* dst = buf1;
  #pragma unroll
  for (int st = 0; st < 5; st++){
    int s = 1 << (2*st);
    __syncthreads();
    #pragma unroll
    for (int i = 0; i < 2; i++){
      int idx = tid + 256*i;
      int sp  = idx & ~(s-1);
      float2 a0 = src[idx];
      float2 a1 = src[idx + 512];
      float2 a2 = src[idx + 1024];
      float2 a3 = src[idx + 1536];
      float2 w1 = stw[sp];
      float2 w2 = stw[2*sp];
      if (INV){ w1.y = -w1.y; w2.y = -w2.y; }
      float2 w3 = cmul(w1, w2);
      float2 t0 = cadd(a0, a2), t1 = csub(a0, a2);
      float2 t2 = cadd(a1, a3), t3 = csub(a1, a3);
      float2 b0 = cadd(t0, t2);
      float2 b2 = csub(t0, t2);
      float2 b1, b3;
      if (!INV){
        b1 = make_float2(t1.x + t3.y, t1.y - t3.x);
        b3 = make_float2(t1.x - t3.y, t1.y + t3.x);
      } else {
        b1 = make_float2(t1.x - t3.y, t1.y + t3.x);
        b3 = make_float2(t1.x + t3.y, t1.y - t3.x);
      }
      int j = idx + 3*sp;
      dst[j]       = b0;
      dst[j + s]   = cmul(b1, w1);
      dst[j + 2*s] = cmul(b2, w2);
      dst[j + 3*s] = cmul(b3, w3);
    }
    float2* tp = src; src = dst; dst = tp;
  }
  __syncthreads();
  #pragma unroll
  for (int i = 0; i < 4; i++){
    int idx = tid + 256*i;
    float2 a = src[idx];
    float2 b = src[idx + 1024];
    dst[idx]        = cadd(a, b);
    dst[idx + 1024] = csub(a, b);
  }
  float2* tp = src; src = dst; dst = tp;
  __syncthreads();
  return src;
}

// ----------------- Kd kernel ------------------------------------------------
__global__ __launch_bounds__(256) void kd_kernel(float2* __restrict__ Kd){
  __shared__ float2 sA[2048];
  __shared__ float2 sB[2048];
  __shared__ float2 stw[1024];
  int tid = threadIdx.x;
  int h = blockIdx.x;
  for (int i = tid; i < 1024; i += 256) stw[i] = g_twA[i];
  const float2* ar = g_ar + (size_t)h*Lseq;
  #pragma unroll
  for (int i = 0; i < 8; i++){ int k = tid + 256*i; sA[k] = ar[k]; }
  float2* K = fft2048_r4<true>(sA, sB, stw, tid);
  float2* Ob = (K == sA) ? sB : sA;
  const float sc = 1.f/2048.f;
  #pragma unroll
  for (int i = 0; i < 8; i++){
    int n = tid + 256*i;
    float2 v = make_float2(0.f, 0.f);
    if (n < 1024) v = make_float2(K[2*n].x*sc, K[2*n+1].x*sc);
    Ob[n] = v;
  }
  float2* Zp = fft2048_r4<false>(Ob, K, stw, tid);
  float2* outKd = Kd + (size_t)h*2049;
  #pragma unroll
  for (int i = 0; i < 8; i++){
    int k  = tid + 256*i;
    int kc = (2048 - k) & 2047;
    float2 zk = Zp[k], zc = Zp[kc];
    float2 E  = make_float2(0.5f*(zk.x+zc.x),  0.5f*(zk.y-zc.y));
    float2 Od = make_float2(0.5f*(zk.y+zc.y), -0.5f*(zk.x-zc.x));
    outKd[k] = cadd(E, cmul(g_twB[k], Od));
  }
  if (tid == 0){
    float2 z0 = Zp[0];
    outKd[2048] = make_float2(z0.x - z0.y, 0.f);
  }
}

// ----------------- conv kernel ----------------------------------------------
__global__ __launch_bounds__(256) void conv_kernel(const float2* __restrict__ Kdbase){
  __shared__ float2 sA[2048];
  __shared__ float2 sB[2048];
  __shared__ float2 stw[1024];
  __shared__ float2 sY2048;
  int tid = threadIdx.x;
  int h = blockIdx.x;
  int b = blockIdx.y;
  const float* u = g_ht + ((size_t)b*Hdim + h)*Lseq;
  for (int i = tid; i < 1024; i += 256) stw[i] = g_twA[i];
  #pragma unroll
  for (int i = 0; i < 4; i++){
    int n = tid + 256*i;
    sA[n]        = make_float2(u[2*n], u[2*n+1]);
    sA[n + 1024] = make_float2(0.f, 0.f);
  }
  float2* Z = fft2048_r4<false>(sA, sB, stw, tid);
  float2* O = (Z == sA) ? sB : sA;
  const float2* kd = Kdbase + (size_t)h*2049;
  #pragma unroll
  for (int i = 0; i < 8; i++){
    int k  = tid + 256*i;
    int kc = (2048 - k) & 2047;
    float2 zk = Z[k], zc = Z[kc];
    float2 E  = make_float2(0.5f*(zk.x+zc.x),  0.5f*(zk.y-zc.y));
    float2 Od = make_float2(0.5f*(zk.y+zc.y), -0.5f*(zk.x-zc.x));
    float2 U  = cadd(E, cmul(g_twB[k], Od));
    O[k] = cmul(U, kd[k]);
  }
  if (tid == 0){
    float2 z0 = Z[0];
    float U2048 = z0.x - z0.y;
    float2 kv = kd[2048];
    sY2048 = make_float2(U2048*kv.x, U2048*kv.y);
  }
  __syncthreads();
  #pragma unroll
  for (int i = 0; i < 8; i++){
    int k = tid + 256*i;
    float2 Yk = O[k];
    float2 Yc = (k == 0) ? sY2048 : O[2048 - k];
    float2 Ey = make_float2(0.5f*(Yk.x+Yc.x), 0.5f*(Yk.y-Yc.y));
    float2 Dm = make_float2(0.5f*(Yk.x-Yc.x), 0.5f*(Yk.y+Yc.y));
    float2 tb = g_twB[k];
    float2 Oy = cmul(Dm, make_float2(tb.x, -tb.y));
    Z[k] = make_float2(Ey.x - Oy.y, Ey.y + Oy.x);
  }
  float2* w = fft2048_r4<true>(Z, O, stw, tid);
  float* out = g_yt + ((size_t)b*Hdim + h)*Lseq;
  const float sc = 1.f/2048.f;
  #pragma unroll
  for (int i = 0; i < 4; i++){
    int n = tid + 256*i;
    float2 v = w[n];
    out[2*n]   = v.x*sc;
    out[2*n+1] = v.y*sc;
  }
}

// ----------------- HMMA GEMM: 128x128 tile, bf16x3 (R8-proven config) --------
// mode 0: C = acc+bias            mode 1: C = gelu(acc+bias)
// mode 2: C = resid + aux*sigmoid(acc+bias)   mode 3: C = resid + acc+bias
#define TROW    80
#define TBYTES  (128*TROW)
#define STAGEB  (4*TBYTES)
#define SMEM_GEMM (2*STAGEB)            // 81920

__global__ __launch_bounds__(256) void hgemm_kernel(
    const __nv_bfloat16* __restrict__ A0g, const __nv_bfloat16* __restrict__ A1g,
    const __nv_bfloat16* __restrict__ B0g, const __nv_bfloat16* __restrict__ B1g,
    const float* __restrict__ bias, const float* __restrict__ aux,
    const float* __restrict__ resid,
    float* __restrict__ C, int mode,
    __nv_bfloat16* __restrict__ S0, __nv_bfloat16* __restrict__ S1)
{
  extern __shared__ char smem[];
  uint32_t sb = smem_u32(smem);
  int tid = threadIdx.x, wid = tid >> 5, lid = tid & 31;
  int bn = blockIdx.x*128, bm = blockIdx.y*128;
  int mw = wid & 3, nw = wid >> 2;

  int lrow = tid >> 1;
  int lc0  = tid & 1;

  int arow = lid & 15;
  int aoff = (lid >> 4) * 16;
  int brow = ((lid >> 4) << 3) + (lid & 7);
  int boff = ((lid >> 3) & 1) * 16;

  float acc[2][8][4];
  #pragma unroll
  for (int i = 0; i < 2; i++)
    #pragma unroll
    for (int j = 0; j < 8; j++)
      #pragma unroll
      for (int q = 0; q < 4; q++) acc[i][j][q] = 0.f;

  #pragma unroll
  for (int j = 0; j < 2; j++){
    int c = lc0 + 2*j;
    uint32_t so = (uint32_t)lrow*TROW + (uint32_t)c*16;
    size_t ga = (size_t)(bm + lrow)*Hdim + c*8;
    size_t gb = (size_t)(bn + lrow)*Hdim + c*8;
    cp16(sb + so,             A0g + ga);
    cp16(sb + TBYTES   + so,  A1g + ga);
    cp16(sb + 2*TBYTES + so,  B0g + gb);
    cp16(sb + 3*TBYTES + so,  B1g + gb);
  }
  CP_COMMIT();

  for (int ch = 0; ch < 16; ch++){
    int st = ch & 1;
    if (ch < 15){
      uint32_t sbase = sb + (st^1)*STAGEB;
      int k0 = (ch+1)*32;
      #pragma unroll
      for (int j = 0; j < 2; j++){
        int c = lc0 + 2*j;
        uint32_t so = (uint32_t)lrow*TROW + (uint32_t)c*16;
        size_t ga = (size_t)(bm + lrow)*Hdim + k0 + c*8;
        size_t gb = (size_t)(bn + lrow)*Hdim + k0 + c*8;
        cp16(sbase + so,             A0g + ga);
        cp16(sbase + TBYTES   + so,  A1g + ga);
        cp16(sbase + 2*TBYTES + so,  B0g + gb);
        cp16(sbase + 3*TBYTES + so,  B1g + gb);
      }
      CP_COMMIT();
      asm volatile("cp.async.wait_group 1;" ::: "memory");
    } else {
      asm volatile("cp.async.wait_group 0;" ::: "memory");
    }
    __syncthreads();

    uint32_t sA0 = sb + st*STAGEB;
    uint32_t sA1 = sA0 + TBYTES;
    uint32_t sB0 = sA0 + 2*TBYTES;
    uint32_t sB1 = sA0 + 3*TBYTES;
    #pragma unroll
    for (int ks = 0; ks < 2; ks++){
      int kb = ks*32;
      uint32_t a0f[2][4], a1f[2][4], b0f[4][4], b1f[4][4];
      #pragma unroll
      for (int mi = 0; mi < 2; mi++){
        uint32_t ro = (uint32_t)(mw*32 + mi*16 + arow)*TROW + kb + aoff;
        ldsm4(a0f[mi], sA0 + ro);
        ldsm4(a1f[mi], sA1 + ro);
      }
      #pragma unroll
      for (int nj = 0; nj < 4; nj++){
        uint32_t ro = (uint32_t)(nw*64 + nj*16 + brow)*TROW + kb + boff;
        ldsm4(b0f[nj], sB0 + ro);
        ldsm4(b1f[nj], sB1 + ro);
      }
      #pragma unroll
      for (int mi = 0; mi < 2; mi++){
        #pragma unroll
        for (int nt = 0; nt < 8; nt++){
          int nj = nt >> 1, sub = (nt & 1)*2;
          mma16816(acc[mi][nt], a0f[mi], &b0f[nj][sub]);
          mma16816(acc[mi][nt], a1f[mi], &b0f[nj][sub]);
          mma16816(acc[mi][nt], a0f[mi], &b1f[nj][sub]);
        }
      }
    }
    __syncthreads();
  }

  // epilogue
  int qr = lid >> 2, qc = (lid & 3)*2;
  #pragma unroll
  for (int mi = 0; mi < 2; mi++){
    #pragma unroll
    for (int hf = 0; hf < 2; hf++){
      int row = bm + mw*32 + mi*16 + hf*8 + qr;
      float* crow = C + (size_t)row*Hdim;
      const float* xrow = aux + (size_t)row*Hdim;
      const float* rrow = resid + (size_t)row*Hdim;
      #pragma unroll
      for (int nt = 0; nt < 8; nt++){
        int col = bn + nw*64 + nt*8 + qc;
        float2 bv = *(const float2*)(bias + col);
        float v0 = acc[mi][nt][hf*2+0] + bv.x;
        float v1 = acc[mi][nt][hf*2+1] + bv.y;
        float2 o;
        if (mode == 0){
          o = make_float2(v0, v1);
        } else if (mode == 1){
          o = make_float2(gelu_f(v0), gelu_f(v1));
        } else if (mode == 2){
          float2 rv = *(const float2*)(rrow + col);
          float2 av = *(const float2*)(xrow + col);
          o.x = rv.x + av.x*sigm_f(v0);
          o.y = rv.y + av.y*sigm_f(v1);
        } else {
          float2 rv = *(const float2*)(rrow + col);
          o = make_float2(rv.x + v0, rv.y + v1);
        }
        *(float2*)(crow + col) = o;
        if (S0){
          size_t gi = (size_t)row*Hdim + col;
          __nv_bfloat16 h0 = __float2bfloat16_rn(o.x);
          __nv_bfloat16 h1 = __float2bfloat16_rn(o.y);
          __nv_bfloat162 p; p.x = h0; p.y = h1;
          *(__nv_bfloat162*)(S0 + gi) = p;
          __nv_bfloat162 q;
          q.x = __float2bfloat16_rn(o.x - __bfloat162float(h0));
          q.y = __float2bfloat16_rn(o.y - __bfloat162float(h1));
          *(__nv_bfloat162*)(S1 + gi) = q;
        }
      }
    }
  }
}

// ----------------- host driver ----------------------------------------------
extern "C" void kernel_launch(void* const* d_in, const int* in_sizes, int n_in,
                              void* d_out, int out_size){
  (void)in_sizes; (void)n_in; (void)out_size;
  const float* x     = (const float*)d_in[0];
  const float* sLre  = (const float*)d_in[1];
  const float* sLim  = (const float*)d_in[2];
  const float* sPre  = (const float*)d_in[3];
  const float* sPim  = (const float*)d_in[4];
  const float* sBre  = (const float*)d_in[5];
  const float* sBim  = (const float*)d_in[6];
  const float* sCre  = (const float*)d_in[7];
  const float* sCim  = (const float*)d_in[8];
  const float* sD    = (const float*)d_in[9];
  const float* sLog  = (const float*)d_in[10];
  const float* sb_ls = (const float*)d_in[11];
  const float* sb_lb = (const float*)d_in[12];
  const float* sb_W1 = (const float*)d_in[13];
  const float* sb_b1 = (const float*)d_in[14];
  const float* sb_W2 = (const float*)d_in[15];
  const float* sb_b2 = (const float*)d_in[16];
  const float* bk_ls = (const float*)d_in[17];
  const float* bk_lb = (const float*)d_in[18];
  const float* bk_W1 = (const float*)d_in[19];
  const float* bk_b1 = (const float*)d_in[20];
  const float* bk_W2 = (const float*)d_in[21];
  const float* bk_b2 = (const float*)d_in[22];
  float* out = (float*)d_out;

  float *p_x, *p_z1;
  float2* p_kd;
  __nv_bfloat16 *p_a0, *p_a1, *p_b0, *p_b1, *p_wt0, *p_wt1;
  cudaGetSymbolAddress((void**)&p_x,   g_x);
  cudaGetSymbolAddress((void**)&p_z1,  g_z1);
  cudaGetSymbolAddress((void**)&p_kd,  g_KdL);
  cudaGetSymbolAddress((void**)&p_a0,  g_a0);
  cudaGetSymbolAddress((void**)&p_a1,  g_a1);
  cudaGetSymbolAddress((void**)&p_b0,  g_b0);
  cudaGetSymbolAddress((void**)&p_b1,  g_b1);
  cudaGetSymbolAddress((void**)&p_wt0, g_wt0);
  cudaGetSymbolAddress((void**)&p_wt1, g_wt1);

  cudaFuncSetAttribute(hgemm_kernel, cudaFuncAttributeMaxDynamicSharedMemorySize, SMEM_GEMM);

  cudaStream_t s2;
  cudaStreamCreateWithFlags(&s2, cudaStreamNonBlocking);
  cudaEvent_t evStart, evKd[4], evW[4], evWB[2];
  cudaEventCreateWithFlags(&evStart, cudaEventDisableTiming);
  for (int i = 0; i < 4; i++){
    cudaEventCreateWithFlags(&evKd[i], cudaEventDisableTiming);
    cudaEventCreateWithFlags(&evW[i],  cudaEventDisableTiming);
  }
  for (int b = 0; b < 2; b++) cudaEventCreateWithFlags(&evWB[b], cudaEventDisableTiming);

  dim3 wgrid(16, 16);
  dim3 tblk(32, 8);
  dim3 tgrid(Hdim/32, Lseq/32, Bsz);
  dim3 ggrid(Hdim/128, NROW/128);

  init_tw_kernel<<<8, 256>>>();
  cudaEventRecord(evStart, 0);
  cudaStreamWaitEvent(s2, evStart, 0);

  cauchy_kernel<<<dim3(Lseq/256, Hdim), 256, 0, s2>>>(
      sLre, sLim, sPre, sPim, sBre, sBim, sCre, sCim, sLog);
  ln_kernel<<<NROW/8, 256>>>(x, sb_ls, sb_lb, 0);
  transpose_fwd_kernel<<<tgrid, tblk>>>();
  kd_kernel<<<Hdim, 256, 0, s2>>>(p_kd);                         // node 5 (profiled)
  cudaEventRecord(evKd[0], s2);
  wprep_kernel<<<wgrid, tblk, 0, s2>>>(sb_W1, 0);
  wprep_kernel<<<wgrid, tblk, 0, s2>>>(sb_W2, 4);
  cudaEventRecord(evW[0], s2);
  for (int i = 1; i < 4; i++){
    cauchy_kernel<<<dim3(Lseq/256, Hdim), 256, 0, s2>>>(
        sLre + i*HN, sLim + i*HN, sPre + i*HN, sPim + i*HN,
        sBre + i*HN, sBim + i*HN, sCre + i*HN, sCim + i*HN, sLog + i*Hdim);
    kd_kernel<<<Hdim, 256, 0, s2>>>(p_kd + (size_t)i*KDSZ);
    cudaEventRecord(evKd[i], s2);
    wprep_kernel<<<wgrid, tblk, 0, s2>>>(sb_W1 + (size_t)i*HH, i);
    wprep_kernel<<<wgrid, tblk, 0, s2>>>(sb_W2 + (size_t)i*HH, 4 + i);
    cudaEventRecord(evW[i], s2);
  }
  for (int b = 0; b < 2; b++){
    wprep_kernel<<<wgrid, tblk, 0, s2>>>(bk_W1 + (size_t)b*HH, 8 + b);
    wprep_kernel<<<wgrid, tblk, 0, s2>>>(bk_W2 + (size_t)b*HH, 10 + b);
    cudaEventRecord(evWB[b], s2);
  }

  for (int b = 0; b < 2; b++){
    for (int li = 0; li < 2; li++){
      int i = b*2 + li;
      if (i > 0){
        ln_kernel<<<NROW/8, 256>>>(p_x, sb_ls + i*Hdim, sb_lb + i*Hdim, 0);
        transpose_fwd_kernel<<<tgrid, tblk>>>();
      }
      cudaStreamWaitEvent(0, evKd[i], 0);
      conv_kernel<<<dim3(Hdim, Bsz), 256>>>(p_kd + (size_t)i*KDSZ);
      transpose_bwd_kernel<<<tgrid, tblk>>>(sD + i*Hdim);
      cudaStreamWaitEvent(0, evW[i], 0);
      hgemm_kernel<<<ggrid, 256, SMEM_GEMM>>>(p_a0, p_a1,
          p_wt0 + (size_t)i*HH, p_wt1 + (size_t)i*HH,
          sb_b1 + i*Hdim, p_z1, p_z1, p_z1, 0, nullptr, nullptr);
      const float* res = (i == 0) ? x : p_x;
      hgemm_kernel<<<ggrid, 256, SMEM_GEMM>>>(p_a0, p_a1,
          p_wt0 + (size_t)(4+i)*HH, p_wt1 + (size_t)(4+i)*HH,
          sb_b2 + i*Hdim, p_z1, res, p_x, 2, nullptr, nullptr);
    }
    ln_kernel<<<NROW/8, 256>>>(p_x, bk_ls + b*Hdim, bk_lb + b*Hdim, 1);
    cudaStreamWaitEvent(0, evWB[b], 0);
    hgemm_kernel<<<ggrid, 256, SMEM_GEMM>>>(p_a0, p_a1,
        p_wt0 + (size_t)(8+b)*HH, p_wt1 + (size_t)(8+b)*HH,
        bk_b1 + b*Hdim, p_z1, p_z1, p_z1, 1, p_b0, p_b1);
    float* Cfinal = (b == 1) ? out : p_x;
    hgemm_kernel<<<ggrid, 256, SMEM_GEMM>>>(p_b0, p_b1,
        p_wt0 + (size_t)(10+b)*HH, p_wt1 + (size_t)(10+b)*HH,
        bk_b2 + b*Hdim, p_z1, p_x, Cfinal, 3, nullptr, nullptr);
  }
}

// round 13
// speedup vs baseline: 1.2439x; 1.0389x over previous
#include <cuda_runtime.h>
#include <cuda_bf16.h>
#include <cstdint>
#include <math.h>

#define Bsz   8
#define Lseq  2048
#define Hdim  512
#define Nst   64
#define NROW  (Bsz*Lseq)          // 16384
#define BLH   (Bsz*Lseq*Hdim)     // 8388608
#define HH    (Hdim*Hdim)
#define HN    (Hdim*Nst)
#define KDSZ  (Hdim*2049)

// ----------------- device scratch (no allocations allowed) ------------------
__device__ float  g_x [BLH];
__device__ float  g_ht[BLH];
__device__ float  g_yt[BLH];
__device__ float  g_z1[BLH];
__device__ float2 g_ar[Hdim*Lseq];
__device__ float2 g_KdL[4*KDSZ];
__device__ float2 g_twA[1024];
__device__ float2 g_twB[2048];
__device__ __nv_bfloat16 g_a0[BLH];
__device__ __nv_bfloat16 g_a1[BLH];
__device__ __nv_bfloat16 g_b0[BLH];
__device__ __nv_bfloat16 g_b1[BLH];
__device__ __nv_bfloat16 g_wt0[12*HH];
__device__ __nv_bfloat16 g_wt1[12*HH];

// ----------------- helpers --------------------------------------------------
__device__ __forceinline__ float2 cadd(float2 a, float2 b){ return make_float2(a.x+b.x, a.y+b.y); }
__device__ __forceinline__ float2 csub(float2 a, float2 b){ return make_float2(a.x-b.x, a.y-b.y); }
__device__ __forceinline__ float2 cmul(float2 a, float2 b){ return make_float2(a.x*b.x-a.y*b.y, a.x*b.y+a.y*b.x); }
__device__ __forceinline__ float frcp_fast(float x){ float y; asm("rcp.approx.f32 %0, %1;" : "=f"(y) : "f"(x)); return y; }
__device__ __forceinline__ float gelu_f(float x){
  float u = 0.7978845608028654f*(x + 0.044715f*x*x*x);
  float e = __expf(2.f*u);
  float t = 1.f - 2.f/(e + 1.f);          // tanh(u), saturates correctly
  return 0.5f*x*(1.0f + t);
}
__device__ __forceinline__ float sigm_f(float x){ return 1.0f/(1.0f + __expf(-x)); }

__device__ __forceinline__ uint32_t smem_u32(const void* p){
  uint32_t a;
  asm("{ .reg .u64 t; cvta.to.shared.u64 t, %1; cvt.u32.u64 %0, t; }" : "=r"(a) : "l"(p));
  return a;
}
__device__ __forceinline__ void cp16(uint32_t saddr, const void* g){
  asm volatile("cp.async.ca.shared.global [%0], [%1], 16;" :: "r"(saddr), "l"(g));
}
#define CP_COMMIT() asm volatile("cp.async.commit_group;" ::: "memory")

__device__ __forceinline__ void ldsm4(uint32_t* r, uint32_t addr){
  asm volatile("ldmatrix.sync.aligned.m8n8.x4.shared.b16 {%0,%1,%2,%3}, [%4];"
    : "=r"(r[0]), "=r"(r[1]), "=r"(r[2]), "=r"(r[3]) : "r"(addr));
}
__device__ __forceinline__ void mma16816(float* c, const uint32_t* a, const uint32_t* b){
  asm volatile("mma.sync.aligned.m16n8k16.row.col.f32.bf16.bf16.f32 "
    "{%0,%1,%2,%3}, {%4,%5,%6,%7}, {%8,%9}, {%0,%1,%2,%3};"
    : "+f"(c[0]), "+f"(c[1]), "+f"(c[2]), "+f"(c[3])
    : "r"(a[0]), "r"(a[1]), "r"(a[2]), "r"(a[3]), "r"(b[0]), "r"(b[1]));
}

// ----------------- twiddle init ---------------------------------------------
__global__ void init_tw_kernel(){
  int i = blockIdx.x*256 + threadIdx.x;
  if (i < 1024){
    float a = (float)(6.283185307179586/2048.0) * (float)i;
    float s, c; sincosf(a, &s, &c);
    g_twA[i] = make_float2(c, -s);
  }
  if (i < 2048){
    float a = (float)(3.141592653589793/2048.0) * (float)i;
    float s, c; sincosf(a, &s, &c);
    g_twB[i] = make_float2(c, -s);
  }
}

// ----------------- fused LN + transpose: xin (B,L,H) -> g_ht (B,H,L) --------
#define LNT_PAD  513
#define LNT_SMEM (32*LNT_PAD*4)   // 65664 bytes

__global__ __launch_bounds__(256) void lnT_kernel(const float* __restrict__ xin,
                                                  const float* __restrict__ sc,
                                                  const float* __restrict__ bi){
  extern __shared__ float tile[];      // [32][LNT_PAD]
  int b  = blockIdx.y;
  int l0 = blockIdx.x*32;
  int warp = threadIdx.x >> 5, lane = threadIdx.x & 31;
  const float4* s4 = (const float4*)sc;
  const float4* b4 = (const float4*)bi;
  #pragma unroll
  for (int r = warp; r < 32; r += 8){
    const float4* xr = (const float4*)(xin + ((size_t)b*Lseq + l0 + r)*Hdim);
    float4 v[4];
    float s = 0.f, s2 = 0.f;
    #pragma unroll
    for (int i = 0; i < 4; i++){
      float4 t = xr[lane + 32*i];
      v[i] = t;
      s  += t.x + t.y + t.z + t.w;
      s2 += t.x*t.x + t.y*t.y + t.z*t.z + t.w*t.w;
    }
    #pragma unroll
    for (int o = 16; o; o >>= 1){
      s  += __shfl_xor_sync(0xffffffffu, s,  o);
      s2 += __shfl_xor_sync(0xffffffffu, s2, o);
    }
    float mean = s*(1.f/Hdim);
    float var  = s2*(1.f/Hdim) - mean*mean;
    float inv  = rsqrtf(var + 1e-6f);
    float* trow = tile + r*LNT_PAD;
    #pragma unroll
    for (int i = 0; i < 4; i++){
      int ci = lane + 32*i;
      float4 sv = s4[ci], bv = b4[ci], t = v[i];
      trow[ci*4+0] = (t.x-mean)*inv*sv.x + bv.x;
      trow[ci*4+1] = (t.y-mean)*inv*sv.y + bv.y;
      trow[ci*4+2] = (t.z-mean)*inv*sv.z + bv.z;
      trow[ci*4+3] = (t.w-mean)*inv*sv.w + bv.w;
    }
  }
  __syncthreads();
  float* outb = g_ht + (size_t)b*Hdim*Lseq + l0 + lane;
  #pragma unroll 8
  for (int h0 = 0; h0 < Hdim; h0 += 8){
    int h = h0 + warp;
    outb[(size_t)h*Lseq] = tile[lane*LNT_PAD + h];
  }
}

// ----------------- layernorm (FFN path): xin -> bf16 splits only ------------
__global__ __launch_bounds__(256) void ln_kernel(const float* __restrict__ xin,
                                                 const float* __restrict__ sc,
                                                 const float* __restrict__ bi){
  int warp = threadIdx.x >> 5, lane = threadIdx.x & 31;
  size_t row = (size_t)blockIdx.x*8 + warp;
  const float4* xr = (const float4*)(xin + row*Hdim);
  float4 v[4];
  float s = 0.f, s2 = 0.f;
  #pragma unroll
  for (int i = 0; i < 4; i++){
    float4 t = xr[lane + 32*i];
    v[i] = t;
    s  += t.x + t.y + t.z + t.w;
    s2 += t.x*t.x + t.y*t.y + t.z*t.z + t.w*t.w;
  }
  #pragma unroll
  for (int o = 16; o; o >>= 1){
    s  += __shfl_xor_sync(0xffffffffu, s,  o);
    s2 += __shfl_xor_sync(0xffffffffu, s2, o);
  }
  float mean = s*(1.f/Hdim);
  float var  = s2*(1.f/Hdim) - mean*mean;
  float inv  = rsqrtf(var + 1e-6f);
  const float4* s4 = (const float4*)sc;
  const float4* b4 = (const float4*)bi;
  #pragma unroll
  for (int i = 0; i < 4; i++){
    int ci = lane + 32*i;
    float4 sv = s4[ci], bv = b4[ci], t = v[i], o;
    o.x = (t.x-mean)*inv*sv.x + bv.x;
    o.y = (t.y-mean)*inv*sv.y + bv.y;
    o.z = (t.z-mean)*inv*sv.z + bv.z;
    o.w = (t.w-mean)*inv*sv.w + bv.w;
    size_t gi = row*Hdim + ci*4;
    __nv_bfloat16 h0 = __float2bfloat16_rn(o.x);
    __nv_bfloat16 h1 = __float2bfloat16_rn(o.y);
    __nv_bfloat16 h2 = __float2bfloat16_rn(o.z);
    __nv_bfloat16 h3 = __float2bfloat16_rn(o.w);
    __nv_bfloat162 p0; p0.x = h0; p0.y = h1;
    __nv_bfloat162 p1; p1.x = h2; p1.y = h3;
    *(__nv_bfloat162*)(g_a0 + gi)     = p0;
    *(__nv_bfloat162*)(g_a0 + gi + 2) = p1;
    __nv_bfloat162 q0, q1;
    q0.x = __float2bfloat16_rn(o.x - __bfloat162float(h0));
    q0.y = __float2bfloat16_rn(o.y - __bfloat162float(h1));
    q1.x = __float2bfloat16_rn(o.z - __bfloat162float(h2));
    q1.y = __float2bfloat16_rn(o.w - __bfloat162float(h3));
    *(__nv_bfloat162*)(g_a1 + gi)     = q0;
    *(__nv_bfloat162*)(g_a1 + gi + 2) = q1;
  }
}

// ----------------- bwd transpose: g_yt (B,H,L) -> gelu -> bf16 splits -------
// g_yt already contains y + D*h (D feed-through fused into conv).
__global__ void transpose_bwd_kernel(){
  __shared__ float tile[32][33];
  int b  = blockIdx.z;
  int h0 = blockIdx.x*32;
  int l0 = blockIdx.y*32;
  int tx = threadIdx.x, ty = threadIdx.y;
  const float* in = g_yt + (size_t)b*Hdim*Lseq;
  #pragma unroll
  for (int j = 0; j < 32; j += 8)
    tile[ty+j][tx] = in[(size_t)(h0+ty+j)*Lseq + l0 + tx];
  __syncthreads();
  size_t boff = (size_t)b*Lseq*Hdim;
  #pragma unroll
  for (int j = 0; j < 32; j += 8){
    size_t idx = boff + (size_t)(l0+ty+j)*Hdim + h0 + tx;
    float g = gelu_f(tile[tx][ty+j]);
    __nv_bfloat16 hi = __float2bfloat16_rn(g);
    float r = g - __bfloat162float(hi);
    g_a0[idx] = hi;
    g_a1[idx] = __float2bfloat16_rn(r);
  }
}

// ----------------- weight transpose + split ----------------------------------
__global__ void wprep_kernel(const float* __restrict__ W, int widx){
  __shared__ float tile[32][33];
  int n0 = blockIdx.x*32, k0 = blockIdx.y*32;
  int tx = threadIdx.x, ty = threadIdx.y;
  #pragma unroll
  for (int j = 0; j < 32; j += 8)
    tile[ty+j][tx] = W[(size_t)(k0+ty+j)*Hdim + n0 + tx];
  __syncthreads();
  size_t base = (size_t)widx*HH;
  #pragma unroll
  for (int j = 0; j < 32; j += 8){
    float a = tile[tx][ty+j];
    size_t o = base + (size_t)(n0+ty+j)*Hdim + k0 + tx;
    __nv_bfloat16 hi = __float2bfloat16_rn(a);
    g_wt0[o] = hi;
    g_wt1[o] = __float2bfloat16_rn(a - __bfloat162float(hi));
  }
}

// ----------------- Cauchy kernel (prep fused in) -----------------------------
__global__ __launch_bounds__(256) void cauchy_kernel(
    const float* __restrict__ Lre, const float* __restrict__ Lim,
    const float* __restrict__ Pre, const float* __restrict__ Pim,
    const float* __restrict__ Bre, const float* __restrict__ Bim,
    const float* __restrict__ Cre, const float* __restrict__ Cim,
    const float* __restrict__ logstep){
  __shared__ float4 spk01[Nst];
  __shared__ float4 spk23[Nst];
  __shared__ float2 slam [Nst];
  __shared__ float  s2step;
  int tid = threadIdx.x;
  int h = blockIdx.y;
  int l = blockIdx.x*256 + tid;
  if (tid < Nst){
    int i = h*Nst + tid;
    float pr = Pre[i], pi = Pim[i];
    float br = Bre[i], bi = Bim[i];
    float cr = Cre[i], ci = Cim[i];
    spk01[tid] = make_float4(cr*br + ci*bi, cr*bi - ci*br,
                             cr*pr + ci*pi, cr*pi - ci*pr);
    spk23[tid] = make_float4(pr*br + pi*bi, pr*bi - pi*br,
                             pr*pr + pi*pi, 0.f);
    slam [tid] = make_float2(fminf(Lre[i], -1e-4f), Lim[i]);
  }
  if (tid == 0) s2step = 2.f*expf(-logstep[h]);
  __syncthreads();
  float t   = tanf((float)(3.141592653589793/2048.0)*(float)l);
  float gim = s2step*t;
  float k00r=0.f,k00i=0.f,k01r=0.f,k01i=0.f,k10r=0.f,k10i=0.f,k11r=0.f,k11i=0.f;
  #pragma unroll 8
  for (int n = 0; n < Nst; n++){
    float2 lam = slam[n];
    float dre = -lam.x;
    float dim = gim - lam.y;
    float inv = frcp_fast(dre*dre + dim*dim);
    float ir  =  dre*inv;
    float ii  = -dim*inv;
    float4 w01 = spk01[n];
    float4 w23 = spk23[n];
    k00r += w01.x*ir - w01.y*ii;  k00i += w01.x*ii + w01.y*ir;
    k01r += w01.z*ir - w01.w*ii;  k01i += w01.z*ii + w01.w*ir;
    k10r += w23.x*ir - w23.y*ii;  k10i += w23.x*ii + w23.y*ir;
    k11r += w23.z*ir;             k11i += w23.z*ii;
  }
  float denr = 1.f + k11r, deni = k11i;
  float dinv = frcp_fast(denr*denr + deni*deni);
  float qr = denr*dinv, qi = -deni*dinv;
  float mr = k01r*k10r - k01i*k10i;
  float mi = k01r*k10i + k01i*k10r;
  float cr = mr*qr - mi*qi, ci2 = mr*qi + mi*qr;
  float ar = k00r - cr, ai = k00i - ci2;
  g_ar[(size_t)h*Lseq + l] = make_float2(ar - t*ai, ai + t*ar);
}

// ----------------- shared-mem radix-4 Stockham FFT(2048) ---------------------
template<bool INV>
__device__ __forceinline__ float2* fft2048_r4(float2* buf0, float2* buf1,
                                              const float2* stw, int tid){
  float2* src = buf0; float2* dst = buf1;
  #pragma unroll
  for (int st = 0; st < 5; st++){
    int s = 1 << (2*st);
    __syncthreads();
    #pragma unroll
    for (int i = 0; i < 2; i++){
      int idx = tid + 256*i;
      int sp  = idx & ~(s-1);
      float2 a0 = src[idx];
      float2 a1 = src[idx + 512];
      float2 a2 = src[idx + 1024];
      float2 a3 = src[idx + 1536];
      float2 w1 = stw[sp];
      float2 w2 = stw[2*sp];
      if (INV){ w1.y = -w1.y; w2.y = -w2.y; }
      float2 w3 = cmul(w1, w2);
      float2 t0 = cadd(a0, a2), t1 = csub(a0, a2);
      float2 t2 = cadd(a1, a3), t3 = csub(a1, a3);
      float2 b0 = cadd(t0, t2);
      float2 b2 = csub(t0, t2);
      float2 b1, b3;
      if (!INV){
        b1 = make_float2(t1.x + t3.y, t1.y - t3.x);
        b3 = make_float2(t1.x - t3.y, t1.y + t3.x);
      } else {
        b1 = make_float2(t1.x - t3.y, t1.y + t3.x);
        b3 = make_float2(t1.x + t3.y, t1.y - t3.x);
      }
      int j = idx + 3*sp;
      dst[j]       = b0;
      dst[j + s]   = cmul(b1, w1);
      dst[j + 2*s] = cmul(b2, w2);
      dst[j + 3*s] = cmul(b3, w3);
    }
    float2* tp = src; src = dst; dst = tp;
  }
  __syncthreads();
  #pragma unroll
  for (int i = 0; i < 4; i++){
    int idx = tid + 256*i;
    float2 a = src[idx];
    float2 b = src[idx + 1024];
    dst[idx]        = cadd(a, b);
    dst[idx + 1024] = csub(a, b);
  }
  float2* tp = src; src = dst; dst = tp;
  __syncthreads();
  return src;
}

// ----------------- Kd kernel ------------------------------------------------
__global__ __launch_bounds__(256) void kd_kernel(float2* __restrict__ Kd){
  __shared__ float2 sA[2048];
  __shared__ float2 sB[2048];
  __shared__ float2 stw[1024];
  int tid = threadIdx.x;
  int h = blockIdx.x;
  for (int i = tid; i < 1024; i += 256) stw[i] = g_twA[i];
  const float2* ar = g_ar + (size_t)h*Lseq;
  #pragma unroll
  for (int i = 0; i < 8; i++){ int k = tid + 256*i; sA[k] = ar[k]; }
  float2* K = fft2048_r4<true>(sA, sB, stw, tid);
  float2* Ob = (K == sA) ? sB : sA;
  const float sc = 1.f/2048.f;
  #pragma unroll
  for (int i = 0; i < 8; i++){
    int n = tid + 256*i;
    float2 v = make_float2(0.f, 0.f);
    if (n < 1024) v = make_float2(K[2*n].x*sc, K[2*n+1].x*sc);
    Ob[n] = v;
  }
  float2* Zp = fft2048_r4<false>(Ob, K, stw, tid);
  float2* outKd = Kd + (size_t)h*2049;
  #pragma unroll
  for (int i = 0; i < 8; i++){
    int k  = tid + 256*i;
    int kc = (2048 - k) & 2047;
    float2 zk = Zp[k], zc = Zp[kc];
    float2 E  = make_float2(0.5f*(zk.x+zc.x),  0.5f*(zk.y-zc.y));
    float2 Od = make_float2(0.5f*(zk.y+zc.y), -0.5f*(zk.x-zc.x));
    outKd[k] = cadd(E, cmul(g_twB[k], Od));
  }
  if (tid == 0){
    float2 z0 = Zp[0];
    outKd[2048] = make_float2(z0.x - z0.y, 0.f);
  }
}

// ----------------- conv kernel (D feed-through fused) ------------------------
__global__ __launch_bounds__(256) void conv_kernel(const float2* __restrict__ Kdbase,
                                                   const float* __restrict__ Dp){
  __shared__ float2 sA[2048];
  __shared__ float2 sB[2048];
  __shared__ float2 stw[1024];
  __shared__ float2 sY2048;
  int tid = threadIdx.x;
  int h = blockIdx.x;
  int b = blockIdx.y;
  const float* u = g_ht + ((size_t)b*Hdim + h)*Lseq;
  for (int i = tid; i < 1024; i += 256) stw[i] = g_twA[i];
  float ur[8];
  #pragma unroll
  for (int i = 0; i < 4; i++){
    int n = tid + 256*i;
    float u0 = u[2*n], u1 = u[2*n+1];
    ur[2*i] = u0; ur[2*i+1] = u1;
    sA[n]        = make_float2(u0, u1);
    sA[n + 1024] = make_float2(0.f, 0.f);
  }
  float2* Z = fft2048_r4<false>(sA, sB, stw, tid);
  float2* O = (Z == sA) ? sB : sA;
  const float2* kd = Kdbase + (size_t)h*2049;
  #pragma unroll
  for (int i = 0; i < 8; i++){
    int k  = tid + 256*i;
    int kc = (2048 - k) & 2047;
    float2 zk = Z[k], zc = Z[kc];
    float2 E  = make_float2(0.5f*(zk.x+zc.x),  0.5f*(zk.y-zc.y));
    float2 Od = make_float2(0.5f*(zk.y+zc.y), -0.5f*(zk.x-zc.x));
    float2 U  = cadd(E, cmul(g_twB[k], Od));
    O[k] = cmul(U, kd[k]);
  }
  if (tid == 0){
    float2 z0 = Z[0];
    float U2048 = z0.x - z0.y;
    float2 kv = kd[2048];
    sY2048 = make_float2(U2048*kv.x, U2048*kv.y);
  }
  __syncthreads();
  #pragma unroll
  for (int i = 0; i < 8; i++){
    int k = tid + 256*i;
    float2 Yk = O[k];
    float2 Yc = (k == 0) ? sY2048 : O[2048 - k];
    float2 Ey = make_float2(0.5f*(Yk.x+Yc.x), 0.5f*(Yk.y-Yc.y));
    float2 Dm = make_float2(0.5f*(Yk.x-Yc.x), 0.5f*(Yk.y+Yc.y));
    float2 tb = g_twB[k];
    float2 Oy = cmul(Dm, make_float2(tb.x, -tb.y));
    Z[k] = make_float2(Ey.x - Oy.y, Ey.y + Oy.x);
  }
  float2* w = fft2048_r4<true>(Z, O, stw, tid);
  float* out = g_yt + ((size_t)b*Hdim + h)*Lseq;
  const float sc = 1.f/2048.f;
  float Dh = Dp[h];
  #pragma unroll
  for (int i = 0; i < 4; i++){
    int n = tid + 256*i;
    float2 v = w[n];
    out[2*n]   = v.x*sc + Dh*ur[2*i];
    out[2*n+1] = v.y*sc + Dh*ur[2*i+1];
  }
}

// ----------------- HMMA GEMM: 128x128 tile, bf16x3 (R8-proven config) --------
// mode 0: C = acc+bias            mode 1: C = gelu(acc+bias)
// mode 2: C = resid + aux*sigmoid(acc+bias)   mode 3: C = resid + acc+bias
#define TROW    80
#define TBYTES  (128*TROW)
#define STAGEB  (4*TBYTES)
#define SMEM_GEMM (2*STAGEB)            // 81920

__global__ __launch_bounds__(256) void hgemm_kernel(
    const __nv_bfloat16* __restrict__ A0g, const __nv_bfloat16* __restrict__ A1g,
    const __nv_bfloat16* __restrict__ B0g, const __nv_bfloat16* __restrict__ B1g,
    const float* __restrict__ bias, const float* __restrict__ aux,
    const float* __restrict__ resid,
    float* __restrict__ C, int mode,
    __nv_bfloat16* __restrict__ S0, __nv_bfloat16* __restrict__ S1)
{
  extern __shared__ char smem[];
  uint32_t sb = smem_u32(smem);
  int tid = threadIdx.x, wid = tid >> 5, lid = tid & 31;
  int bn = blockIdx.x*128, bm = blockIdx.y*128;
  int mw = wid & 3, nw = wid >> 2;

  int lrow = tid >> 1;
  int lc0  = tid & 1;

  int arow = lid & 15;
  int aoff = (lid >> 4) * 16;
  int brow = ((lid >> 4) << 3) + (lid & 7);
  int boff = ((lid >> 3) & 1) * 16;

  float acc[2][8][4];
  #pragma unroll
  for (int i = 0; i < 2; i++)
    #pragma unroll
    for (int j = 0; j < 8; j++)
      #pragma unroll
      for (int q = 0; q < 4; q++) acc[i][j][q] = 0.f;

  #pragma unroll
  for (int j = 0; j < 2; j++){
    int c = lc0 + 2*j;
    uint32_t so = (uint32_t)lrow*TROW + (uint32_t)c*16;
    size_t ga = (size_t)(bm + lrow)*Hdim + c*8;
    size_t gb = (size_t)(bn + lrow)*Hdim + c*8;
    cp16(sb + so,             A0g + ga);
    cp16(sb + TBYTES   + so,  A1g + ga);
    cp16(sb + 2*TBYTES + so,  B0g + gb);
    cp16(sb + 3*TBYTES + so,  B1g + gb);
  }
  CP_COMMIT();

  for (int ch = 0; ch < 16; ch++){
    int st = ch & 1;
    if (ch < 15){
      uint32_t sbase = sb + (st^1)*STAGEB;
      int k0 = (ch+1)*32;
      #pragma unroll
      for (int j = 0; j < 2; j++){
        int c = lc0 + 2*j;
        uint32_t so = (uint32_t)lrow*TROW + (uint32_t)c*16;
        size_t ga = (size_t)(bm + lrow)*Hdim + k0 + c*8;
        size_t gb = (size_t)(bn + lrow)*Hdim + k0 + c*8;
        cp16(sbase + so,             A0g + ga);
        cp16(sbase + TBYTES   + so,  A1g + ga);
        cp16(sbase + 2*TBYTES + so,  B0g + gb);
        cp16(sbase + 3*TBYTES + so,  B1g + gb);
      }
      CP_COMMIT();
      asm volatile("cp.async.wait_group 1;" ::: "memory");
    } else {
      asm volatile("cp.async.wait_group 0;" ::: "memory");
    }
    __syncthreads();

    uint32_t sA0 = sb + st*STAGEB;
    uint32_t sA1 = sA0 + TBYTES;
    uint32_t sB0 = sA0 + 2*TBYTES;
    uint32_t sB1 = sA0 + 3*TBYTES;
    #pragma unroll
    for (int ks = 0; ks < 2; ks++){
      int kb = ks*32;
      uint32_t a0f[2][4], a1f[2][4], b0f[4][4], b1f[4][4];
      #pragma unroll
      for (int mi = 0; mi < 2; mi++){
        uint32_t ro = (uint32_t)(mw*32 + mi*16 + arow)*TROW + kb + aoff;
        ldsm4(a0f[mi], sA0 + ro);
        ldsm4(a1f[mi], sA1 + ro);
      }
      #pragma unroll
      for (int nj = 0; nj < 4; nj++){
        uint32_t ro = (uint32_t)(nw*64 + nj*16 + brow)*TROW + kb + boff;
        ldsm4(b0f[nj], sB0 + ro);
        ldsm4(b1f[nj], sB1 + ro);
      }
      #pragma unroll
      for (int mi = 0; mi < 2; mi++){
        #pragma unroll
        for (int nt = 0; nt < 8; nt++){
          int nj = nt >> 1, sub = (nt & 1)*2;
          mma16816(acc[mi][nt], a0f[mi], &b0f[nj][sub]);
          mma16816(acc[mi][nt], a1f[mi], &b0f[nj][sub]);
          mma16816(acc[mi][nt], a0f[mi], &b1f[nj][sub]);
        }
      }
    }
    __syncthreads();
  }

  // epilogue
  int qr = lid >> 2, qc = (lid & 3)*2;
  #pragma unroll
  for (int mi = 0; mi < 2; mi++){
    #pragma unroll
    for (int hf = 0; hf < 2; hf++){
      int row = bm + mw*32 + mi*16 + hf*8 + qr;
      float* crow = C + (size_t)row*Hdim;
      const float* xrow = aux + (size_t)row*Hdim;
      const float* rrow = resid + (size_t)row*Hdim;
      #pragma unroll
      for (int nt = 0; nt < 8; nt++){
        int col = bn + nw*64 + nt*8 + qc;
        float2 bv = *(const float2*)(bias + col);
        float v0 = acc[mi][nt][hf*2+0] + bv.x;
        float v1 = acc[mi][nt][hf*2+1] + bv.y;
        float2 o;
        if (mode == 0){
          o = make_float2(v0, v1);
        } else if (mode == 1){
          o = make_float2(gelu_f(v0), gelu_f(v1));
        } else if (mode == 2){
          float2 rv = *(const float2*)(rrow + col);
          float2 av = *(const float2*)(xrow + col);
          o.x = rv.x + av.x*sigm_f(v0);
          o.y = rv.y + av.y*sigm_f(v1);
        } else {
          float2 rv = *(const float2*)(rrow + col);
          o = make_float2(rv.x + v0, rv.y + v1);
        }
        *(float2*)(crow + col) = o;
        if (S0){
          size_t gi = (size_t)row*Hdim + col;
          __nv_bfloat16 h0 = __float2bfloat16_rn(o.x);
          __nv_bfloat16 h1 = __float2bfloat16_rn(o.y);
          __nv_bfloat162 p; p.x = h0; p.y = h1;
          *(__nv_bfloat162*)(S0 + gi) = p;
          __nv_bfloat162 q;
          q.x = __float2bfloat16_rn(o.x - __bfloat162float(h0));
          q.y = __float2bfloat16_rn(o.y - __bfloat162float(h1));
          *(__nv_bfloat162*)(S1 + gi) = q;
        }
      }
    }
  }
}

// ----------------- host driver ----------------------------------------------
extern "C" void kernel_launch(void* const* d_in, const int* in_sizes, int n_in,
                              void* d_out, int out_size){
  (void)in_sizes; (void)n_in; (void)out_size;
  const float* x     = (const float*)d_in[0];
  const float* sLre  = (const float*)d_in[1];
  const float* sLim  = (const float*)d_in[2];
  const float* sPre  = (const float*)d_in[3];
  const float* sPim  = (const float*)d_in[4];
  const float* sBre  = (const float*)d_in[5];
  const float* sBim  = (const float*)d_in[6];
  const float* sCre  = (const float*)d_in[7];
  const float* sCim  = (const float*)d_in[8];
  const float* sD    = (const float*)d_in[9];
  const float* sLog  = (const float*)d_in[10];
  const float* sb_ls = (const float*)d_in[11];
  const float* sb_lb = (const float*)d_in[12];
  const float* sb_W1 = (const float*)d_in[13];
  const float* sb_b1 = (const float*)d_in[14];
  const float* sb_W2 = (const float*)d_in[15];
  const float* sb_b2 = (const float*)d_in[16];
  const float* bk_ls = (const float*)d_in[17];
  const float* bk_lb = (const float*)d_in[18];
  const float* bk_W1 = (const float*)d_in[19];
  const float* bk_b1 = (const float*)d_in[20];
  const float* bk_W2 = (const float*)d_in[21];
  const float* bk_b2 = (const float*)d_in[22];
  float* out = (float*)d_out;

  float *p_x, *p_z1;
  float2* p_kd;
  __nv_bfloat16 *p_a0, *p_a1, *p_b0, *p_b1, *p_wt0, *p_wt1;
  cudaGetSymbolAddress((void**)&p_x,   g_x);
  cudaGetSymbolAddress((void**)&p_z1,  g_z1);
  cudaGetSymbolAddress((void**)&p_kd,  g_KdL);
  cudaGetSymbolAddress((void**)&p_a0,  g_a0);
  cudaGetSymbolAddress((void**)&p_a1,  g_a1);
  cudaGetSymbolAddress((void**)&p_b0,  g_b0);
  cudaGetSymbolAddress((void**)&p_b1,  g_b1);
  cudaGetSymbolAddress((void**)&p_wt0, g_wt0);
  cudaGetSymbolAddress((void**)&p_wt1, g_wt1);

  cudaFuncSetAttribute(hgemm_kernel, cudaFuncAttributeMaxDynamicSharedMemorySize, SMEM_GEMM);
  cudaFuncSetAttribute(lnT_kernel,   cudaFuncAttributeMaxDynamicSharedMemorySize, LNT_SMEM);

  cudaStream_t s2;
  cudaStreamCreateWithFlags(&s2, cudaStreamNonBlocking);
  cudaEvent_t evStart, evKd[4], evW[4], evWB[2];
  cudaEventCreateWithFlags(&evStart, cudaEventDisableTiming);
  for (int i = 0; i < 4; i++){
    cudaEventCreateWithFlags(&evKd[i], cudaEventDisableTiming);
    cudaEventCreateWithFlags(&evW[i],  cudaEventDisableTiming);
  }
  for (int b = 0; b < 2; b++) cudaEventCreateWithFlags(&evWB[b], cudaEventDisableTiming);

  dim3 wgrid(16, 16);
  dim3 tblk(32, 8);
  dim3 tgrid(Hdim/32, Lseq/32, Bsz);
  dim3 lgrid(Lseq/32, Bsz);
  dim3 ggrid(Hdim/128, NROW/128);

  init_tw_kernel<<<8, 256>>>();
  cudaEventRecord(evStart, 0);
  cudaStreamWaitEvent(s2, evStart, 0);

  cauchy_kernel<<<dim3(Lseq/256, Hdim), 256, 0, s2>>>(
      sLre, sLim, sPre, sPim, sBre, sBim, sCre, sCim, sLog);
  lnT_kernel<<<lgrid, 256, LNT_SMEM>>>(x, sb_ls, sb_lb);
  kd_kernel<<<Hdim, 256, 0, s2>>>(p_kd);
  cudaEventRecord(evKd[0], s2);
  wprep_kernel<<<wgrid, tblk, 0, s2>>>(sb_W1, 0);
  wprep_kernel<<<wgrid, tblk, 0, s2>>>(sb_W2, 4);
  cudaEventRecord(evW[0], s2);
  for (int i = 1; i < 4; i++){
    cauchy_kernel<<<dim3(Lseq/256, Hdim), 256, 0, s2>>>(
        sLre + i*HN, sLim + i*HN, sPre + i*HN, sPim + i*HN,
        sBre + i*HN, sBim + i*HN, sCre + i*HN, sCim + i*HN, sLog + i*Hdim);
    kd_kernel<<<Hdim, 256, 0, s2>>>(p_kd + (size_t)i*KDSZ);
    cudaEventRecord(evKd[i], s2);
    wprep_kernel<<<wgrid, tblk, 0, s2>>>(sb_W1 + (size_t)i*HH, i);
    wprep_kernel<<<wgrid, tblk, 0, s2>>>(sb_W2 + (size_t)i*HH, 4 + i);
    cudaEventRecord(evW[i], s2);
  }
  for (int b = 0; b < 2; b++){
    wprep_kernel<<<wgrid, tblk, 0, s2>>>(bk_W1 + (size_t)b*HH, 8 + b);
    wprep_kernel<<<wgrid, tblk, 0, s2>>>(bk_W2 + (size_t)b*HH, 10 + b);
    cudaEventRecord(evWB[b], s2);
  }

  for (int b = 0; b < 2; b++){
    for (int li = 0; li < 2; li++){
      int i = b*2 + li;
      if (i > 0)
        lnT_kernel<<<lgrid, 256, LNT_SMEM>>>(p_x, sb_ls + i*Hdim, sb_lb + i*Hdim);
      cudaStreamWaitEvent(0, evKd[i], 0);
      conv_kernel<<<dim3(Hdim, Bsz), 256>>>(p_kd + (size_t)i*KDSZ, sD + i*Hdim);
      transpose_bwd_kernel<<<tgrid, tblk>>>();
      cudaStreamWaitEvent(0, evW[i], 0);
      hgemm_kernel<<<ggrid, 256, SMEM_GEMM>>>(p_a0, p_a1,
          p_wt0 + (size_t)i*HH, p_wt1 + (size_t)i*HH,
          sb_b1 + i*Hdim, p_z1, p_z1, p_z1, 0, nullptr, nullptr);
      const float* res = (i == 0) ? x : p_x;
      hgemm_kernel<<<ggrid, 256, SMEM_GEMM>>>(p_a0, p_a1,
          p_wt0 + (size_t)(4+i)*HH, p_wt1 + (size_t)(4+i)*HH,
          sb_b2 + i*Hdim, p_z1, res, p_x, 2, nullptr, nullptr);
    }
    ln_kernel<<<NROW/8, 256>>>(p_x, bk_ls + b*Hdim, bk_lb + b*Hdim);
    cudaStreamWaitEvent(0, evWB[b], 0);
    hgemm_kernel<<<ggrid, 256, SMEM_GEMM>>>(p_a0, p_a1,
        p_wt0 + (size_t)(8+b)*HH, p_wt1 + (size_t)(8+b)*HH,
        bk_b1 + b*Hdim, p_z1, p_z1, p_z1, 1, p_b0, p_b1);
    float* Cfinal = (b == 1) ? out : p_x;
    hgemm_kernel<<<ggrid, 256, SMEM_GEMM>>>(p_b0, p_b1,
        p_wt0 + (size_t)(10+b)*HH, p_wt1 + (size_t)(10+b)*HH,
        bk_b2 + b*Hdim, p_z1, p_x, Cfinal, 3, nullptr, nullptr);
  }
}

// round 14
// speedup vs baseline: 1.2914x; 1.0382x over previous
#include <cuda_runtime.h>
#include <cuda_bf16.h>
#include <cstdint>
#include <math.h>

#define Bsz   8
#define Lseq  2048
#define Hdim  512
#define Nst   64
#define NROW  (Bsz*Lseq)          // 16384
#define BLH   (Bsz*Lseq*Hdim)     // 8388608
#define HH    (Hdim*Hdim)
#define HN    (Hdim*Nst)
#define KDSZ  (Hdim*2049)

// ----------------- device scratch (no allocations allowed) ------------------
__device__ float  g_x [BLH];
__device__ float  g_ht[BLH];
__device__ float  g_yt[BLH];
__device__ float  g_z1[BLH];
__device__ float2 g_ar[Hdim*Lseq];
__device__ float2 g_KdL[4*KDSZ];
__device__ float2 g_twA[1024];
__device__ float2 g_twB[2048];
__device__ __nv_bfloat16 g_a0[BLH];
__device__ __nv_bfloat16 g_a1[BLH];
__device__ __nv_bfloat16 g_b0[BLH];
__device__ __nv_bfloat16 g_b1[BLH];
__device__ __nv_bfloat16 g_wt0[12*HH];
__device__ __nv_bfloat16 g_wt1[12*HH];

// ----------------- helpers --------------------------------------------------
__device__ __forceinline__ float2 cadd(float2 a, float2 b){ return make_float2(a.x+b.x, a.y+b.y); }
__device__ __forceinline__ float2 csub(float2 a, float2 b){ return make_float2(a.x-b.x, a.y-b.y); }
__device__ __forceinline__ float2 cmul(float2 a, float2 b){ return make_float2(a.x*b.x-a.y*b.y, a.x*b.y+a.y*b.x); }
__device__ __forceinline__ float frcp_fast(float x){ float y; asm("rcp.approx.f32 %0, %1;" : "=f"(y) : "f"(x)); return y; }
__device__ __forceinline__ float gelu_f(float x){
  float u = 0.7978845608028654f*(x + 0.044715f*x*x*x);
  float e = __expf(2.f*u);
  float t = 1.f - 2.f/(e + 1.f);          // tanh(u), saturates correctly
  return 0.5f*x*(1.0f + t);
}
__device__ __forceinline__ float sigm_f(float x){ return 1.0f/(1.0f + __expf(-x)); }

__device__ __forceinline__ uint32_t smem_u32(const void* p){
  uint32_t a;
  asm("{ .reg .u64 t; cvta.to.shared.u64 t, %1; cvt.u32.u64 %0, t; }" : "=r"(a) : "l"(p));
  return a;
}
__device__ __forceinline__ void cp16(uint32_t saddr, const void* g){
  asm volatile("cp.async.ca.shared.global [%0], [%1], 16;" :: "r"(saddr), "l"(g));
}
#define CP_COMMIT() asm volatile("cp.async.commit_group;" ::: "memory")

__device__ __forceinline__ void ldsm4(uint32_t* r, uint32_t addr){
  asm volatile("ldmatrix.sync.aligned.m8n8.x4.shared.b16 {%0,%1,%2,%3}, [%4];"
    : "=r"(r[0]), "=r"(r[1]), "=r"(r[2]), "=r"(r[3]) : "r"(addr));
}
__device__ __forceinline__ void mma16816(float* c, const uint32_t* a, const uint32_t* b){
  asm volatile("mma.sync.aligned.m16n8k16.row.col.f32.bf16.bf16.f32 "
    "{%0,%1,%2,%3}, {%4,%5,%6,%7}, {%8,%9}, {%0,%1,%2,%3};"
    : "+f"(c[0]), "+f"(c[1]), "+f"(c[2]), "+f"(c[3])
    : "r"(a[0]), "r"(a[1]), "r"(a[2]), "r"(a[3]), "r"(b[0]), "r"(b[1]));
}

// ----------------- twiddle init ---------------------------------------------
__global__ void init_tw_kernel(){
  int i = blockIdx.x*256 + threadIdx.x;
  if (i < 1024){
    float a = (float)(6.283185307179586/2048.0) * (float)i;
    float s, c; sincosf(a, &s, &c);
    g_twA[i] = make_float2(c, -s);
  }
  if (i < 2048){
    float a = (float)(3.141592653589793/2048.0) * (float)i;
    float s, c; sincosf(a, &s, &c);
    g_twB[i] = make_float2(c, -s);
  }
}

// ----------------- fused LN + transpose: xin (B,L,H) -> g_ht (B,H,L) --------
#define LNT_PAD  513
#define LNT_SMEM (32*LNT_PAD*4)   // 65664 bytes

__global__ __launch_bounds__(256) void lnT_kernel(const float* __restrict__ xin,
                                                  const float* __restrict__ sc,
                                                  const float* __restrict__ bi){
  extern __shared__ float tile[];      // [32][LNT_PAD]
  int b  = blockIdx.y;
  int l0 = blockIdx.x*32;
  int warp = threadIdx.x >> 5, lane = threadIdx.x & 31;
  const float4* s4 = (const float4*)sc;
  const float4* b4 = (const float4*)bi;
  #pragma unroll
  for (int r = warp; r < 32; r += 8){
    const float4* xr = (const float4*)(xin + ((size_t)b*Lseq + l0 + r)*Hdim);
    float4 v[4];
    float s = 0.f, s2 = 0.f;
    #pragma unroll
    for (int i = 0; i < 4; i++){
      float4 t = xr[lane + 32*i];
      v[i] = t;
      s  += t.x + t.y + t.z + t.w;
      s2 += t.x*t.x + t.y*t.y + t.z*t.z + t.w*t.w;
    }
    #pragma unroll
    for (int o = 16; o; o >>= 1){
      s  += __shfl_xor_sync(0xffffffffu, s,  o);
      s2 += __shfl_xor_sync(0xffffffffu, s2, o);
    }
    float mean = s*(1.f/Hdim);
    float var  = s2*(1.f/Hdim) - mean*mean;
    float inv  = rsqrtf(var + 1e-6f);
    float* trow = tile + r*LNT_PAD;
    #pragma unroll
    for (int i = 0; i < 4; i++){
      int ci = lane + 32*i;
      float4 sv = s4[ci], bv = b4[ci], t = v[i];
      trow[ci*4+0] = (t.x-mean)*inv*sv.x + bv.x;
      trow[ci*4+1] = (t.y-mean)*inv*sv.y + bv.y;
      trow[ci*4+2] = (t.z-mean)*inv*sv.z + bv.z;
      trow[ci*4+3] = (t.w-mean)*inv*sv.w + bv.w;
    }
  }
  __syncthreads();
  float* outb = g_ht + (size_t)b*Hdim*Lseq + l0 + lane;
  #pragma unroll 8
  for (int h0 = 0; h0 < Hdim; h0 += 8){
    int h = h0 + warp;
    outb[(size_t)h*Lseq] = tile[lane*LNT_PAD + h];
  }
}

// ----------------- layernorm (FFN path): xin -> bf16 splits only ------------
__global__ __launch_bounds__(256) void ln_kernel(const float* __restrict__ xin,
                                                 const float* __restrict__ sc,
                                                 const float* __restrict__ bi){
  int warp = threadIdx.x >> 5, lane = threadIdx.x & 31;
  size_t row = (size_t)blockIdx.x*8 + warp;
  const float4* xr = (const float4*)(xin + row*Hdim);
  float4 v[4];
  float s = 0.f, s2 = 0.f;
  #pragma unroll
  for (int i = 0; i < 4; i++){
    float4 t = xr[lane + 32*i];
    v[i] = t;
    s  += t.x + t.y + t.z + t.w;
    s2 += t.x*t.x + t.y*t.y + t.z*t.z + t.w*t.w;
  }
  #pragma unroll
  for (int o = 16; o; o >>= 1){
    s  += __shfl_xor_sync(0xffffffffu, s,  o);
    s2 += __shfl_xor_sync(0xffffffffu, s2, o);
  }
  float mean = s*(1.f/Hdim);
  float var  = s2*(1.f/Hdim) - mean*mean;
  float inv  = rsqrtf(var + 1e-6f);
  const float4* s4 = (const float4*)sc;
  const float4* b4 = (const float4*)bi;
  #pragma unroll
  for (int i = 0; i < 4; i++){
    int ci = lane + 32*i;
    float4 sv = s4[ci], bv = b4[ci], t = v[i], o;
    o.x = (t.x-mean)*inv*sv.x + bv.x;
    o.y = (t.y-mean)*inv*sv.y + bv.y;
    o.z = (t.z-mean)*inv*sv.z + bv.z;
    o.w = (t.w-mean)*inv*sv.w + bv.w;
    size_t gi = row*Hdim + ci*4;
    __nv_bfloat16 h0 = __float2bfloat16_rn(o.x);
    __nv_bfloat16 h1 = __float2bfloat16_rn(o.y);
    __nv_bfloat16 h2 = __float2bfloat16_rn(o.z);
    __nv_bfloat16 h3 = __float2bfloat16_rn(o.w);
    __nv_bfloat162 p0; p0.x = h0; p0.y = h1;
    __nv_bfloat162 p1; p1.x = h2; p1.y = h3;
    *(__nv_bfloat162*)(g_a0 + gi)     = p0;
    *(__nv_bfloat162*)(g_a0 + gi + 2) = p1;
    __nv_bfloat162 q0, q1;
    q0.x = __float2bfloat16_rn(o.x - __bfloat162float(h0));
    q0.y = __float2bfloat16_rn(o.y - __bfloat162float(h1));
    q1.x = __float2bfloat16_rn(o.z - __bfloat162float(h2));
    q1.y = __float2bfloat16_rn(o.w - __bfloat162float(h3));
    *(__nv_bfloat162*)(g_a1 + gi)     = q0;
    *(__nv_bfloat162*)(g_a1 + gi + 2) = q1;
  }
}

// ----------------- bwd transpose: g_yt (B,H,L) -> gelu -> bf16 splits -------
__global__ void transpose_bwd_kernel(){
  __shared__ float tile[32][33];
  int b  = blockIdx.z;
  int h0 = blockIdx.x*32;
  int l0 = blockIdx.y*32;
  int tx = threadIdx.x, ty = threadIdx.y;
  const float* in = g_yt + (size_t)b*Hdim*Lseq;
  #pragma unroll
  for (int j = 0; j < 32; j += 8)
    tile[ty+j][tx] = in[(size_t)(h0+ty+j)*Lseq + l0 + tx];
  __syncthreads();
  size_t boff = (size_t)b*Lseq*Hdim;
  #pragma unroll
  for (int j = 0; j < 32; j += 8){
    size_t idx = boff + (size_t)(l0+ty+j)*Hdim + h0 + tx;
    float g = gelu_f(tile[tx][ty+j]);
    __nv_bfloat16 hi = __float2bfloat16_rn(g);
    float r = g - __bfloat162float(hi);
    g_a0[idx] = hi;
    g_a1[idx] = __float2bfloat16_rn(r);
  }
}

// ----------------- weight transpose + split ----------------------------------
__global__ void wprep_kernel(const float* __restrict__ W, int widx){
  __shared__ float tile[32][33];
  int n0 = blockIdx.x*32, k0 = blockIdx.y*32;
  int tx = threadIdx.x, ty = threadIdx.y;
  #pragma unroll
  for (int j = 0; j < 32; j += 8)
    tile[ty+j][tx] = W[(size_t)(k0+ty+j)*Hdim + n0 + tx];
  __syncthreads();
  size_t base = (size_t)widx*HH;
  #pragma unroll
  for (int j = 0; j < 32; j += 8){
    float a = tile[tx][ty+j];
    size_t o = base + (size_t)(n0+ty+j)*Hdim + k0 + tx;
    __nv_bfloat16 hi = __float2bfloat16_rn(a);
    g_wt0[o] = hi;
    g_wt1[o] = __float2bfloat16_rn(a - __bfloat162float(hi));
  }
}

// ----------------- Cauchy kernel (prep fused in) -----------------------------
__global__ __launch_bounds__(256) void cauchy_kernel(
    const float* __restrict__ Lre, const float* __restrict__ Lim,
    const float* __restrict__ Pre, const float* __restrict__ Pim,
    const float* __restrict__ Bre, const float* __restrict__ Bim,
    const float* __restrict__ Cre, const float* __restrict__ Cim,
    const float* __restrict__ logstep){
  __shared__ float4 spk01[Nst];
  __shared__ float4 spk23[Nst];
  __shared__ float2 slam [Nst];
  __shared__ float  s2step;
  int tid = threadIdx.x;
  int h = blockIdx.y;
  int l = blockIdx.x*256 + tid;
  if (tid < Nst){
    int i = h*Nst + tid;
    float pr = Pre[i], pi = Pim[i];
    float br = Bre[i], bi = Bim[i];
    float cr = Cre[i], ci = Cim[i];
    spk01[tid] = make_float4(cr*br + ci*bi, cr*bi - ci*br,
                             cr*pr + ci*pi, cr*pi - ci*pr);
    spk23[tid] = make_float4(pr*br + pi*bi, pr*bi - pi*br,
                             pr*pr + pi*pi, 0.f);
    slam [tid] = make_float2(fminf(Lre[i], -1e-4f), Lim[i]);
  }
  if (tid == 0) s2step = 2.f*expf(-logstep[h]);
  __syncthreads();
  float t   = tanf((float)(3.141592653589793/2048.0)*(float)l);
  float gim = s2step*t;
  float k00r=0.f,k00i=0.f,k01r=0.f,k01i=0.f,k10r=0.f,k10i=0.f,k11r=0.f,k11i=0.f;
  #pragma unroll 8
  for (int n = 0; n < Nst; n++){
    float2 lam = slam[n];
    float dre = -lam.x;
    float dim = gim - lam.y;
    float inv = frcp_fast(dre*dre + dim*dim);
    float ir  =  dre*inv;
    float ii  = -dim*inv;
    float4 w01 = spk01[n];
    float4 w23 = spk23[n];
    k00r += w01.x*ir - w01.y*ii;  k00i += w01.x*ii + w01.y*ir;
    k01r += w01.z*ir - w01.w*ii;  k01i += w01.z*ii + w01.w*ir;
    k10r += w23.x*ir - w23.y*ii;  k10i += w23.x*ii + w23.y*ir;
    k11r += w23.z*ir;             k11i += w23.z*ii;
  }
  float denr = 1.f + k11r, deni = k11i;
  float dinv = frcp_fast(denr*denr + deni*deni);
  float qr = denr*dinv, qi = -deni*dinv;
  float mr = k01r*k10r - k01i*k10i;
  float mi = k01r*k10i + k01i*k10r;
  float cr = mr*qr - mi*qi, ci2 = mr*qi + mi*qr;
  float ar = k00r - cr, ai = k00i - ci2;
  g_ar[(size_t)h*Lseq + l] = make_float2(ar - t*ai, ai + t*ar);
}

// ----------------- shared-mem radix-8 Stockham FFT(2048) ---------------------
// 3 radix-8 stages (s=1,8,64) + 1 twiddle-free radix-4 (s=512).
// Generic Stockham DIF stage: B_q = sum_p a_p w_r^{pq};
// dst[idx+(r-1)*sp+q*s] = B_q * W^{q*sp}  (same form as the validated radix-4).
template<bool INV>
__device__ __forceinline__ float2* fft2048_r8(float2* buf0, float2* buf1,
                                              const float2* stw, int tid){
  const float C2 = 0.7071067811865476f;
  float2* src = buf0; float2* dst = buf1;
  #pragma unroll
  for (int st = 0; st < 3; st++){
    int s = 1 << (3*st);            // 1, 8, 64
    __syncthreads();
    int idx = tid;                  // 0..255, one radix-8 butterfly each
    int sp  = idx & ~(s-1);
    float2 a0 = src[idx       ];
    float2 a1 = src[idx +  256];
    float2 a2 = src[idx +  512];
    float2 a3 = src[idx +  768];
    float2 a4 = src[idx + 1024];
    float2 a5 = src[idx + 1280];
    float2 a6 = src[idx + 1536];
    float2 a7 = src[idx + 1792];
    // even radix-4 on (a0,a2,a4,a6), odd radix-4 on (a1,a3,a5,a7)
    float2 t0 = cadd(a0,a4), t1 = csub(a0,a4);
    float2 t2 = cadd(a2,a6), t3 = csub(a2,a6);
    float2 e0 = cadd(t0,t2), e2 = csub(t0,t2);
    float2 u0 = cadd(a1,a5), u1 = csub(a1,a5);
    float2 u2 = cadd(a3,a7), u3 = csub(a3,a7);
    float2 o0 = cadd(u0,u2), o2 = csub(u0,u2);
    float2 e1, e3, o1, o3, m1, m2, m3;
    if (!INV){
      e1 = make_float2(t1.x + t3.y, t1.y - t3.x);
      e3 = make_float2(t1.x - t3.y, t1.y + t3.x);
      o1 = make_float2(u1.x + u3.y, u1.y - u3.x);
      o3 = make_float2(u1.x - u3.y, u1.y + u3.x);
      m1 = make_float2(C2*(o1.x + o1.y), C2*(o1.y - o1.x));    // * (C,-C)
      m2 = make_float2(o2.y, -o2.x);                           // * (-i)
      m3 = make_float2(C2*(o3.y - o3.x), -C2*(o3.x + o3.y));   // * (-C,-C)
    } else {
      e1 = make_float2(t1.x - t3.y, t1.y + t3.x);
      e3 = make_float2(t1.x + t3.y, t1.y - t3.x);
      o1 = make_float2(u1.x - u3.y, u1.y + u3.x);
      o3 = make_float2(u1.x + u3.y, u1.y - u3.x);
      m1 = make_float2(C2*(o1.x - o1.y), C2*(o1.x + o1.y));    // * (C,C)
      m2 = make_float2(-o2.y, o2.x);                           // * (+i)
      m3 = make_float2(-C2*(o3.x + o3.y), C2*(o3.x - o3.y));   // * (-C,C)
    }
    float2 B0 = cadd(e0,o0), B4 = csub(e0,o0);
    float2 B1 = cadd(e1,m1), B5 = csub(e1,m1);
    float2 B2 = cadd(e2,m2), B6 = csub(e2,m2);
    float2 B3 = cadd(e3,m3), B7 = csub(e3,m3);
    float2 w1 = stw[sp], w2 = stw[2*sp], w4 = stw[4*sp];
    if (INV){ w1.y = -w1.y; w2.y = -w2.y; w4.y = -w4.y; }
    float2 w3 = cmul(w1,w2);
    float2 w5 = cmul(w1,w4);
    float2 w6 = cmul(w2,w4);
    float2 w7 = cmul(w3,w4);
    int j = idx + 7*sp;
    dst[j      ] = B0;
    dst[j +   s] = cmul(B1,w1);
    dst[j + 2*s] = cmul(B2,w2);
    dst[j + 3*s] = cmul(B3,w3);
    dst[j + 4*s] = cmul(B4,w4);
    dst[j + 5*s] = cmul(B5,w5);
    dst[j + 6*s] = cmul(B6,w6);
    dst[j + 7*s] = cmul(B7,w7);
    float2* tp = src; src = dst; dst = tp;
  }
  // final radix-4, s=512: sp = idx&~511 = 0 -> twiddle-free
  __syncthreads();
  #pragma unroll
  for (int i = 0; i < 2; i++){
    int idx = tid + 256*i;          // 0..511
    float2 a0 = src[idx];
    float2 a1 = src[idx + 512];
    float2 a2 = src[idx + 1024];
    float2 a3 = src[idx + 1536];
    float2 t0 = cadd(a0,a2), t1 = csub(a0,a2);
    float2 t2 = cadd(a1,a3), t3 = csub(a1,a3);
    float2 b0 = cadd(t0,t2), b2 = csub(t0,t2);
    float2 b1, b3;
    if (!INV){
      b1 = make_float2(t1.x + t3.y, t1.y - t3.x);
      b3 = make_float2(t1.x - t3.y, t1.y + t3.x);
    } else {
      b1 = make_float2(t1.x - t3.y, t1.y + t3.x);
      b3 = make_float2(t1.x + t3.y, t1.y - t3.x);
    }
    dst[idx       ] = b0;
    dst[idx +  512] = b1;
    dst[idx + 1024] = b2;
    dst[idx + 1536] = b3;
  }
  float2* tp = src; src = dst; dst = tp;
  __syncthreads();
  return src;
}

// ----------------- Kd kernel ------------------------------------------------
__global__ __launch_bounds__(256) void kd_kernel(float2* __restrict__ Kd){
  __shared__ float2 sA[2048];
  __shared__ float2 sB[2048];
  __shared__ float2 stw[1024];
  int tid = threadIdx.x;
  int h = blockIdx.x;
  for (int i = tid; i < 1024; i += 256) stw[i] = g_twA[i];
  const float2* ar = g_ar + (size_t)h*Lseq;
  #pragma unroll
  for (int i = 0; i < 8; i++){ int k = tid + 256*i; sA[k] = ar[k]; }
  float2* K = fft2048_r8<true>(sA, sB, stw, tid);
  float2* Ob = (K == sA) ? sB : sA;
  const float sc = 1.f/2048.f;
  #pragma unroll
  for (int i = 0; i < 8; i++){
    int n = tid + 256*i;
    float2 v = make_float2(0.f, 0.f);
    if (n < 1024) v = make_float2(K[2*n].x*sc, K[2*n+1].x*sc);
    Ob[n] = v;
  }
  float2* Zp = fft2048_r8<false>(Ob, K, stw, tid);
  float2* outKd = Kd + (size_t)h*2049;
  #pragma unroll
  for (int i = 0; i < 8; i++){
    int k  = tid + 256*i;
    int kc = (2048 - k) & 2047;
    float2 zk = Zp[k], zc = Zp[kc];
    float2 E  = make_float2(0.5f*(zk.x+zc.x),  0.5f*(zk.y-zc.y));
    float2 Od = make_float2(0.5f*(zk.y+zc.y), -0.5f*(zk.x-zc.x));
    outKd[k] = cadd(E, cmul(g_twB[k], Od));
  }
  if (tid == 0){
    float2 z0 = Zp[0];
    outKd[2048] = make_float2(z0.x - z0.y, 0.f);
  }
}

// ----------------- conv kernel (D feed-through fused) ------------------------
__global__ __launch_bounds__(256) void conv_kernel(const float2* __restrict__ Kdbase,
                                                   const float* __restrict__ Dp){
  __shared__ float2 sA[2048];
  __shared__ float2 sB[2048];
  __shared__ float2 stw[1024];
  __shared__ float2 sY2048;
  int tid = threadIdx.x;
  int h = blockIdx.x;
  int b = blockIdx.y;
  const float* u = g_ht + ((size_t)b*Hdim + h)*Lseq;
  for (int i = tid; i < 1024; i += 256) stw[i] = g_twA[i];
  float ur[8];
  #pragma unroll
  for (int i = 0; i < 4; i++){
    int n = tid + 256*i;
    float u0 = u[2*n], u1 = u[2*n+1];
    ur[2*i] = u0; ur[2*i+1] = u1;
    sA[n]        = make_float2(u0, u1);
    sA[n + 1024] = make_float2(0.f, 0.f);
  }
  float2* Z = fft2048_r8<false>(sA, sB, stw, tid);
  float2* O = (Z == sA) ? sB : sA;
  const float2* kd = Kdbase + (size_t)h*2049;
  #pragma unroll
  for (int i = 0; i < 8; i++){
    int k  = tid + 256*i;
    int kc = (2048 - k) & 2047;
    float2 zk = Z[k], zc = Z[kc];
    float2 E  = make_float2(0.5f*(zk.x+zc.x),  0.5f*(zk.y-zc.y));
    float2 Od = make_float2(0.5f*(zk.y+zc.y), -0.5f*(zk.x-zc.x));
    float2 U  = cadd(E, cmul(g_twB[k], Od));
    O[k] = cmul(U, kd[k]);
  }
  if (tid == 0){
    float2 z0 = Z[0];
    float U2048 = z0.x - z0.y;
    float2 kv = kd[2048];
    sY2048 = make_float2(U2048*kv.x, U2048*kv.y);
  }
  __syncthreads();
  #pragma unroll
  for (int i = 0; i < 8; i++){
    int k = tid + 256*i;
    float2 Yk = O[k];
    float2 Yc = (k == 0) ? sY2048 : O[2048 - k];
    float2 Ey = make_float2(0.5f*(Yk.x+Yc.x), 0.5f*(Yk.y-Yc.y));
    float2 Dm = make_float2(0.5f*(Yk.x-Yc.x), 0.5f*(Yk.y+Yc.y));
    float2 tb = g_twB[k];
    float2 Oy = cmul(Dm, make_float2(tb.x, -tb.y));
    Z[k] = make_float2(Ey.x - Oy.y, Ey.y + Oy.x);
  }
  float2* w = fft2048_r8<true>(Z, O, stw, tid);
  float* out = g_yt + ((size_t)b*Hdim + h)*Lseq;
  const float sc = 1.f/2048.f;
  float Dh = Dp[h];
  #pragma unroll
  for (int i = 0; i < 4; i++){
    int n = tid + 256*i;
    float2 v = w[n];
    out[2*n]   = v.x*sc + Dh*ur[2*i];
    out[2*n+1] = v.y*sc + Dh*ur[2*i+1];
  }
}

// ----------------- HMMA GEMM: 128x128 tile, bf16x3 (R8-proven config) --------
#define TROW    80
#define TBYTES  (128*TROW)
#define STAGEB  (4*TBYTES)
#define SMEM_GEMM (2*STAGEB)            // 81920

__global__ __launch_bounds__(256) void hgemm_kernel(
    const __nv_bfloat16* __restrict__ A0g, const __nv_bfloat16* __restrict__ A1g,
    const __nv_bfloat16* __restrict__ B0g, const __nv_bfloat16* __restrict__ B1g,
    const float* __restrict__ bias, const float* __restrict__ aux,
    const float* __restrict__ resid,
    float* __restrict__ C, int mode,
    __nv_bfloat16* __restrict__ S0, __nv_bfloat16* __restrict__ S1)
{
  extern __shared__ char smem[];
  uint32_t sb = smem_u32(smem);
  int tid = threadIdx.x, wid = tid >> 5, lid = tid & 31;
  int bn = blockIdx.x*128, bm = blockIdx.y*128;
  int mw = wid & 3, nw = wid >> 2;

  int lrow = tid >> 1;
  int lc0  = tid & 1;

  int arow = lid & 15;
  int aoff = (lid >> 4) * 16;
  int brow = ((lid >> 4) << 3) + (lid & 7);
  int boff = ((lid >> 3) & 1) * 16;

  float acc[2][8][4];
  #pragma unroll
  for (int i = 0; i < 2; i++)
    #pragma unroll
    for (int j = 0; j < 8; j++)
      #pragma unroll
      for (int q = 0; q < 4; q++) acc[i][j][q] = 0.f;

  #pragma unroll
  for (int j = 0; j < 2; j++){
    int c = lc0 + 2*j;
    uint32_t so = (uint32_t)lrow*TROW + (uint32_t)c*16;
    size_t ga = (size_t)(bm + lrow)*Hdim + c*8;
    size_t gb = (size_t)(bn + lrow)*Hdim + c*8;
    cp16(sb + so,             A0g + ga);
    cp16(sb + TBYTES   + so,  A1g + ga);
    cp16(sb + 2*TBYTES + so,  B0g + gb);
    cp16(sb + 3*TBYTES + so,  B1g + gb);
  }
  CP_COMMIT();

  for (int ch = 0; ch < 16; ch++){
    int st = ch & 1;
    if (ch < 15){
      uint32_t sbase = sb + (st^1)*STAGEB;
      int k0 = (ch+1)*32;
      #pragma unroll
      for (int j = 0; j < 2; j++){
        int c = lc0 + 2*j;
        uint32_t so = (uint32_t)lrow*TROW + (uint32_t)c*16;
        size_t ga = (size_t)(bm + lrow)*Hdim + k0 + c*8;
        size_t gb = (size_t)(bn + lrow)*Hdim + k0 + c*8;
        cp16(sbase + so,             A0g + ga);
        cp16(sbase + TBYTES   + so,  A1g + ga);
        cp16(sbase + 2*TBYTES + so,  B0g + gb);
        cp16(sbase + 3*TBYTES + so,  B1g + gb);
      }
      CP_COMMIT();
      asm volatile("cp.async.wait_group 1;" ::: "memory");
    } else {
      asm volatile("cp.async.wait_group 0;" ::: "memory");
    }
    __syncthreads();

    uint32_t sA0 = sb + st*STAGEB;
    uint32_t sA1 = sA0 + TBYTES;
    uint32_t sB0 = sA0 + 2*TBYTES;
    uint32_t sB1 = sA0 + 3*TBYTES;
    #pragma unroll
    for (int ks = 0; ks < 2; ks++){
      int kb = ks*32;
      uint32_t a0f[2][4], a1f[2][4], b0f[4][4], b1f[4][4];
      #pragma unroll
      for (int mi = 0; mi < 2; mi++){
        uint32_t ro = (uint32_t)(mw*32 + mi*16 + arow)*TROW + kb + aoff;
        ldsm4(a0f[mi], sA0 + ro);
        ldsm4(a1f[mi], sA1 + ro);
      }
      #pragma unroll
      for (int nj = 0; nj < 4; nj++){
        uint32_t ro = (uint32_t)(nw*64 + nj*16 + brow)*TROW + kb + boff;
        ldsm4(b0f[nj], sB0 + ro);
        ldsm4(b1f[nj], sB1 + ro);
      }
      #pragma unroll
      for (int mi = 0; mi < 2; mi++){
        #pragma unroll
        for (int nt = 0; nt < 8; nt++){
          int nj = nt >> 1, sub = (nt & 1)*2;
          mma16816(acc[mi][nt], a0f[mi], &b0f[nj][sub]);
          mma16816(acc[mi][nt], a1f[mi], &b0f[nj][sub]);
          mma16816(acc[mi][nt], a0f[mi], &b1f[nj][sub]);
        }
      }
    }
    __syncthreads();
  }

  // epilogue
  int qr = lid >> 2, qc = (lid & 3)*2;
  #pragma unroll
  for (int mi = 0; mi < 2; mi++){
    #pragma unroll
    for (int hf = 0; hf < 2; hf++){
      int row = bm + mw*32 + mi*16 + hf*8 + qr;
      float* crow = C + (size_t)row*Hdim;
      const float* xrow = aux + (size_t)row*Hdim;
      const float* rrow = resid + (size_t)row*Hdim;
      #pragma unroll
      for (int nt = 0; nt < 8; nt++){
        int col = bn + nw*64 + nt*8 + qc;
        float2 bv = *(const float2*)(bias + col);
        float v0 = acc[mi][nt][hf*2+0] + bv.x;
        float v1 = acc[mi][nt][hf*2+1] + bv.y;
        float2 o;
        if (mode == 0){
          o = make_float2(v0, v1);
        } else if (mode == 1){
          o = make_float2(gelu_f(v0), gelu_f(v1));
        } else if (mode == 2){
          float2 rv = *(const float2*)(rrow + col);
          float2 av = *(const float2*)(xrow + col);
          o.x = rv.x + av.x*sigm_f(v0);
          o.y = rv.y + av.y*sigm_f(v1);
        } else {
          float2 rv = *(const float2*)(rrow + col);
          o = make_float2(rv.x + v0, rv.y + v1);
        }
        *(float2*)(crow + col) = o;
        if (S0){
          size_t gi = (size_t)row*Hdim + col;
          __nv_bfloat16 h0 = __float2bfloat16_rn(o.x);
          __nv_bfloat16 h1 = __float2bfloat16_rn(o.y);
          __nv_bfloat162 p; p.x = h0; p.y = h1;
          *(__nv_bfloat162*)(S0 + gi) = p;
          __nv_bfloat162 q;
          q.x = __float2bfloat16_rn(o.x - __bfloat162float(h0));
          q.y = __float2bfloat16_rn(o.y - __bfloat162float(h1));
          *(__nv_bfloat162*)(S1 + gi) = q;
        }
      }
    }
  }
}

// ----------------- host driver ----------------------------------------------
extern "C" void kernel_launch(void* const* d_in, const int* in_sizes, int n_in,
                              void* d_out, int out_size){
  (void)in_sizes; (void)n_in; (void)out_size;
  const float* x     = (const float*)d_in[0];
  const float* sLre  = (const float*)d_in[1];
  const float* sLim  = (const float*)d_in[2];
  const float* sPre  = (const float*)d_in[3];
  const float* sPim  = (const float*)d_in[4];
  const float* sBre  = (const float*)d_in[5];
  const float* sBim  = (const float*)d_in[6];
  const float* sCre  = (const float*)d_in[7];
  const float* sCim  = (const float*)d_in[8];
  const float* sD    = (const float*)d_in[9];
  const float* sLog  = (const float*)d_in[10];
  const float* sb_ls = (const float*)d_in[11];
  const float* sb_lb = (const float*)d_in[12];
  const float* sb_W1 = (const float*)d_in[13];
  const float* sb_b1 = (const float*)d_in[14];
  const float* sb_W2 = (const float*)d_in[15];
  const float* sb_b2 = (const float*)d_in[16];
  const float* bk_ls = (const float*)d_in[17];
  const float* bk_lb = (const float*)d_in[18];
  const float* bk_W1 = (const float*)d_in[19];
  const float* bk_b1 = (const float*)d_in[20];
  const float* bk_W2 = (const float*)d_in[21];
  const float* bk_b2 = (const float*)d_in[22];
  float* out = (float*)d_out;

  float *p_x, *p_z1;
  float2* p_kd;
  __nv_bfloat16 *p_a0, *p_a1, *p_b0, *p_b1, *p_wt0, *p_wt1;
  cudaGetSymbolAddress((void**)&p_x,   g_x);
  cudaGetSymbolAddress((void**)&p_z1,  g_z1);
  cudaGetSymbolAddress((void**)&p_kd,  g_KdL);
  cudaGetSymbolAddress((void**)&p_a0,  g_a0);
  cudaGetSymbolAddress((void**)&p_a1,  g_a1);
  cudaGetSymbolAddress((void**)&p_b0,  g_b0);
  cudaGetSymbolAddress((void**)&p_b1,  g_b1);
  cudaGetSymbolAddress((void**)&p_wt0, g_wt0);
  cudaGetSymbolAddress((void**)&p_wt1, g_wt1);

  cudaFuncSetAttribute(hgemm_kernel, cudaFuncAttributeMaxDynamicSharedMemorySize, SMEM_GEMM);
  cudaFuncSetAttribute(lnT_kernel,   cudaFuncAttributeMaxDynamicSharedMemorySize, LNT_SMEM);

  cudaStream_t s2;
  cudaStreamCreateWithFlags(&s2, cudaStreamNonBlocking);
  cudaEvent_t evStart, evKd[4], evW[4], evWB[2];
  cudaEventCreateWithFlags(&evStart, cudaEventDisableTiming);
  for (int i = 0; i < 4; i++){
    cudaEventCreateWithFlags(&evKd[i], cudaEventDisableTiming);
    cudaEventCreateWithFlags(&evW[i],  cudaEventDisableTiming);
  }
  for (int b = 0; b < 2; b++) cudaEventCreateWithFlags(&evWB[b], cudaEventDisableTiming);

  dim3 wgrid(16, 16);
  dim3 tblk(32, 8);
  dim3 tgrid(Hdim/32, Lseq/32, Bsz);
  dim3 lgrid(Lseq/32, Bsz);
  dim3 ggrid(Hdim/128, NROW/128);

  init_tw_kernel<<<8, 256>>>();
  cudaEventRecord(evStart, 0);
  cudaStreamWaitEvent(s2, evStart, 0);

  cauchy_kernel<<<dim3(Lseq/256, Hdim), 256, 0, s2>>>(
      sLre, sLim, sPre, sPim, sBre, sBim, sCre, sCim, sLog);
  lnT_kernel<<<lgrid, 256, LNT_SMEM>>>(x, sb_ls, sb_lb);
  kd_kernel<<<Hdim, 256, 0, s2>>>(p_kd);
  cudaEventRecord(evKd[0], s2);
  wprep_kernel<<<wgrid, tblk, 0, s2>>>(sb_W1, 0);
  wprep_kernel<<<wgrid, tblk, 0, s2>>>(sb_W2, 4);
  cudaEventRecord(evW[0], s2);
  for (int i = 1; i < 4; i++){
    cauchy_kernel<<<dim3(Lseq/256, Hdim), 256, 0, s2>>>(
        sLre + i*HN, sLim + i*HN, sPre + i*HN, sPim + i*HN,
        sBre + i*HN, sBim + i*HN, sCre + i*HN, sCim + i*HN, sLog + i*Hdim);
    kd_kernel<<<Hdim, 256, 0, s2>>>(p_kd + (size_t)i*KDSZ);
    cudaEventRecord(evKd[i], s2);
    wprep_kernel<<<wgrid, tblk, 0, s2>>>(sb_W1 + (size_t)i*HH, i);
    wprep_kernel<<<wgrid, tblk, 0, s2>>>(sb_W2 + (size_t)i*HH, 4 + i);
    cudaEventRecord(evW[i], s2);
  }
  for (int b = 0; b < 2; b++){
    wprep_kernel<<<wgrid, tblk, 0, s2>>>(bk_W1 + (size_t)b*HH, 8 + b);
    wprep_kernel<<<wgrid, tblk, 0, s2>>>(bk_W2 + (size_t)b*HH, 10 + b);
    cudaEventRecord(evWB[b], s2);
  }

  for (int b = 0; b < 2; b++){
    for (int li = 0; li < 2; li++){
      int i = b*2 + li;
      if (i > 0)
        lnT_kernel<<<lgrid, 256, LNT_SMEM>>>(p_x, sb_ls + i*Hdim, sb_lb + i*Hdim);
      cudaStreamWaitEvent(0, evKd[i], 0);
      conv_kernel<<<dim3(Hdim, Bsz), 256>>>(p_kd + (size_t)i*KDSZ, sD + i*Hdim);
      transpose_bwd_kernel<<<tgrid, tblk>>>();
      cudaStreamWaitEvent(0, evW[i], 0);
      hgemm_kernel<<<ggrid, 256, SMEM_GEMM>>>(p_a0, p_a1,
          p_wt0 + (size_t)i*HH, p_wt1 + (size_t)i*HH,
          sb_b1 + i*Hdim, p_z1, p_z1, p_z1, 0, nullptr, nullptr);
      const float* res = (i == 0) ? x : p_x;
      hgemm_kernel<<<ggrid, 256, SMEM_GEMM>>>(p_a0, p_a1,
          p_wt0 + (size_t)(4+i)*HH, p_wt1 + (size_t)(4+i)*HH,
          sb_b2 + i*Hdim, p_z1, res, p_x, 2, nullptr, nullptr);
    }
    ln_kernel<<<NROW/8, 256>>>(p_x, bk_ls + b*Hdim, bk_lb + b*Hdim);
    cudaStreamWaitEvent(0, evWB[b], 0);
    hgemm_kernel<<<ggrid, 256, SMEM_GEMM>>>(p_a0, p_a1,
        p_wt0 + (size_t)(8+b)*HH, p_wt1 + (size_t)(8+b)*HH,
        bk_b1 + b*Hdim, p_z1, p_z1, p_z1, 1, p_b0, p_b1);
    float* Cfinal = (b == 1) ? out : p_x;
    hgemm_kernel<<<ggrid, 256, SMEM_GEMM>>>(p_b0, p_b1,
        p_wt0 + (size_t)(10+b)*HH, p_wt1 + (size_t)(10+b)*HH,
        bk_b2 + b*Hdim, p_z1, p_x, Cfinal, 3, nullptr, nullptr);
  }
}

// round 15
// speedup vs baseline: 1.3113x; 1.0154x over previous
#include <cuda_runtime.h>
#include <cuda_bf16.h>
#include <cstdint>
#include <math.h>

#define Bsz   8
#define Lseq  2048
#define Hdim  512
#define Nst   64
#define NROW  (Bsz*Lseq)          // 16384
#define BLH   (Bsz*Lseq*Hdim)     // 8388608
#define HH    (Hdim*Hdim)
#define HN    (Hdim*Nst)
#define KDSZ  (Hdim*2049)

// ----------------- device scratch (no allocations allowed) ------------------
__device__ float  g_x [BLH];
__device__ float  g_ht[BLH];
__device__ float  g_yt[BLH];
__device__ float  g_z1[BLH];
__device__ float2 g_ar[Hdim*Lseq];
__device__ float2 g_KdL[4*KDSZ];
__device__ float2 g_twA[1024];
__device__ float2 g_twB[2048];
__device__ __nv_bfloat16 g_a0[BLH];
__device__ __nv_bfloat16 g_a1[BLH];
__device__ __nv_bfloat16 g_b0[BLH];
__device__ __nv_bfloat16 g_b1[BLH];
__device__ __nv_bfloat16 g_wt0[12*HH];
__device__ __nv_bfloat16 g_wt1[12*HH];

// ----------------- helpers --------------------------------------------------
__device__ __forceinline__ float2 cadd(float2 a, float2 b){ return make_float2(a.x+b.x, a.y+b.y); }
__device__ __forceinline__ float2 csub(float2 a, float2 b){ return make_float2(a.x-b.x, a.y-b.y); }
__device__ __forceinline__ float2 cmul(float2 a, float2 b){ return make_float2(a.x*b.x-a.y*b.y, a.x*b.y+a.y*b.x); }
__device__ __forceinline__ float frcp_fast(float x){ float y; asm("rcp.approx.f32 %0, %1;" : "=f"(y) : "f"(x)); return y; }
__device__ __forceinline__ float gelu_f(float x){
  float u = 0.7978845608028654f*(x + 0.044715f*x*x*x);
  float e = __expf(2.f*u);
  float t = 1.f - 2.f/(e + 1.f);          // tanh(u), saturates correctly
  return 0.5f*x*(1.0f + t);
}
__device__ __forceinline__ float sigm_f(float x){ return 1.0f/(1.0f + __expf(-x)); }

__device__ __forceinline__ uint32_t smem_u32(const void* p){
  uint32_t a;
  asm("{ .reg .u64 t; cvta.to.shared.u64 t, %1; cvt.u32.u64 %0, t; }" : "=r"(a) : "l"(p));
  return a;
}
__device__ __forceinline__ void cp16(uint32_t saddr, const void* g){
  asm volatile("cp.async.ca.shared.global [%0], [%1], 16;" :: "r"(saddr), "l"(g));
}
#define CP_COMMIT() asm volatile("cp.async.commit_group;" ::: "memory")

__device__ __forceinline__ void ldsm4(uint32_t* r, uint32_t addr){
  asm volatile("ldmatrix.sync.aligned.m8n8.x4.shared.b16 {%0,%1,%2,%3}, [%4];"
    : "=r"(r[0]), "=r"(r[1]), "=r"(r[2]), "=r"(r[3]) : "r"(addr));
}
__device__ __forceinline__ void mma16816(float* c, const uint32_t* a, const uint32_t* b){
  asm volatile("mma.sync.aligned.m16n8k16.row.col.f32.bf16.bf16.f32 "
    "{%0,%1,%2,%3}, {%4,%5,%6,%7}, {%8,%9}, {%0,%1,%2,%3};"
    : "+f"(c[0]), "+f"(c[1]), "+f"(c[2]), "+f"(c[3])
    : "r"(a[0]), "r"(a[1]), "r"(a[2]), "r"(a[3]), "r"(b[0]), "r"(b[1]));
}

// ----------------- twiddle init ---------------------------------------------
__global__ void init_tw_kernel(){
  int i = blockIdx.x*256 + threadIdx.x;
  if (i < 1024){
    float a = (float)(6.283185307179586/2048.0) * (float)i;
    float s, c; sincosf(a, &s, &c);
    g_twA[i] = make_float2(c, -s);
  }
  if (i < 2048){
    float a = (float)(3.141592653589793/2048.0) * (float)i;
    float s, c; sincosf(a, &s, &c);
    g_twB[i] = make_float2(c, -s);
  }
}

// ----------------- fused LN + transpose: xin (B,L,H) -> g_ht (B,H,L) --------
#define LNT_PAD  513
#define LNT_SMEM (32*LNT_PAD*4)   // 65664 bytes

__global__ __launch_bounds__(256) void lnT_kernel(const float* __restrict__ xin,
                                                  const float* __restrict__ sc,
                                                  const float* __restrict__ bi){
  extern __shared__ float tile[];      // [32][LNT_PAD]
  int b  = blockIdx.y;
  int l0 = blockIdx.x*32;
  int warp = threadIdx.x >> 5, lane = threadIdx.x & 31;
  const float4* s4 = (const float4*)sc;
  const float4* b4 = (const float4*)bi;
  #pragma unroll
  for (int r = warp; r < 32; r += 8){
    const float4* xr = (const float4*)(xin + ((size_t)b*Lseq + l0 + r)*Hdim);
    float4 v[4];
    float s = 0.f, s2 = 0.f;
    #pragma unroll
    for (int i = 0; i < 4; i++){
      float4 t = xr[lane + 32*i];
      v[i] = t;
      s  += t.x + t.y + t.z + t.w;
      s2 += t.x*t.x + t.y*t.y + t.z*t.z + t.w*t.w;
    }
    #pragma unroll
    for (int o = 16; o; o >>= 1){
      s  += __shfl_xor_sync(0xffffffffu, s,  o);
      s2 += __shfl_xor_sync(0xffffffffu, s2, o);
    }
    float mean = s*(1.f/Hdim);
    float var  = s2*(1.f/Hdim) - mean*mean;
    float inv  = rsqrtf(var + 1e-6f);
    float* trow = tile + r*LNT_PAD;
    #pragma unroll
    for (int i = 0; i < 4; i++){
      int ci = lane + 32*i;
      float4 sv = s4[ci], bv = b4[ci], t = v[i];
      trow[ci*4+0] = (t.x-mean)*inv*sv.x + bv.x;
      trow[ci*4+1] = (t.y-mean)*inv*sv.y + bv.y;
      trow[ci*4+2] = (t.z-mean)*inv*sv.z + bv.z;
      trow[ci*4+3] = (t.w-mean)*inv*sv.w + bv.w;
    }
  }
  __syncthreads();
  float* outb = g_ht + (size_t)b*Hdim*Lseq + l0 + lane;
  #pragma unroll 8
  for (int h0 = 0; h0 < Hdim; h0 += 8){
    int h = h0 + warp;
    outb[(size_t)h*Lseq] = tile[lane*LNT_PAD + h];
  }
}

// ----------------- layernorm (FFN path): xin -> bf16 splits only ------------
__global__ __launch_bounds__(256) void ln_kernel(const float* __restrict__ xin,
                                                 const float* __restrict__ sc,
                                                 const float* __restrict__ bi){
  int warp = threadIdx.x >> 5, lane = threadIdx.x & 31;
  size_t row = (size_t)blockIdx.x*8 + warp;
  const float4* xr = (const float4*)(xin + row*Hdim);
  float4 v[4];
  float s = 0.f, s2 = 0.f;
  #pragma unroll
  for (int i = 0; i < 4; i++){
    float4 t = xr[lane + 32*i];
    v[i] = t;
    s  += t.x + t.y + t.z + t.w;
    s2 += t.x*t.x + t.y*t.y + t.z*t.z + t.w*t.w;
  }
  #pragma unroll
  for (int o = 16; o; o >>= 1){
    s  += __shfl_xor_sync(0xffffffffu, s,  o);
    s2 += __shfl_xor_sync(0xffffffffu, s2, o);
  }
  float mean = s*(1.f/Hdim);
  float var  = s2*(1.f/Hdim) - mean*mean;
  float inv  = rsqrtf(var + 1e-6f);
  const float4* s4 = (const float4*)sc;
  const float4* b4 = (const float4*)bi;
  #pragma unroll
  for (int i = 0; i < 4; i++){
    int ci = lane + 32*i;
    float4 sv = s4[ci], bv = b4[ci], t = v[i], o;
    o.x = (t.x-mean)*inv*sv.x + bv.x;
    o.y = (t.y-mean)*inv*sv.y + bv.y;
    o.z = (t.z-mean)*inv*sv.z + bv.z;
    o.w = (t.w-mean)*inv*sv.w + bv.w;
    size_t gi = row*Hdim + ci*4;
    __nv_bfloat16 h0 = __float2bfloat16_rn(o.x);
    __nv_bfloat16 h1 = __float2bfloat16_rn(o.y);
    __nv_bfloat16 h2 = __float2bfloat16_rn(o.z);
    __nv_bfloat16 h3 = __float2bfloat16_rn(o.w);
    __nv_bfloat162 p0; p0.x = h0; p0.y = h1;
    __nv_bfloat162 p1; p1.x = h2; p1.y = h3;
    *(__nv_bfloat162*)(g_a0 + gi)     = p0;
    *(__nv_bfloat162*)(g_a0 + gi + 2) = p1;
    __nv_bfloat162 q0, q1;
    q0.x = __float2bfloat16_rn(o.x - __bfloat162float(h0));
    q0.y = __float2bfloat16_rn(o.y - __bfloat162float(h1));
    q1.x = __float2bfloat16_rn(o.z - __bfloat162float(h2));
    q1.y = __float2bfloat16_rn(o.w - __bfloat162float(h3));
    *(__nv_bfloat162*)(g_a1 + gi)     = q0;
    *(__nv_bfloat162*)(g_a1 + gi + 2) = q1;
  }
}

// ----------------- bwd transpose: g_yt (B,H,L) -> gelu -> bf16 splits -------
__global__ void transpose_bwd_kernel(){
  __shared__ float tile[32][33];
  int b  = blockIdx.z;
  int h0 = blockIdx.x*32;
  int l0 = blockIdx.y*32;
  int tx = threadIdx.x, ty = threadIdx.y;
  const float* in = g_yt + (size_t)b*Hdim*Lseq;
  #pragma unroll
  for (int j = 0; j < 32; j += 8)
    tile[ty+j][tx] = in[(size_t)(h0+ty+j)*Lseq + l0 + tx];
  __syncthreads();
  size_t boff = (size_t)b*Lseq*Hdim;
  #pragma unroll
  for (int j = 0; j < 32; j += 8){
    size_t idx = boff + (size_t)(l0+ty+j)*Hdim + h0 + tx;
    float g = gelu_f(tile[tx][ty+j]);
    __nv_bfloat16 hi = __float2bfloat16_rn(g);
    float r = g - __bfloat162float(hi);
    g_a0[idx] = hi;
    g_a1[idx] = __float2bfloat16_rn(r);
  }
}

// ----------------- weight transpose + split ----------------------------------
__global__ void wprep_kernel(const float* __restrict__ W, int widx){
  __shared__ float tile[32][33];
  int n0 = blockIdx.x*32, k0 = blockIdx.y*32;
  int tx = threadIdx.x, ty = threadIdx.y;
  #pragma unroll
  for (int j = 0; j < 32; j += 8)
    tile[ty+j][tx] = W[(size_t)(k0+ty+j)*Hdim + n0 + tx];
  __syncthreads();
  size_t base = (size_t)widx*HH;
  #pragma unroll
  for (int j = 0; j < 32; j += 8){
    float a = tile[tx][ty+j];
    size_t o = base + (size_t)(n0+ty+j)*Hdim + k0 + tx;
    __nv_bfloat16 hi = __float2bfloat16_rn(a);
    g_wt0[o] = hi;
    g_wt1[o] = __float2bfloat16_rn(a - __bfloat162float(hi));
  }
}

// ----------------- Cauchy kernel (prep fused in) -----------------------------
__global__ __launch_bounds__(256) void cauchy_kernel(
    const float* __restrict__ Lre, const float* __restrict__ Lim,
    const float* __restrict__ Pre, const float* __restrict__ Pim,
    const float* __restrict__ Bre, const float* __restrict__ Bim,
    const float* __restrict__ Cre, const float* __restrict__ Cim,
    const float* __restrict__ logstep){
  __shared__ float4 spk01[Nst];
  __shared__ float4 spk23[Nst];
  __shared__ float2 slam [Nst];
  __shared__ float  s2step;
  int tid = threadIdx.x;
  int h = blockIdx.y;
  int l = blockIdx.x*256 + tid;
  if (tid < Nst){
    int i = h*Nst + tid;
    float pr = Pre[i], pi = Pim[i];
    float br = Bre[i], bi = Bim[i];
    float cr = Cre[i], ci = Cim[i];
    spk01[tid] = make_float4(cr*br + ci*bi, cr*bi - ci*br,
                             cr*pr + ci*pi, cr*pi - ci*pr);
    spk23[tid] = make_float4(pr*br + pi*bi, pr*bi - pi*br,
                             pr*pr + pi*pi, 0.f);
    slam [tid] = make_float2(fminf(Lre[i], -1e-4f), Lim[i]);
  }
  if (tid == 0) s2step = 2.f*expf(-logstep[h]);
  __syncthreads();
  float t   = tanf((float)(3.141592653589793/2048.0)*(float)l);
  float gim = s2step*t;
  float k00r=0.f,k00i=0.f,k01r=0.f,k01i=0.f,k10r=0.f,k10i=0.f,k11r=0.f,k11i=0.f;
  #pragma unroll 8
  for (int n = 0; n < Nst; n++){
    float2 lam = slam[n];
    float dre = -lam.x;
    float dim = gim - lam.y;
    float inv = frcp_fast(dre*dre + dim*dim);
    float ir  =  dre*inv;
    float ii  = -dim*inv;
    float4 w01 = spk01[n];
    float4 w23 = spk23[n];
    k00r += w01.x*ir - w01.y*ii;  k00i += w01.x*ii + w01.y*ir;
    k01r += w01.z*ir - w01.w*ii;  k01i += w01.z*ii + w01.w*ir;
    k10r += w23.x*ir - w23.y*ii;  k10i += w23.x*ii + w23.y*ir;
    k11r += w23.z*ir;             k11i += w23.z*ii;
  }
  float denr = 1.f + k11r, deni = k11i;
  float dinv = frcp_fast(denr*denr + deni*deni);
  float qr = denr*dinv, qi = -deni*dinv;
  float mr = k01r*k10r - k01i*k10i;
  float mi = k01r*k10i + k01i*k10r;
  float cr = mr*qr - mi*qi, ci2 = mr*qi + mi*qr;
  float ar = k00r - cr, ai = k00i - ci2;
  g_ar[(size_t)h*Lseq + l] = make_float2(ar - t*ai, ai + t*ar);
}

// ----------------- shared-mem radix-8 Stockham FFT(2048) ---------------------
// 3 radix-8 stages (s=1,8,64) + 1 twiddle-free radix-4 (s=512).
// stw may point to GLOBAL memory (g_twA) — table is small and L1-hot.
template<bool INV>
__device__ __forceinline__ float2* fft2048_r8(float2* buf0, float2* buf1,
                                              const float2* __restrict__ stw, int tid){
  const float C2 = 0.7071067811865476f;
  float2* src = buf0; float2* dst = buf1;
  #pragma unroll
  for (int st = 0; st < 3; st++){
    int s = 1 << (3*st);            // 1, 8, 64
    __syncthreads();
    int idx = tid;
    int sp  = idx & ~(s-1);
    float2 a0 = src[idx       ];
    float2 a1 = src[idx +  256];
    float2 a2 = src[idx +  512];
    float2 a3 = src[idx +  768];
    float2 a4 = src[idx + 1024];
    float2 a5 = src[idx + 1280];
    float2 a6 = src[idx + 1536];
    float2 a7 = src[idx + 1792];
    float2 t0 = cadd(a0,a4), t1 = csub(a0,a4);
    float2 t2 = cadd(a2,a6), t3 = csub(a2,a6);
    float2 e0 = cadd(t0,t2), e2 = csub(t0,t2);
    float2 u0 = cadd(a1,a5), u1 = csub(a1,a5);
    float2 u2 = cadd(a3,a7), u3 = csub(a3,a7);
    float2 o0 = cadd(u0,u2), o2 = csub(u0,u2);
    float2 e1, e3, o1, o3, m1, m2, m3;
    if (!INV){
      e1 = make_float2(t1.x + t3.y, t1.y - t3.x);
      e3 = make_float2(t1.x - t3.y, t1.y + t3.x);
      o1 = make_float2(u1.x + u3.y, u1.y - u3.x);
      o3 = make_float2(u1.x - u3.y, u1.y + u3.x);
      m1 = make_float2(C2*(o1.x + o1.y), C2*(o1.y - o1.x));
      m2 = make_float2(o2.y, -o2.x);
      m3 = make_float2(C2*(o3.y - o3.x), -C2*(o3.x + o3.y));
    } else {
      e1 = make_float2(t1.x - t3.y, t1.y + t3.x);
      e3 = make_float2(t1.x + t3.y, t1.y - t3.x);
      o1 = make_float2(u1.x - u3.y, u1.y + u3.x);
      o3 = make_float2(u1.x + u3.y, u1.y - u3.x);
      m1 = make_float2(C2*(o1.x - o1.y), C2*(o1.x + o1.y));
      m2 = make_float2(-o2.y, o2.x);
      m3 = make_float2(-C2*(o3.x + o3.y), C2*(o3.x - o3.y));
    }
    float2 B0 = cadd(e0,o0), B4 = csub(e0,o0);
    float2 B1 = cadd(e1,m1), B5 = csub(e1,m1);
    float2 B2 = cadd(e2,m2), B6 = csub(e2,m2);
    float2 B3 = cadd(e3,m3), B7 = csub(e3,m3);
    float2 w1 = stw[sp], w2 = stw[2*sp], w4 = stw[4*sp];
    if (INV){ w1.y = -w1.y; w2.y = -w2.y; w4.y = -w4.y; }
    float2 w3 = cmul(w1,w2);
    float2 w5 = cmul(w1,w4);
    float2 w6 = cmul(w2,w4);
    float2 w7 = cmul(w3,w4);
    int j = idx + 7*sp;
    dst[j      ] = B0;
    dst[j +   s] = cmul(B1,w1);
    dst[j + 2*s] = cmul(B2,w2);
    dst[j + 3*s] = cmul(B3,w3);
    dst[j + 4*s] = cmul(B4,w4);
    dst[j + 5*s] = cmul(B5,w5);
    dst[j + 6*s] = cmul(B6,w6);
    dst[j + 7*s] = cmul(B7,w7);
    float2* tp = src; src = dst; dst = tp;
  }
  // final radix-4, s=512: twiddle-free
  __syncthreads();
  #pragma unroll
  for (int i = 0; i < 2; i++){
    int idx = tid + 256*i;
    float2 a0 = src[idx];
    float2 a1 = src[idx + 512];
    float2 a2 = src[idx + 1024];
    float2 a3 = src[idx + 1536];
    float2 t0 = cadd(a0,a2), t1 = csub(a0,a2);
    float2 t2 = cadd(a1,a3), t3 = csub(a1,a3);
    float2 b0 = cadd(t0,t2), b2 = csub(t0,t2);
    float2 b1, b3;
    if (!INV){
      b1 = make_float2(t1.x + t3.y, t1.y - t3.x);
      b3 = make_float2(t1.x - t3.y, t1.y + t3.x);
    } else {
      b1 = make_float2(t1.x - t3.y, t1.y + t3.x);
      b3 = make_float2(t1.x + t3.y, t1.y - t3.x);
    }
    dst[idx       ] = b0;
    dst[idx +  512] = b1;
    dst[idx + 1024] = b2;
    dst[idx + 1536] = b3;
  }
  float2* tp = src; src = dst; dst = tp;
  __syncthreads();
  return src;
}

// ----------------- Kd kernel ------------------------------------------------
__global__ __launch_bounds__(256) void kd_kernel(float2* __restrict__ Kd){
  __shared__ float2 sA[2048];
  __shared__ float2 sB[2048];
  int tid = threadIdx.x;
  int h = blockIdx.x;
  const float2* ar = g_ar + (size_t)h*Lseq;
  #pragma unroll
  for (int i = 0; i < 8; i++){ int k = tid + 256*i; sA[k] = ar[k]; }
  float2* K = fft2048_r8<true>(sA, sB, g_twA, tid);
  float2* Ob = (K == sA) ? sB : sA;
  const float sc = 1.f/2048.f;
  #pragma unroll
  for (int i = 0; i < 8; i++){
    int n = tid + 256*i;
    float2 v = make_float2(0.f, 0.f);
    if (n < 1024) v = make_float2(K[2*n].x*sc, K[2*n+1].x*sc);
    Ob[n] = v;
  }
  float2* Zp = fft2048_r8<false>(Ob, K, g_twA, tid);
  float2* outKd = Kd + (size_t)h*2049;
  #pragma unroll
  for (int i = 0; i < 8; i++){
    int k  = tid + 256*i;
    int kc = (2048 - k) & 2047;
    float2 zk = Zp[k], zc = Zp[kc];
    float2 E  = make_float2(0.5f*(zk.x+zc.x),  0.5f*(zk.y-zc.y));
    float2 Od = make_float2(0.5f*(zk.y+zc.y), -0.5f*(zk.x-zc.x));
    outKd[k] = cadd(E, cmul(g_twB[k], Od));
  }
  if (tid == 0){
    float2 z0 = Zp[0];
    outKd[2048] = make_float2(z0.x - z0.y, 0.f);
  }
}

// ----------------- conv kernel (fused untangle*Kd*retangle, fused D) ---------
__global__ __launch_bounds__(256) void conv_kernel(const float2* __restrict__ Kdbase,
                                                   const float* __restrict__ Dp){
  __shared__ float2 sA[2048];
  __shared__ float2 sB[2048];
  int tid = threadIdx.x;
  int h = blockIdx.x;
  int b = blockIdx.y;
  const float* u = g_ht + ((size_t)b*Hdim + h)*Lseq;
  float ur[8];
  #pragma unroll
  for (int i = 0; i < 4; i++){
    int n = tid + 256*i;
    float u0 = u[2*n], u1 = u[2*n+1];
    ur[2*i] = u0; ur[2*i+1] = u1;
    sA[n]        = make_float2(u0, u1);
    sA[n + 1024] = make_float2(0.f, 0.f);
  }
  float2* Z = fft2048_r8<false>(sA, sB, g_twA, tid);
  float2* O = (Z == sA) ? sB : sA;
  const float2* kd = Kdbase + (size_t)h*2049;
  // fused: untangle -> *Kd -> retangle, one pass over conjugate pairs
  #pragma unroll
  for (int i = 0; i < 4; i++){
    int k = tid + 256*i;               // 0..1023
    if (k == 0){
      float2 z0 = Z[0];
      float U0 = z0.x + z0.y;
      float U2 = z0.x - z0.y;
      float2 k0 = kd[0], k2 = kd[2048];
      float2 Y0 = make_float2(U0*k0.x, U0*k0.y);
      float2 Y2 = make_float2(U2*k2.x, U2*k2.y);
      float2 Ey = make_float2(0.5f*(Y0.x+Y2.x), 0.5f*(Y0.y-Y2.y));
      float2 Dm = make_float2(0.5f*(Y0.x-Y2.x), 0.5f*(Y0.y+Y2.y));
      O[0] = make_float2(Ey.x - Dm.y, Ey.y + Dm.x);
      float2 zm = Z[1024];
      float2 Um = make_float2(zm.x, -zm.y);
      float2 Ym = cmul(Um, kd[1024]);
      O[1024] = make_float2(Ym.x, -Ym.y);
    } else {
      int kc = 2048 - k;
      float2 zk = Z[k], zc = Z[kc];
      float2 E  = make_float2(0.5f*(zk.x+zc.x),  0.5f*(zk.y-zc.y));
      float2 Od = make_float2(0.5f*(zk.y+zc.y), -0.5f*(zk.x-zc.x));
      float2 tk = g_twB[k];
      float2 P  = cmul(tk, Od);
      float2 Uk = cadd(E, P);
      float2 EmP = csub(E, P);
      float2 Uc = make_float2(EmP.x, -EmP.y);      // conj(E - P)
      float2 Yk = cmul(Uk, kd[k]);
      float2 Yc = cmul(Uc, kd[kc]);
      float2 Ey = make_float2(0.5f*(Yk.x+Yc.x), 0.5f*(Yk.y-Yc.y));
      float2 Dm = make_float2(0.5f*(Yk.x-Yc.x), 0.5f*(Yk.y+Yc.y));
      float2 Oy = cmul(Dm, make_float2(tk.x, -tk.y));   // Dm * conj(t_k)
      O[k]  = make_float2(Ey.x - Oy.y,  Ey.y + Oy.x);
      O[kc] = make_float2(Ey.x + Oy.y, -Ey.y + Oy.x);   // conjugate-pair form
    }
  }
  float2* w = fft2048_r8<true>(O, Z, g_twA, tid);
  float* out = g_yt + ((size_t)b*Hdim + h)*Lseq;
  const float sc = 1.f/2048.f;
  float Dh = Dp[h];
  #pragma unroll
  for (int i = 0; i < 4; i++){
    int n = tid + 256*i;
    float2 v = w[n];
    out[2*n]   = v.x*sc + Dh*ur[2*i];
    out[2*n+1] = v.y*sc + Dh*ur[2*i+1];
  }
}

// ----------------- HMMA GEMM: 128x128 tile, bf16x3 (R8-proven config) --------
#define TROW    80
#define TBYTES  (128*TROW)
#define STAGEB  (4*TBYTES)
#define SMEM_GEMM (2*STAGEB)            // 81920

__global__ __launch_bounds__(256) void hgemm_kernel(
    const __nv_bfloat16* __restrict__ A0g, const __nv_bfloat16* __restrict__ A1g,
    const __nv_bfloat16* __restrict__ B0g, const __nv_bfloat16* __restrict__ B1g,
    const float* __restrict__ bias, const float* __restrict__ aux,
    const float* __restrict__ resid,
    float* __restrict__ C, int mode,
    __nv_bfloat16* __restrict__ S0, __nv_bfloat16* __restrict__ S1)
{
  extern __shared__ char smem[];
  uint32_t sb = smem_u32(smem);
  int tid = threadIdx.x, wid = tid >> 5, lid = tid & 31;
  int bn = blockIdx.x*128, bm = blockIdx.y*128;
  int mw = wid & 3, nw = wid >> 2;

  int lrow = tid >> 1;
  int lc0  = tid & 1;

  int arow = lid & 15;
  int aoff = (lid >> 4) * 16;
  int brow = ((lid >> 4) << 3) + (lid & 7);
  int boff = ((lid >> 3) & 1) * 16;

  float acc[2][8][4];
  #pragma unroll
  for (int i = 0; i < 2; i++)
    #pragma unroll
    for (int j = 0; j < 8; j++)
      #pragma unroll
      for (int q = 0; q < 4; q++) acc[i][j][q] = 0.f;

  #pragma unroll
  for (int j = 0; j < 2; j++){
    int c = lc0 + 2*j;
    uint32_t so = (uint32_t)lrow*TROW + (uint32_t)c*16;
    size_t ga = (size_t)(bm + lrow)*Hdim + c*8;
    size_t gb = (size_t)(bn + lrow)*Hdim + c*8;
    cp16(sb + so,             A0g + ga);
    cp16(sb + TBYTES   + so,  A1g + ga);
    cp16(sb + 2*TBYTES + so,  B0g + gb);
    cp16(sb + 3*TBYTES + so,  B1g + gb);
  }
  CP_COMMIT();

  for (int ch = 0; ch < 16; ch++){
    int st = ch & 1;
    if (ch < 15){
      uint32_t sbase = sb + (st^1)*STAGEB;
      int k0 = (ch+1)*32;
      #pragma unroll
      for (int j = 0; j < 2; j++){
        int c = lc0 + 2*j;
        uint32_t so = (uint32_t)lrow*TROW + (uint32_t)c*16;
        size_t ga = (size_t)(bm + lrow)*Hdim + k0 + c*8;
        size_t gb = (size_t)(bn + lrow)*Hdim + k0 + c*8;
        cp16(sbase + so,             A0g + ga);
        cp16(sbase + TBYTES   + so,  A1g + ga);
        cp16(sbase + 2*TBYTES + so,  B0g + gb);
        cp16(sbase + 3*TBYTES + so,  B1g + gb);
      }
      CP_COMMIT();
      asm volatile("cp.async.wait_group 1;" ::: "memory");
    } else {
      asm volatile("cp.async.wait_group 0;" ::: "memory");
    }
    __syncthreads();

    uint32_t sA0 = sb + st*STAGEB;
    uint32_t sA1 = sA0 + TBYTES;
    uint32_t sB0 = sA0 + 2*TBYTES;
    uint32_t sB1 = sA0 + 3*TBYTES;
    #pragma unroll
    for (int ks = 0; ks < 2; ks++){
      int kb = ks*32;
      uint32_t a0f[2][4], a1f[2][4], b0f[4][4], b1f[4][4];
      #pragma unroll
      for (int mi = 0; mi < 2; mi++){
        uint32_t ro = (uint32_t)(mw*32 + mi*16 + arow)*TROW + kb + aoff;
        ldsm4(a0f[mi], sA0 + ro);
        ldsm4(a1f[mi], sA1 + ro);
      }
      #pragma unroll
      for (int nj = 0; nj < 4; nj++){
        uint32_t ro = (uint32_t)(nw*64 + nj*16 + brow)*TROW + kb + boff;
        ldsm4(b0f[nj], sB0 + ro);
        ldsm4(b1f[nj], sB1 + ro);
      }
      #pragma unroll
      for (int mi = 0; mi < 2; mi++){
        #pragma unroll
        for (int nt = 0; nt < 8; nt++){
          int nj = nt >> 1, sub = (nt & 1)*2;
          mma16816(acc[mi][nt], a0f[mi], &b0f[nj][sub]);
          mma16816(acc[mi][nt], a1f[mi], &b0f[nj][sub]);
          mma16816(acc[mi][nt], a0f[mi], &b1f[nj][sub]);
        }
      }
    }
    __syncthreads();
  }

  // epilogue
  int qr = lid >> 2, qc = (lid & 3)*2;
  #pragma unroll
  for (int mi = 0; mi < 2; mi++){
    #pragma unroll
    for (int hf = 0; hf < 2; hf++){
      int row = bm + mw*32 + mi*16 + hf*8 + qr;
      float* crow = C + (size_t)row*Hdim;
      const float* xrow = aux + (size_t)row*Hdim;
      const float* rrow = resid + (size_t)row*Hdim;
      #pragma unroll
      for (int nt = 0; nt < 8; nt++){
        int col = bn + nw*64 + nt*8 + qc;
        float2 bv = *(const float2*)(bias + col);
        float v0 = acc[mi][nt][hf*2+0] + bv.x;
        float v1 = acc[mi][nt][hf*2+1] + bv.y;
        float2 o;
        if (mode == 0){
          o = make_float2(v0, v1);
        } else if (mode == 1){
          o = make_float2(gelu_f(v0), gelu_f(v1));
        } else if (mode == 2){
          float2 rv = *(const float2*)(rrow + col);
          float2 av = *(const float2*)(xrow + col);
          o.x = rv.x + av.x*sigm_f(v0);
          o.y = rv.y + av.y*sigm_f(v1);
        } else {
          float2 rv = *(const float2*)(rrow + col);
          o = make_float2(rv.x + v0, rv.y + v1);
        }
        *(float2*)(crow + col) = o;
        if (S0){
          size_t gi = (size_t)row*Hdim + col;
          __nv_bfloat16 h0 = __float2bfloat16_rn(o.x);
          __nv_bfloat16 h1 = __float2bfloat16_rn(o.y);
          __nv_bfloat162 p; p.x = h0; p.y = h1;
          *(__nv_bfloat162*)(S0 + gi) = p;
          __nv_bfloat162 q;
          q.x = __float2bfloat16_rn(o.x - __bfloat162float(h0));
          q.y = __float2bfloat16_rn(o.y - __bfloat162float(h1));
          *(__nv_bfloat162*)(S1 + gi) = q;
        }
      }
    }
  }
}

// ----------------- host driver ----------------------------------------------
extern "C" void kernel_launch(void* const* d_in, const int* in_sizes, int n_in,
                              void* d_out, int out_size){
  (void)in_sizes; (void)n_in; (void)out_size;
  const float* x     = (const float*)d_in[0];
  const float* sLre  = (const float*)d_in[1];
  const float* sLim  = (const float*)d_in[2];
  const float* sPre  = (const float*)d_in[3];
  const float* sPim  = (const float*)d_in[4];
  const float* sBre  = (const float*)d_in[5];
  const float* sBim  = (const float*)d_in[6];
  const float* sCre  = (const float*)d_in[7];
  const float* sCim  = (const float*)d_in[8];
  const float* sD    = (const float*)d_in[9];
  const float* sLog  = (const float*)d_in[10];
  const float* sb_ls = (const float*)d_in[11];
  const float* sb_lb = (const float*)d_in[12];
  const float* sb_W1 = (const float*)d_in[13];
  const float* sb_b1 = (const float*)d_in[14];
  const float* sb_W2 = (const float*)d_in[15];
  const float* sb_b2 = (const float*)d_in[16];
  const float* bk_ls = (const float*)d_in[17];
  const float* bk_lb = (const float*)d_in[18];
  const float* bk_W1 = (const float*)d_in[19];
  const float* bk_b1 = (const float*)d_in[20];
  const float* bk_W2 = (const float*)d_in[21];
  const float* bk_b2 = (const float*)d_in[22];
  float* out = (float*)d_out;

  float *p_x, *p_z1;
  float2* p_kd;
  __nv_bfloat16 *p_a0, *p_a1, *p_b0, *p_b1, *p_wt0, *p_wt1;
  cudaGetSymbolAddress((void**)&p_x,   g_x);
  cudaGetSymbolAddress((void**)&p_z1,  g_z1);
  cudaGetSymbolAddress((void**)&p_kd,  g_KdL);
  cudaGetSymbolAddress((void**)&p_a0,  g_a0);
  cudaGetSymbolAddress((void**)&p_a1,  g_a1);
  cudaGetSymbolAddress((void**)&p_b0,  g_b0);
  cudaGetSymbolAddress((void**)&p_b1,  g_b1);
  cudaGetSymbolAddress((void**)&p_wt0, g_wt0);
  cudaGetSymbolAddress((void**)&p_wt1, g_wt1);

  cudaFuncSetAttribute(hgemm_kernel, cudaFuncAttributeMaxDynamicSharedMemorySize, SMEM_GEMM);
  cudaFuncSetAttribute(lnT_kernel,   cudaFuncAttributeMaxDynamicSharedMemorySize, LNT_SMEM);

  cudaStream_t s2;
  cudaStreamCreateWithFlags(&s2, cudaStreamNonBlocking);
  cudaEvent_t evStart, evKd[4], evW[4], evWB[2];
  cudaEventCreateWithFlags(&evStart, cudaEventDisableTiming);
  for (int i = 0; i < 4; i++){
    cudaEventCreateWithFlags(&evKd[i], cudaEventDisableTiming);
    cudaEventCreateWithFlags(&evW[i],  cudaEventDisableTiming);
  }
  for (int b = 0; b < 2; b++) cudaEventCreateWithFlags(&evWB[b], cudaEventDisableTiming);

  dim3 wgrid(16, 16);
  dim3 tblk(32, 8);
  dim3 tgrid(Hdim/32, Lseq/32, Bsz);
  dim3 lgrid(Lseq/32, Bsz);
  dim3 ggrid(Hdim/128, NROW/128);

  init_tw_kernel<<<8, 256>>>();
  cudaEventRecord(evStart, 0);
  cudaStreamWaitEvent(s2, evStart, 0);

  cauchy_kernel<<<dim3(Lseq/256, Hdim), 256, 0, s2>>>(
      sLre, sLim, sPre, sPim, sBre, sBim, sCre, sCim, sLog);
  lnT_kernel<<<lgrid, 256, LNT_SMEM>>>(x, sb_ls, sb_lb);
  kd_kernel<<<Hdim, 256, 0, s2>>>(p_kd);
  cudaEventRecord(evKd[0], s2);
  wprep_kernel<<<wgrid, tblk, 0, s2>>>(sb_W1, 0);
  wprep_kernel<<<wgrid, tblk, 0, s2>>>(sb_W2, 4);
  cudaEventRecord(evW[0], s2);
  for (int i = 1; i < 4; i++){
    cauchy_kernel<<<dim3(Lseq/256, Hdim), 256, 0, s2>>>(
        sLre + i*HN, sLim + i*HN, sPre + i*HN, sPim + i*HN,
        sBre + i*HN, sBim + i*HN, sCre + i*HN, sCim + i*HN, sLog + i*Hdim);
    kd_kernel<<<Hdim, 256, 0, s2>>>(p_kd + (size_t)i*KDSZ);
    cudaEventRecord(evKd[i], s2);
    wprep_kernel<<<wgrid, tblk, 0, s2>>>(sb_W1 + (size_t)i*HH, i);
    wprep_kernel<<<wgrid, tblk, 0, s2>>>(sb_W2 + (size_t)i*HH, 4 + i);
    cudaEventRecord(evW[i], s2);
  }
  for (int b = 0; b < 2; b++){
    wprep_kernel<<<wgrid, tblk, 0, s2>>>(bk_W1 + (size_t)b*HH, 8 + b);
    wprep_kernel<<<wgrid, tblk, 0, s2>>>(bk_W2 + (size_t)b*HH, 10 + b);
    cudaEventRecord(evWB[b], s2);
  }

  for (int b = 0; b < 2; b++){
    for (int li = 0; li < 2; li++){
      int i = b*2 + li;
      if (i > 0)
        lnT_kernel<<<lgrid, 256, LNT_SMEM>>>(p_x, sb_ls + i*Hdim, sb_lb + i*Hdim);
      cudaStreamWaitEvent(0, evKd[i], 0);
      conv_kernel<<<dim3(Hdim, Bsz), 256>>>(p_kd + (size_t)i*KDSZ, sD + i*Hdim);
      transpose_bwd_kernel<<<tgrid, tblk>>>();
      cudaStreamWaitEvent(0, evW[i], 0);
      hgemm_kernel<<<ggrid, 256, SMEM_GEMM>>>(p_a0, p_a1,
          p_wt0 + (size_t)i*HH, p_wt1 + (size_t)i*HH,
          sb_b1 + i*Hdim, p_z1, p_z1, p_z1, 0, nullptr, nullptr);
      const float* res = (i == 0) ? x : p_x;
      hgemm_kernel<<<ggrid, 256, SMEM_GEMM>>>(p_a0, p_a1,
          p_wt0 + (size_t)(4+i)*HH, p_wt1 + (size_t)(4+i)*HH,
          sb_b2 + i*Hdim, p_z1, res, p_x, 2, nullptr, nullptr);
    }
    ln_kernel<<<NROW/8, 256>>>(p_x, bk_ls + b*Hdim, bk_lb + b*Hdim);
    cudaStreamWaitEvent(0, evWB[b], 0);
    hgemm_kernel<<<ggrid, 256, SMEM_GEMM>>>(p_a0, p_a1,
        p_wt0 + (size_t)(8+b)*HH, p_wt1 + (size_t)(8+b)*HH,
        bk_b1 + b*Hdim, p_z1, p_z1, p_z1, 1, p_b0, p_b1);
    float* Cfinal = (b == 1) ? out : p_x;
    hgemm_kernel<<<ggrid, 256, SMEM_GEMM>>>(p_b0, p_b1,
        p_wt0 + (size_t)(10+b)*HH, p_wt1 + (size_t)(10+b)*HH,
        bk_b2 + b*Hdim, p_z1, p_x, Cfinal, 3, nullptr, nullptr);
  }
}

// round 16
// speedup vs baseline: 1.3166x; 1.0041x over previous
#include <cuda_runtime.h>
#include <cuda_bf16.h>
#include <cstdint>
#include <math.h>

#define Bsz   8
#define Lseq  2048
#define Hdim  512
#define Nst   64
#define NROW  (Bsz*Lseq)          // 16384
#define BLH   (Bsz*Lseq*Hdim)     // 8388608
#define HH    (Hdim*Hdim)
#define HN    (Hdim*Nst)
#define KDSZ  (Hdim*2049)

// ----------------- device scratch (no allocations allowed) ------------------
__device__ float  g_x [BLH];
__device__ float  g_ht[BLH];
__device__ float  g_yt[BLH];
__device__ float  g_z1[BLH];
__device__ float2 g_ar[Hdim*Lseq];
__device__ float2 g_KdL[4*KDSZ];
__device__ float2 g_twA[1024];
__device__ float2 g_twB[2048];
__device__ __nv_bfloat16 g_a0[BLH];
__device__ __nv_bfloat16 g_a1[BLH];
__device__ __nv_bfloat16 g_b0[BLH];
__device__ __nv_bfloat16 g_b1[BLH];
__device__ __nv_bfloat16 g_wt0[12*HH];
__device__ __nv_bfloat16 g_wt1[12*HH];

// ----------------- helpers --------------------------------------------------
__device__ __forceinline__ float2 cadd(float2 a, float2 b){ return make_float2(a.x+b.x, a.y+b.y); }
__device__ __forceinline__ float2 csub(float2 a, float2 b){ return make_float2(a.x-b.x, a.y-b.y); }
__device__ __forceinline__ float2 cmul(float2 a, float2 b){ return make_float2(a.x*b.x-a.y*b.y, a.x*b.y+a.y*b.x); }
__device__ __forceinline__ float frcp_fast(float x){ float y; asm("rcp.approx.f32 %0, %1;" : "=f"(y) : "f"(x)); return y; }
__device__ __forceinline__ float gelu_f(float x){
  float u = 0.7978845608028654f*(x + 0.044715f*x*x*x);
  float e = __expf(2.f*u);
  float t = 1.f - 2.f/(e + 1.f);          // tanh(u), saturates correctly
  return 0.5f*x*(1.0f + t);
}
__device__ __forceinline__ float sigm_f(float x){ return 1.0f/(1.0f + __expf(-x)); }

__device__ __forceinline__ uint32_t smem_u32(const void* p){
  uint32_t a;
  asm("{ .reg .u64 t; cvta.to.shared.u64 t, %1; cvt.u32.u64 %0, t; }" : "=r"(a) : "l"(p));
  return a;
}
__device__ __forceinline__ void cp16(uint32_t saddr, const void* g){
  asm volatile("cp.async.ca.shared.global [%0], [%1], 16;" :: "r"(saddr), "l"(g));
}
#define CP_COMMIT() asm volatile("cp.async.commit_group;" ::: "memory")

__device__ __forceinline__ void ldsm4(uint32_t* r, uint32_t addr){
  asm volatile("ldmatrix.sync.aligned.m8n8.x4.shared.b16 {%0,%1,%2,%3}, [%4];"
    : "=r"(r[0]), "=r"(r[1]), "=r"(r[2]), "=r"(r[3]) : "r"(addr));
}
__device__ __forceinline__ void mma16816(float* c, const uint32_t* a, const uint32_t* b){
  asm volatile("mma.sync.aligned.m16n8k16.row.col.f32.bf16.bf16.f32 "
    "{%0,%1,%2,%3}, {%4,%5,%6,%7}, {%8,%9}, {%0,%1,%2,%3};"
    : "+f"(c[0]), "+f"(c[1]), "+f"(c[2]), "+f"(c[3])
    : "r"(a[0]), "r"(a[1]), "r"(a[2]), "r"(a[3]), "r"(b[0]), "r"(b[1]));
}

// ----------------- twiddle init ---------------------------------------------
__global__ void init_tw_kernel(){
  int i = blockIdx.x*256 + threadIdx.x;
  if (i < 1024){
    float a = (float)(6.283185307179586/2048.0) * (float)i;
    float s, c; sincosf(a, &s, &c);
    g_twA[i] = make_float2(c, -s);
  }
  if (i < 2048){
    float a = (float)(3.141592653589793/2048.0) * (float)i;
    float s, c; sincosf(a, &s, &c);
    g_twB[i] = make_float2(c, -s);
  }
}

// ----------------- fused LN + transpose: xin (B,L,H) -> g_ht (B,H,L) --------
#define LNT_PAD  513
#define LNT_SMEM (32*LNT_PAD*4)   // 65664 bytes

__global__ __launch_bounds__(256) void lnT_kernel(const float* __restrict__ xin,
                                                  const float* __restrict__ sc,
                                                  const float* __restrict__ bi){
  extern __shared__ float tile[];      // [32][LNT_PAD]
  int b  = blockIdx.y;
  int l0 = blockIdx.x*32;
  int warp = threadIdx.x >> 5, lane = threadIdx.x & 31;
  const float4* s4 = (const float4*)sc;
  const float4* b4 = (const float4*)bi;
  #pragma unroll
  for (int r = warp; r < 32; r += 8){
    const float4* xr = (const float4*)(xin + ((size_t)b*Lseq + l0 + r)*Hdim);
    float4 v[4];
    float s = 0.f, s2 = 0.f;
    #pragma unroll
    for (int i = 0; i < 4; i++){
      float4 t = xr[lane + 32*i];
      v[i] = t;
      s  += t.x + t.y + t.z + t.w;
      s2 += t.x*t.x + t.y*t.y + t.z*t.z + t.w*t.w;
    }
    #pragma unroll
    for (int o = 16; o; o >>= 1){
      s  += __shfl_xor_sync(0xffffffffu, s,  o);
      s2 += __shfl_xor_sync(0xffffffffu, s2, o);
    }
    float mean = s*(1.f/Hdim);
    float var  = s2*(1.f/Hdim) - mean*mean;
    float inv  = rsqrtf(var + 1e-6f);
    float* trow = tile + r*LNT_PAD;
    #pragma unroll
    for (int i = 0; i < 4; i++){
      int ci = lane + 32*i;
      float4 sv = s4[ci], bv = b4[ci], t = v[i];
      trow[ci*4+0] = (t.x-mean)*inv*sv.x + bv.x;
      trow[ci*4+1] = (t.y-mean)*inv*sv.y + bv.y;
      trow[ci*4+2] = (t.z-mean)*inv*sv.z + bv.z;
      trow[ci*4+3] = (t.w-mean)*inv*sv.w + bv.w;
    }
  }
  __syncthreads();
  float* outb = g_ht + (size_t)b*Hdim*Lseq + l0 + lane;
  #pragma unroll 8
  for (int h0 = 0; h0 < Hdim; h0 += 8){
    int h = h0 + warp;
    outb[(size_t)h*Lseq] = tile[lane*LNT_PAD + h];
  }
}

// ----------------- layernorm (FFN path): xin -> bf16 splits only ------------
__global__ __launch_bounds__(256) void ln_kernel(const float* __restrict__ xin,
                                                 const float* __restrict__ sc,
                                                 const float* __restrict__ bi){
  int warp = threadIdx.x >> 5, lane = threadIdx.x & 31;
  size_t row = (size_t)blockIdx.x*8 + warp;
  const float4* xr = (const float4*)(xin + row*Hdim);
  float4 v[4];
  float s = 0.f, s2 = 0.f;
  #pragma unroll
  for (int i = 0; i < 4; i++){
    float4 t = xr[lane + 32*i];
    v[i] = t;
    s  += t.x + t.y + t.z + t.w;
    s2 += t.x*t.x + t.y*t.y + t.z*t.z + t.w*t.w;
  }
  #pragma unroll
  for (int o = 16; o; o >>= 1){
    s  += __shfl_xor_sync(0xffffffffu, s,  o);
    s2 += __shfl_xor_sync(0xffffffffu, s2, o);
  }
  float mean = s*(1.f/Hdim);
  float var  = s2*(1.f/Hdim) - mean*mean;
  float inv  = rsqrtf(var + 1e-6f);
  const float4* s4 = (const float4*)sc;
  const float4* b4 = (const float4*)bi;
  #pragma unroll
  for (int i = 0; i < 4; i++){
    int ci = lane + 32*i;
    float4 sv = s4[ci], bv = b4[ci], t = v[i], o;
    o.x = (t.x-mean)*inv*sv.x + bv.x;
    o.y = (t.y-mean)*inv*sv.y + bv.y;
    o.z = (t.z-mean)*inv*sv.z + bv.z;
    o.w = (t.w-mean)*inv*sv.w + bv.w;
    size_t gi = row*Hdim + ci*4;
    __nv_bfloat16 h0 = __float2bfloat16_rn(o.x);
    __nv_bfloat16 h1 = __float2bfloat16_rn(o.y);
    __nv_bfloat16 h2 = __float2bfloat16_rn(o.z);
    __nv_bfloat16 h3 = __float2bfloat16_rn(o.w);
    __nv_bfloat162 p0; p0.x = h0; p0.y = h1;
    __nv_bfloat162 p1; p1.x = h2; p1.y = h3;
    *(__nv_bfloat162*)(g_a0 + gi)     = p0;
    *(__nv_bfloat162*)(g_a0 + gi + 2) = p1;
    __nv_bfloat162 q0, q1;
    q0.x = __float2bfloat16_rn(o.x - __bfloat162float(h0));
    q0.y = __float2bfloat16_rn(o.y - __bfloat162float(h1));
    q1.x = __float2bfloat16_rn(o.z - __bfloat162float(h2));
    q1.y = __float2bfloat16_rn(o.w - __bfloat162float(h3));
    *(__nv_bfloat162*)(g_a1 + gi)     = q0;
    *(__nv_bfloat162*)(g_a1 + gi + 2) = q1;
  }
}

// ----------------- bwd transpose: g_yt (B,H,L) -> gelu -> bf16 splits -------
__global__ void transpose_bwd_kernel(){
  __shared__ float tile[32][33];
  int b  = blockIdx.z;
  int h0 = blockIdx.x*32;
  int l0 = blockIdx.y*32;
  int tx = threadIdx.x, ty = threadIdx.y;
  const float* in = g_yt + (size_t)b*Hdim*Lseq;
  #pragma unroll
  for (int j = 0; j < 32; j += 8)
    tile[ty+j][tx] = in[(size_t)(h0+ty+j)*Lseq + l0 + tx];
  __syncthreads();
  size_t boff = (size_t)b*Lseq*Hdim;
  #pragma unroll
  for (int j = 0; j < 32; j += 8){
    size_t idx = boff + (size_t)(l0+ty+j)*Hdim + h0 + tx;
    float g = gelu_f(tile[tx][ty+j]);
    __nv_bfloat16 hi = __float2bfloat16_rn(g);
    float r = g - __bfloat162float(hi);
    g_a0[idx] = hi;
    g_a1[idx] = __float2bfloat16_rn(r);
  }
}

// ----------------- weight transpose + split ----------------------------------
__global__ void wprep_kernel(const float* __restrict__ W, int widx){
  __shared__ float tile[32][33];
  int n0 = blockIdx.x*32, k0 = blockIdx.y*32;
  int tx = threadIdx.x, ty = threadIdx.y;
  #pragma unroll
  for (int j = 0; j < 32; j += 8)
    tile[ty+j][tx] = W[(size_t)(k0+ty+j)*Hdim + n0 + tx];
  __syncthreads();
  size_t base = (size_t)widx*HH;
  #pragma unroll
  for (int j = 0; j < 32; j += 8){
    float a = tile[tx][ty+j];
    size_t o = base + (size_t)(n0+ty+j)*Hdim + k0 + tx;
    __nv_bfloat16 hi = __float2bfloat16_rn(a);
    g_wt0[o] = hi;
    g_wt1[o] = __float2bfloat16_rn(a - __bfloat162float(hi));
  }
}

// ----------------- Cauchy kernel (prep fused in) -----------------------------
__global__ __launch_bounds__(256) void cauchy_kernel(
    const float* __restrict__ Lre, const float* __restrict__ Lim,
    const float* __restrict__ Pre, const float* __restrict__ Pim,
    const float* __restrict__ Bre, const float* __restrict__ Bim,
    const float* __restrict__ Cre, const float* __restrict__ Cim,
    const float* __restrict__ logstep){
  __shared__ float4 spk01[Nst];
  __shared__ float4 spk23[Nst];
  __shared__ float2 slam [Nst];
  __shared__ float  s2step;
  int tid = threadIdx.x;
  int h = blockIdx.y;
  int l = blockIdx.x*256 + tid;
  if (tid < Nst){
    int i = h*Nst + tid;
    float pr = Pre[i], pi = Pim[i];
    float br = Bre[i], bi = Bim[i];
    float cr = Cre[i], ci = Cim[i];
    spk01[tid] = make_float4(cr*br + ci*bi, cr*bi - ci*br,
                             cr*pr + ci*pi, cr*pi - ci*pr);
    spk23[tid] = make_float4(pr*br + pi*bi, pr*bi - pi*br,
                             pr*pr + pi*pi, 0.f);
    slam [tid] = make_float2(fminf(Lre[i], -1e-4f), Lim[i]);
  }
  if (tid == 0) s2step = 2.f*expf(-logstep[h]);
  __syncthreads();
  float t   = tanf((float)(3.141592653589793/2048.0)*(float)l);
  float gim = s2step*t;
  float k00r=0.f,k00i=0.f,k01r=0.f,k01i=0.f,k10r=0.f,k10i=0.f,k11r=0.f,k11i=0.f;
  #pragma unroll 8
  for (int n = 0; n < Nst; n++){
    float2 lam = slam[n];
    float dre = -lam.x;
    float dim = gim - lam.y;
    float inv = frcp_fast(dre*dre + dim*dim);
    float ir  =  dre*inv;
    float ii  = -dim*inv;
    float4 w01 = spk01[n];
    float4 w23 = spk23[n];
    k00r += w01.x*ir - w01.y*ii;  k00i += w01.x*ii + w01.y*ir;
    k01r += w01.z*ir - w01.w*ii;  k01i += w01.z*ii + w01.w*ir;
    k10r += w23.x*ir - w23.y*ii;  k10i += w23.x*ii + w23.y*ir;
    k11r += w23.z*ir;             k11i += w23.z*ii;
  }
  float denr = 1.f + k11r, deni = k11i;
  float dinv = frcp_fast(denr*denr + deni*deni);
  float qr = denr*dinv, qi = -deni*dinv;
  float mr = k01r*k10r - k01i*k10i;
  float mi = k01r*k10i + k01i*k10r;
  float cr = mr*qr - mi*qi, ci2 = mr*qi + mi*qr;
  float ar = k00r - cr, ai = k00i - ci2;
  g_ar[(size_t)h*Lseq + l] = make_float2(ar - t*ai, ai + t*ar);
}

// ----------------- shared-mem radix-8 Stockham FFT(2048) ---------------------
// 3 radix-8 stages (s=1,8,64) + 1 twiddle-free radix-4 (s=512).
// ZTOP: input entries [1024,2048) are zero (stage 0 skips those reads).
// HALFOUT: only outputs [0,1024) are needed (final stage skips b2/b3).
template<bool INV, bool ZTOP, bool HALFOUT>
__device__ __forceinline__ float2* fft2048_r8(float2* buf0, float2* buf1,
                                              const float2* __restrict__ stw, int tid){
  const float C2 = 0.7071067811865476f;
  float2* src = buf0; float2* dst = buf1;
  #pragma unroll
  for (int st = 0; st < 3; st++){
    int s = 1 << (3*st);            // 1, 8, 64
    __syncthreads();
    int idx = tid;
    int sp  = idx & ~(s-1);
    float2 e0, e1, e2, e3, o0, o1, o2, o3;
    if (ZTOP && st == 0){
      // a4..a7 = 0  ->  t0=t1=a0, t2=t3=a2, u0=u1=a1, u2=u3=a3
      float2 a0 = src[idx      ];
      float2 a1 = src[idx + 256];
      float2 a2 = src[idx + 512];
      float2 a3 = src[idx + 768];
      e0 = cadd(a0,a2); e2 = csub(a0,a2);
      o0 = cadd(a1,a3); o2 = csub(a1,a3);
      if (!INV){
        e1 = make_float2(a0.x + a2.y, a0.y - a2.x);
        e3 = make_float2(a0.x - a2.y, a0.y + a2.x);
        o1 = make_float2(a1.x + a3.y, a1.y - a3.x);
        o3 = make_float2(a1.x - a3.y, a1.y + a3.x);
      } else {
        e1 = make_float2(a0.x - a2.y, a0.y + a2.x);
        e3 = make_float2(a0.x + a2.y, a0.y - a2.x);
        o1 = make_float2(a1.x - a3.y, a1.y + a3.x);
        o3 = make_float2(a1.x + a3.y, a1.y - a3.x);
      }
    } else {
      float2 a0 = src[idx       ];
      float2 a1 = src[idx +  256];
      float2 a2 = src[idx +  512];
      float2 a3 = src[idx +  768];
      float2 a4 = src[idx + 1024];
      float2 a5 = src[idx + 1280];
      float2 a6 = src[idx + 1536];
      float2 a7 = src[idx + 1792];
      float2 t0 = cadd(a0,a4), t1 = csub(a0,a4);
      float2 t2 = cadd(a2,a6), t3 = csub(a2,a6);
      e0 = cadd(t0,t2); e2 = csub(t0,t2);
      float2 u0 = cadd(a1,a5), u1 = csub(a1,a5);
      float2 u2 = cadd(a3,a7), u3 = csub(a3,a7);
      o0 = cadd(u0,u2); o2 = csub(u0,u2);
      if (!INV){
        e1 = make_float2(t1.x + t3.y, t1.y - t3.x);
        e3 = make_float2(t1.x - t3.y, t1.y + t3.x);
        o1 = make_float2(u1.x + u3.y, u1.y - u3.x);
        o3 = make_float2(u1.x - u3.y, u1.y + u3.x);
      } else {
        e1 = make_float2(t1.x - t3.y, t1.y + t3.x);
        e3 = make_float2(t1.x + t3.y, t1.y - t3.x);
        o1 = make_float2(u1.x - u3.y, u1.y + u3.x);
        o3 = make_float2(u1.x + u3.y, u1.y - u3.x);
      }
    }
    float2 m1, m2, m3;
    if (!INV){
      m1 = make_float2(C2*(o1.x + o1.y), C2*(o1.y - o1.x));
      m2 = make_float2(o2.y, -o2.x);
      m3 = make_float2(C2*(o3.y - o3.x), -C2*(o3.x + o3.y));
    } else {
      m1 = make_float2(C2*(o1.x - o1.y), C2*(o1.x + o1.y));
      m2 = make_float2(-o2.y, o2.x);
      m3 = make_float2(-C2*(o3.x + o3.y), C2*(o3.x - o3.y));
    }
    float2 B0 = cadd(e0,o0), B4 = csub(e0,o0);
    float2 B1 = cadd(e1,m1), B5 = csub(e1,m1);
    float2 B2 = cadd(e2,m2), B6 = csub(e2,m2);
    float2 B3 = cadd(e3,m3), B7 = csub(e3,m3);
    float2 w1 = stw[sp], w2 = stw[2*sp], w4 = stw[4*sp];
    if (INV){ w1.y = -w1.y; w2.y = -w2.y; w4.y = -w4.y; }
    float2 w3 = cmul(w1,w2);
    float2 w5 = cmul(w1,w4);
    float2 w6 = cmul(w2,w4);
    float2 w7 = cmul(w3,w4);
    int j = idx + 7*sp;
    dst[j      ] = B0;
    dst[j +   s] = cmul(B1,w1);
    dst[j + 2*s] = cmul(B2,w2);
    dst[j + 3*s] = cmul(B3,w3);
    dst[j + 4*s] = cmul(B4,w4);
    dst[j + 5*s] = cmul(B5,w5);
    dst[j + 6*s] = cmul(B6,w6);
    dst[j + 7*s] = cmul(B7,w7);
    float2* tp = src; src = dst; dst = tp;
  }
  // final radix-4, s=512: twiddle-free
  __syncthreads();
  #pragma unroll
  for (int i = 0; i < 2; i++){
    int idx = tid + 256*i;
    float2 a0 = src[idx];
    float2 a1 = src[idx + 512];
    float2 a2 = src[idx + 1024];
    float2 a3 = src[idx + 1536];
    float2 t0 = cadd(a0,a2), t1 = csub(a0,a2);
    float2 t2 = cadd(a1,a3), t3 = csub(a1,a3);
    float2 b0 = cadd(t0,t2);
    dst[idx] = b0;
    float2 b1;
    if (!INV) b1 = make_float2(t1.x + t3.y, t1.y - t3.x);
    else      b1 = make_float2(t1.x - t3.y, t1.y + t3.x);
    dst[idx + 512] = b1;
    if (!HALFOUT){
      float2 b2 = csub(t0,t2);
      float2 b3;
      if (!INV) b3 = make_float2(t1.x - t3.y, t1.y + t3.x);
      else      b3 = make_float2(t1.x + t3.y, t1.y - t3.x);
      dst[idx + 1024] = b2;
      dst[idx + 1536] = b3;
    }
  }
  float2* tp = src; src = dst; dst = tp;
  __syncthreads();
  return src;
}

// ----------------- Kd kernel ------------------------------------------------
__global__ __launch_bounds__(256) void kd_kernel(float2* __restrict__ Kd){
  __shared__ float2 sA[2048];
  __shared__ float2 sB[2048];
  int tid = threadIdx.x;
  int h = blockIdx.x;
  const float2* ar = g_ar + (size_t)h*Lseq;
  #pragma unroll
  for (int i = 0; i < 8; i++){ int k = tid + 256*i; sA[k] = ar[k]; }
  float2* K = fft2048_r8<true,false,false>(sA, sB, g_twA, tid);
  float2* Ob = (K == sA) ? sB : sA;
  const float sc = 1.f/2048.f;
  #pragma unroll
  for (int i = 0; i < 4; i++){
    int n = tid + 256*i;   // < 1024 only; upper half unused under ZTOP
    Ob[n] = make_float2(K[2*n].x*sc, K[2*n+1].x*sc);
  }
  float2* Zp = fft2048_r8<false,true,false>(Ob, K, g_twA, tid);
  float2* outKd = Kd + (size_t)h*2049;
  #pragma unroll
  for (int i = 0; i < 8; i++){
    int k  = tid + 256*i;
    int kc = (2048 - k) & 2047;
    float2 zk = Zp[k], zc = Zp[kc];
    float2 E  = make_float2(0.5f*(zk.x+zc.x),  0.5f*(zk.y-zc.y));
    float2 Od = make_float2(0.5f*(zk.y+zc.y), -0.5f*(zk.x-zc.x));
    outKd[k] = cadd(E, cmul(g_twB[k], Od));
  }
  if (tid == 0){
    float2 z0 = Zp[0];
    outKd[2048] = make_float2(z0.x - z0.y, 0.f);
  }
}

// ----------------- conv kernel (fused untangle*Kd*retangle, fused D) ---------
__global__ __launch_bounds__(256) void conv_kernel(const float2* __restrict__ Kdbase,
                                                   const float* __restrict__ Dp){
  __shared__ float2 sA[2048];
  __shared__ float2 sB[2048];
  int tid = threadIdx.x;
  int h = blockIdx.x;
  int b = blockIdx.y;
  const float* u = g_ht + ((size_t)b*Hdim + h)*Lseq;
  float ur[8];
  #pragma unroll
  for (int i = 0; i < 4; i++){
    int n = tid + 256*i;
    float u0 = u[2*n], u1 = u[2*n+1];
    ur[2*i] = u0; ur[2*i+1] = u1;
    sA[n] = make_float2(u0, u1);     // upper half not written (ZTOP)
  }
  float2* Z = fft2048_r8<false,true,false>(sA, sB, g_twA, tid);
  float2* O = (Z == sA) ? sB : sA;
  const float2* kd = Kdbase + (size_t)h*2049;
  // fused: untangle -> *Kd -> retangle, one pass over conjugate pairs
  #pragma unroll
  for (int i = 0; i < 4; i++){
    int k = tid + 256*i;               // 0..1023
    if (k == 0){
      float2 z0 = Z[0];
      float U0 = z0.x + z0.y;
      float U2 = z0.x - z0.y;
      float2 k0 = kd[0], k2 = kd[2048];
      float2 Y0 = make_float2(U0*k0.x, U0*k0.y);
      float2 Y2 = make_float2(U2*k2.x, U2*k2.y);
      float2 Ey = make_float2(0.5f*(Y0.x+Y2.x), 0.5f*(Y0.y-Y2.y));
      float2 Dm = make_float2(0.5f*(Y0.x-Y2.x), 0.5f*(Y0.y+Y2.y));
      O[0] = make_float2(Ey.x - Dm.y, Ey.y + Dm.x);
      float2 zm = Z[1024];
      float2 Um = make_float2(zm.x, -zm.y);
      float2 Ym = cmul(Um, kd[1024]);
      O[1024] = make_float2(Ym.x, -Ym.y);
    } else {
      int kc = 2048 - k;
      float2 zk = Z[k], zc = Z[kc];
      float2 E  = make_float2(0.5f*(zk.x+zc.x),  0.5f*(zk.y-zc.y));
      float2 Od = make_float2(0.5f*(zk.y+zc.y), -0.5f*(zk.x-zc.x));
      float2 tk = g_twB[k];
      float2 P  = cmul(tk, Od);
      float2 Uk = cadd(E, P);
      float2 EmP = csub(E, P);
      float2 Uc = make_float2(EmP.x, -EmP.y);      // conj(E - P)
      float2 Yk = cmul(Uk, kd[k]);
      float2 Yc = cmul(Uc, kd[kc]);
      float2 Ey = make_float2(0.5f*(Yk.x+Yc.x), 0.5f*(Yk.y-Yc.y));
      float2 Dm = make_float2(0.5f*(Yk.x-Yc.x), 0.5f*(Yk.y+Yc.y));
      float2 Oy = cmul(Dm, make_float2(tk.x, -tk.y));   // Dm * conj(t_k)
      O[k]  = make_float2(Ey.x - Oy.y,  Ey.y + Oy.x);
      O[kc] = make_float2(Ey.x + Oy.y, -Ey.y + Oy.x);   // conjugate-pair form
    }
  }
  float2* w = fft2048_r8<true,false,true>(O, Z, g_twA, tid);
  float* out = g_yt + ((size_t)b*Hdim + h)*Lseq;
  const float sc = 1.f/2048.f;
  float Dh = Dp[h];
  #pragma unroll
  for (int i = 0; i < 4; i++){
    int n = tid + 256*i;
    float2 v = w[n];
    out[2*n]   = v.x*sc + Dh*ur[2*i];
    out[2*n+1] = v.y*sc + Dh*ur[2*i+1];
  }
}

// ----------------- HMMA GEMM: 128x128 tile, bf16x3 (R8-proven config) --------
#define TROW    80
#define TBYTES  (128*TROW)
#define STAGEB  (4*TBYTES)
#define SMEM_GEMM (2*STAGEB)            // 81920

__global__ __launch_bounds__(256) void hgemm_kernel(
    const __nv_bfloat16* __restrict__ A0g, const __nv_bfloat16* __restrict__ A1g,
    const __nv_bfloat16* __restrict__ B0g, const __nv_bfloat16* __restrict__ B1g,
    const float* __restrict__ bias, const float* __restrict__ aux,
    const float* __restrict__ resid,
    float* __restrict__ C, int mode,
    __nv_bfloat16* __restrict__ S0, __nv_bfloat16* __restrict__ S1)
{
  extern __shared__ char smem[];
  uint32_t sb = smem_u32(smem);
  int tid = threadIdx.x, wid = tid >> 5, lid = tid & 31;
  int bn = blockIdx.x*128, bm = blockIdx.y*128;
  int mw = wid & 3, nw = wid >> 2;

  int lrow = tid >> 1;
  int lc0  = tid & 1;

  int arow = lid & 15;
  int aoff = (lid >> 4) * 16;
  int brow = ((lid >> 4) << 3) + (lid & 7);
  int boff = ((lid >> 3) & 1) * 16;

  float acc[2][8][4];
  #pragma unroll
  for (int i = 0; i < 2; i++)
    #pragma unroll
    for (int j = 0; j < 8; j++)
      #pragma unroll
      for (int q = 0; q < 4; q++) acc[i][j][q] = 0.f;

  #pragma unroll
  for (int j = 0; j < 2; j++){
    int c = lc0 + 2*j;
    uint32_t so = (uint32_t)lrow*TROW + (uint32_t)c*16;
    size_t ga = (size_t)(bm + lrow)*Hdim + c*8;
    size_t gb = (size_t)(bn + lrow)*Hdim + c*8;
    cp16(sb + so,             A0g + ga);
    cp16(sb + TBYTES   + so,  A1g + ga);
    cp16(sb + 2*TBYTES + so,  B0g + gb);
    cp16(sb + 3*TBYTES + so,  B1g + gb);
  }
  CP_COMMIT();

  for (int ch = 0; ch < 16; ch++){
    int st = ch & 1;
    if (ch < 15){
      uint32_t sbase = sb + (st^1)*STAGEB;
      int k0 = (ch+1)*32;
      #pragma unroll
      for (int j = 0; j < 2; j++){
        int c = lc0 + 2*j;
        uint32_t so = (uint32_t)lrow*TROW + (uint32_t)c*16;
        size_t ga = (size_t)(bm + lrow)*Hdim + k0 + c*8;
        size_t gb = (size_t)(bn + lrow)*Hdim + k0 + c*8;
        cp16(sbase + so,             A0g + ga);
        cp16(sbase + TBYTES   + so,  A1g + ga);
        cp16(sbase + 2*TBYTES + so,  B0g + gb);
        cp16(sbase + 3*TBYTES + so,  B1g + gb);
      }
      CP_COMMIT();
      asm volatile("cp.async.wait_group 1;" ::: "memory");
    } else {
      asm volatile("cp.async.wait_group 0;" ::: "memory");
    }
    __syncthreads();

    uint32_t sA0 = sb + st*STAGEB;
    uint32_t sA1 = sA0 + TBYTES;
    uint32_t sB0 = sA0 + 2*TBYTES;
    uint32_t sB1 = sA0 + 3*TBYTES;
    #pragma unroll
    for (int ks = 0; ks < 2; ks++){
      int kb = ks*32;
      uint32_t a0f[2][4], a1f[2][4], b0f[4][4], b1f[4][4];
      #pragma unroll
      for (int mi = 0; mi < 2; mi++){
        uint32_t ro = (uint32_t)(mw*32 + mi*16 + arow)*TROW + kb + aoff;
        ldsm4(a0f[mi], sA0 + ro);
        ldsm4(a1f[mi], sA1 + ro);
      }
      #pragma unroll
      for (int nj = 0; nj < 4; nj++){
        uint32_t ro = (uint32_t)(nw*64 + nj*16 + brow)*TROW + kb + boff;
        ldsm4(b0f[nj], sB0 + ro);
        ldsm4(b1f[nj], sB1 + ro);
      }
      #pragma unroll
      for (int mi = 0; mi < 2; mi++){
        #pragma unroll
        for (int nt = 0; nt < 8; nt++){
          int nj = nt >> 1, sub = (nt & 1)*2;
          mma16816(acc[mi][nt], a0f[mi], &b0f[nj][sub]);
          mma16816(acc[mi][nt], a1f[mi], &b0f[nj][sub]);
          mma16816(acc[mi][nt], a0f[mi], &b1f[nj][sub]);
        }
      }
    }
    __syncthreads();
  }

  // epilogue
  int qr = lid >> 2, qc = (lid & 3)*2;
  #pragma unroll
  for (int mi = 0; mi < 2; mi++){
    #pragma unroll
    for (int hf = 0; hf < 2; hf++){
      int row = bm + mw*32 + mi*16 + hf*8 + qr;
      float* crow = C + (size_t)row*Hdim;
      const float* xrow = aux + (size_t)row*Hdim;
      const float* rrow = resid + (size_t)row*Hdim;
      #pragma unroll
      for (int nt = 0; nt < 8; nt++){
        int col = bn + nw*64 + nt*8 + qc;
        float2 bv = *(const float2*)(bias + col);
        float v0 = acc[mi][nt][hf*2+0] + bv.x;
        float v1 = acc[mi][nt][hf*2+1] + bv.y;
        float2 o;
        if (mode == 0){
          o = make_float2(v0, v1);
        } else if (mode == 1){
          o = make_float2(gelu_f(v0), gelu_f(v1));
        } else if (mode == 2){
          float2 rv = *(const float2*)(rrow + col);
          float2 av = *(const float2*)(xrow + col);
          o.x = rv.x + av.x*sigm_f(v0);
          o.y = rv.y + av.y*sigm_f(v1);
        } else {
          float2 rv = *(const float2*)(rrow + col);
          o = make_float2(rv.x + v0, rv.y + v1);
        }
        *(float2*)(crow + col) = o;
        if (S0){
          size_t gi = (size_t)row*Hdim + col;
          __nv_bfloat16 h0 = __float2bfloat16_rn(o.x);
          __nv_bfloat16 h1 = __float2bfloat16_rn(o.y);
          __nv_bfloat162 p; p.x = h0; p.y = h1;
          *(__nv_bfloat162*)(S0 + gi) = p;
          __nv_bfloat162 q;
          q.x = __float2bfloat16_rn(o.x - __bfloat162float(h0));
          q.y = __float2bfloat16_rn(o.y - __bfloat162float(h1));
          *(__nv_bfloat162*)(S1 + gi) = q;
        }
      }
    }
  }
}

// ----------------- host driver ----------------------------------------------
extern "C" void kernel_launch(void* const* d_in, const int* in_sizes, int n_in,
                              void* d_out, int out_size){
  (void)in_sizes; (void)n_in; (void)out_size;
  const float* x     = (const float*)d_in[0];
  const float* sLre  = (const float*)d_in[1];
  const float* sLim  = (const float*)d_in[2];
  const float* sPre  = (const float*)d_in[3];
  const float* sPim  = (const float*)d_in[4];
  const float* sBre  = (const float*)d_in[5];
  const float* sBim  = (const float*)d_in[6];
  const float* sCre  = (const float*)d_in[7];
  const float* sCim  = (const float*)d_in[8];
  const float* sD    = (const float*)d_in[9];
  const float* sLog  = (const float*)d_in[10];
  const float* sb_ls = (const float*)d_in[11];
  const float* sb_lb = (const float*)d_in[12];
  const float* sb_W1 = (const float*)d_in[13];
  const float* sb_b1 = (const float*)d_in[14];
  const float* sb_W2 = (const float*)d_in[15];
  const float* sb_b2 = (const float*)d_in[16];
  const float* bk_ls = (const float*)d_in[17];
  const float* bk_lb = (const float*)d_in[18];
  const float* bk_W1 = (const float*)d_in[19];
  const float* bk_b1 = (const float*)d_in[20];
  const float* bk_W2 = (const float*)d_in[21];
  const float* bk_b2 = (const float*)d_in[22];
  float* out = (float*)d_out;

  float *p_x, *p_z1;
  float2* p_kd;
  __nv_bfloat16 *p_a0, *p_a1, *p_b0, *p_b1, *p_wt0, *p_wt1;
  cudaGetSymbolAddress((void**)&p_x,   g_x);
  cudaGetSymbolAddress((void**)&p_z1,  g_z1);
  cudaGetSymbolAddress((void**)&p_kd,  g_KdL);
  cudaGetSymbolAddress((void**)&p_a0,  g_a0);
  cudaGetSymbolAddress((void**)&p_a1,  g_a1);
  cudaGetSymbolAddress((void**)&p_b0,  g_b0);
  cudaGetSymbolAddress((void**)&p_b1,  g_b1);
  cudaGetSymbolAddress((void**)&p_wt0, g_wt0);
  cudaGetSymbolAddress((void**)&p_wt1, g_wt1);

  cudaFuncSetAttribute(hgemm_kernel, cudaFuncAttributeMaxDynamicSharedMemorySize, SMEM_GEMM);
  cudaFuncSetAttribute(lnT_kernel,   cudaFuncAttributeMaxDynamicSharedMemorySize, LNT_SMEM);

  cudaStream_t s2;
  cudaStreamCreateWithFlags(&s2, cudaStreamNonBlocking);
  cudaEvent_t evStart, evKd[4], evW[4], evWB[2];
  cudaEventCreateWithFlags(&evStart, cudaEventDisableTiming);
  for (int i = 0; i < 4; i++){
    cudaEventCreateWithFlags(&evKd[i], cudaEventDisableTiming);
    cudaEventCreateWithFlags(&evW[i],  cudaEventDisableTiming);
  }
  for (int b = 0; b < 2; b++) cudaEventCreateWithFlags(&evWB[b], cudaEventDisableTiming);

  dim3 wgrid(16, 16);
  dim3 tblk(32, 8);
  dim3 tgrid(Hdim/32, Lseq/32, Bsz);
  dim3 lgrid(Lseq/32, Bsz);
  dim3 ggrid(Hdim/128, NROW/128);

  init_tw_kernel<<<8, 256>>>();
  cudaEventRecord(evStart, 0);
  cudaStreamWaitEvent(s2, evStart, 0);

  cauchy_kernel<<<dim3(Lseq/256, Hdim), 256, 0, s2>>>(
      sLre, sLim, sPre, sPim, sBre, sBim, sCre, sCim, sLog);
  lnT_kernel<<<lgrid, 256, LNT_SMEM>>>(x, sb_ls, sb_lb);
  kd_kernel<<<Hdim, 256, 0, s2>>>(p_kd);
  cudaEventRecord(evKd[0], s2);
  wprep_kernel<<<wgrid, tblk, 0, s2>>>(sb_W1, 0);
  wprep_kernel<<<wgrid, tblk, 0, s2>>>(sb_W2, 4);
  cudaEventRecord(evW[0], s2);
  for (int i = 1; i < 4; i++){
    cauchy_kernel<<<dim3(Lseq/256, Hdim), 256, 0, s2>>>(
        sLre + i*HN, sLim + i*HN, sPre + i*HN, sPim + i*HN,
        sBre + i*HN, sBim + i*HN, sCre + i*HN, sCim + i*HN, sLog + i*Hdim);
    kd_kernel<<<Hdim, 256, 0, s2>>>(p_kd + (size_t)i*KDSZ);
    cudaEventRecord(evKd[i], s2);
    wprep_kernel<<<wgrid, tblk, 0, s2>>>(sb_W1 + (size_t)i*HH, i);
    wprep_kernel<<<wgrid, tblk, 0, s2>>>(sb_W2 + (size_t)i*HH, 4 + i);
    cudaEventRecord(evW[i], s2);
  }
  for (int b = 0; b < 2; b++){
    wprep_kernel<<<wgrid, tblk, 0, s2>>>(bk_W1 + (size_t)b*HH, 8 + b);
    wprep_kernel<<<wgrid, tblk, 0, s2>>>(bk_W2 + (size_t)b*HH, 10 + b);
    cudaEventRecord(evWB[b], s2);
  }

  for (int b = 0; b < 2; b++){
    for (int li = 0; li < 2; li++){
      int i = b*2 + li;
      if (i > 0)
        lnT_kernel<<<lgrid, 256, LNT_SMEM>>>(p_x, sb_ls + i*Hdim, sb_lb + i*Hdim);
      cudaStreamWaitEvent(0, evKd[i], 0);
      conv_kernel<<<dim3(Hdim, Bsz), 256>>>(p_kd + (size_t)i*KDSZ, sD + i*Hdim);
      transpose_bwd_kernel<<<tgrid, tblk>>>();
      cudaStreamWaitEvent(0, evW[i], 0);
      hgemm_kernel<<<ggrid, 256, SMEM_GEMM>>>(p_a0, p_a1,
          p_wt0 + (size_t)i*HH, p_wt1 + (size_t)i*HH,
          sb_b1 + i*Hdim, p_z1, p_z1, p_z1, 0, nullptr, nullptr);
      const float* res = (i == 0) ? x : p_x;
      hgemm_kernel<<<ggrid, 256, SMEM_GEMM>>>(p_a0, p_a1,
          p_wt0 + (size_t)(4+i)*HH, p_wt1 + (size_t)(4+i)*HH,
          sb_b2 + i*Hdim, p_z1, res, p_x, 2, nullptr, nullptr);
    }
    ln_kernel<<<NROW/8, 256>>>(p_x, bk_ls + b*Hdim, bk_lb + b*Hdim);
    cudaStreamWaitEvent(0, evWB[b], 0);
    hgemm_kernel<<<ggrid, 256, SMEM_GEMM>>>(p_a0, p_a1,
        p_wt0 + (size_t)(8+b)*HH, p_wt1 + (size_t)(8+b)*HH,
        bk_b1 + b*Hdim, p_z1, p_z1, p_z1, 1, p_b0, p_b1);
    float* Cfinal = (b == 1) ? out : p_x;
    hgemm_kernel<<<ggrid, 256, SMEM_GEMM>>>(p_b0, p_b1,
        p_wt0 + (size_t)(10+b)*HH, p_wt1 + (size_t)(10+b)*HH,
        bk_b2 + b*Hdim, p_z1, p_x, Cfinal, 3, nullptr, nullptr);
  }
}

// round 17
// speedup vs baseline: 1.4401x; 1.0938x over previous
#include <cuda_runtime.h>
#include <cuda_bf16.h>
#include <cstdint>
#include <math.h>

#define Bsz   8
#define Lseq  2048
#define Hdim  512
#define Nst   64
#define NROW  (Bsz*Lseq)          // 16384
#define BLH   (Bsz*Lseq*Hdim)     // 8388608
#define HH    (Hdim*Hdim)
#define HN    (Hdim*Nst)
#define KDSZ  (Hdim*2049)

// ----------------- device scratch (no allocations allowed) ------------------
__device__ float  g_x [BLH];
__device__ float  g_ht[BLH];
__device__ float  g_yt[BLH];
__device__ float  g_z1[BLH];
__device__ float2 g_ar[Hdim*Lseq];
__device__ float2 g_KdL[4*KDSZ];
__device__ float2 g_twA[1024];
__device__ float2 g_twB[2048];
__device__ __nv_bfloat16 g_a0[BLH];
__device__ __nv_bfloat16 g_a1[BLH];
__device__ __nv_bfloat16 g_b0[BLH];
__device__ __nv_bfloat16 g_b1[BLH];
__device__ __nv_bfloat16 g_wt0[12*HH];
__device__ __nv_bfloat16 g_wt1[12*HH];

// ----------------- helpers --------------------------------------------------
__device__ __forceinline__ float2 cadd(float2 a, float2 b){ return make_float2(a.x+b.x, a.y+b.y); }
__device__ __forceinline__ float2 csub(float2 a, float2 b){ return make_float2(a.x-b.x, a.y-b.y); }
__device__ __forceinline__ float2 cmul(float2 a, float2 b){ return make_float2(a.x*b.x-a.y*b.y, a.x*b.y+a.y*b.x); }
__device__ __forceinline__ float frcp_fast(float x){ float y; asm("rcp.approx.f32 %0, %1;" : "=f"(y) : "f"(x)); return y; }
__device__ __forceinline__ float gelu_f(float x){
  float u = 0.7978845608028654f*(x + 0.044715f*x*x*x);
  float e = __expf(2.f*u);
  float t = 1.f - 2.f/(e + 1.f);          // tanh(u), saturates correctly
  return 0.5f*x*(1.0f + t);
}
__device__ __forceinline__ float sigm_f(float x){ return 1.0f/(1.0f + __expf(-x)); }

__device__ __forceinline__ uint32_t smem_u32(const void* p){
  uint32_t a;
  asm("{ .reg .u64 t; cvta.to.shared.u64 t, %1; cvt.u32.u64 %0, t; }" : "=r"(a) : "l"(p));
  return a;
}
__device__ __forceinline__ void cp16(uint32_t saddr, const void* g){
  asm volatile("cp.async.ca.shared.global [%0], [%1], 16;" :: "r"(saddr), "l"(g));
}
#define CP_COMMIT() asm volatile("cp.async.commit_group;" ::: "memory")

__device__ __forceinline__ void ldsm4(uint32_t* r, uint32_t addr){
  asm volatile("ldmatrix.sync.aligned.m8n8.x4.shared.b16 {%0,%1,%2,%3}, [%4];"
    : "=r"(r[0]), "=r"(r[1]), "=r"(r[2]), "=r"(r[3]) : "r"(addr));
}
__device__ __forceinline__ void mma16816(float* c, const uint32_t* a, const uint32_t* b){
  asm volatile("mma.sync.aligned.m16n8k16.row.col.f32.bf16.bf16.f32 "
    "{%0,%1,%2,%3}, {%4,%5,%6,%7}, {%8,%9}, {%0,%1,%2,%3};"
    : "+f"(c[0]), "+f"(c[1]), "+f"(c[2]), "+f"(c[3])
    : "r"(a[0]), "r"(a[1]), "r"(a[2]), "r"(a[3]), "r"(b[0]), "r"(b[1]));
}

// ----------------- twiddle init ---------------------------------------------
__global__ void init_tw_kernel(){
  int i = blockIdx.x*256 + threadIdx.x;
  if (i < 1024){
    float a = (float)(6.283185307179586/2048.0) * (float)i;
    float s, c; sincosf(a, &s, &c);
    g_twA[i] = make_float2(c, -s);
  }
  if (i < 2048){
    float a = (float)(3.141592653589793/2048.0) * (float)i;
    float s, c; sincosf(a, &s, &c);
    g_twB[i] = make_float2(c, -s);
  }
}

// ----------------- fused LN + transpose: xin (B,L,H) -> g_ht (B,H,L) --------
#define LNT_PAD  513
#define LNT_SMEM (32*LNT_PAD*4)   // 65664 bytes

__global__ __launch_bounds__(256) void lnT_kernel(const float* __restrict__ xin,
                                                  const float* __restrict__ sc,
                                                  const float* __restrict__ bi){
  extern __shared__ float tile[];      // [32][LNT_PAD]
  int b  = blockIdx.y;
  int l0 = blockIdx.x*32;
  int warp = threadIdx.x >> 5, lane = threadIdx.x & 31;
  const float4* s4 = (const float4*)sc;
  const float4* b4 = (const float4*)bi;
  #pragma unroll
  for (int r = warp; r < 32; r += 8){
    const float4* xr = (const float4*)(xin + ((size_t)b*Lseq + l0 + r)*Hdim);
    float4 v[4];
    float s = 0.f, s2 = 0.f;
    #pragma unroll
    for (int i = 0; i < 4; i++){
      float4 t = xr[lane + 32*i];
      v[i] = t;
      s  += t.x + t.y + t.z + t.w;
      s2 += t.x*t.x + t.y*t.y + t.z*t.z + t.w*t.w;
    }
    #pragma unroll
    for (int o = 16; o; o >>= 1){
      s  += __shfl_xor_sync(0xffffffffu, s,  o);
      s2 += __shfl_xor_sync(0xffffffffu, s2, o);
    }
    float mean = s*(1.f/Hdim);
    float var  = s2*(1.f/Hdim) - mean*mean;
    float inv  = rsqrtf(var + 1e-6f);
    float* trow = tile + r*LNT_PAD;
    #pragma unroll
    for (int i = 0; i < 4; i++){
      int ci = lane + 32*i;
      float4 sv = s4[ci], bv = b4[ci], t = v[i];
      trow[ci*4+0] = (t.x-mean)*inv*sv.x + bv.x;
      trow[ci*4+1] = (t.y-mean)*inv*sv.y + bv.y;
      trow[ci*4+2] = (t.z-mean)*inv*sv.z + bv.z;
      trow[ci*4+3] = (t.w-mean)*inv*sv.w + bv.w;
    }
  }
  __syncthreads();
  float* outb = g_ht + (size_t)b*Hdim*Lseq + l0 + lane;
  #pragma unroll 8
  for (int h0 = 0; h0 < Hdim; h0 += 8){
    int h = h0 + warp;
    outb[(size_t)h*Lseq] = tile[lane*LNT_PAD + h];
  }
}

// ----------------- layernorm (FFN path): xin -> bf16 splits only ------------
__global__ __launch_bounds__(256) void ln_kernel(const float* __restrict__ xin,
                                                 const float* __restrict__ sc,
                                                 const float* __restrict__ bi){
  int warp = threadIdx.x >> 5, lane = threadIdx.x & 31;
  size_t row = (size_t)blockIdx.x*8 + warp;
  const float4* xr = (const float4*)(xin + row*Hdim);
  float4 v[4];
  float s = 0.f, s2 = 0.f;
  #pragma unroll
  for (int i = 0; i < 4; i++){
    float4 t = xr[lane + 32*i];
    v[i] = t;
    s  += t.x + t.y + t.z + t.w;
    s2 += t.x*t.x + t.y*t.y + t.z*t.z + t.w*t.w;
  }
  #pragma unroll
  for (int o = 16; o; o >>= 1){
    s  += __shfl_xor_sync(0xffffffffu, s,  o);
    s2 += __shfl_xor_sync(0xffffffffu, s2, o);
  }
  float mean = s*(1.f/Hdim);
  float var  = s2*(1.f/Hdim) - mean*mean;
  float inv  = rsqrtf(var + 1e-6f);
  const float4* s4 = (const float4*)sc;
  const float4* b4 = (const float4*)bi;
  #pragma unroll
  for (int i = 0; i < 4; i++){
    int ci = lane + 32*i;
    float4 sv = s4[ci], bv = b4[ci], t = v[i], o;
    o.x = (t.x-mean)*inv*sv.x + bv.x;
    o.y = (t.y-mean)*inv*sv.y + bv.y;
    o.z = (t.z-mean)*inv*sv.z + bv.z;
    o.w = (t.w-mean)*inv*sv.w + bv.w;
    size_t gi = row*Hdim + ci*4;
    __nv_bfloat16 h0 = __float2bfloat16_rn(o.x);
    __nv_bfloat16 h1 = __float2bfloat16_rn(o.y);
    __nv_bfloat16 h2 = __float2bfloat16_rn(o.z);
    __nv_bfloat16 h3 = __float2bfloat16_rn(o.w);
    __nv_bfloat162 p0; p0.x = h0; p0.y = h1;
    __nv_bfloat162 p1; p1.x = h2; p1.y = h3;
    *(__nv_bfloat162*)(g_a0 + gi)     = p0;
    *(__nv_bfloat162*)(g_a0 + gi + 2) = p1;
    __nv_bfloat162 q0, q1;
    q0.x = __float2bfloat16_rn(o.x - __bfloat162float(h0));
    q0.y = __float2bfloat16_rn(o.y - __bfloat162float(h1));
    q1.x = __float2bfloat16_rn(o.z - __bfloat162float(h2));
    q1.y = __float2bfloat16_rn(o.w - __bfloat162float(h3));
    *(__nv_bfloat162*)(g_a1 + gi)     = q0;
    *(__nv_bfloat162*)(g_a1 + gi + 2) = q1;
  }
}

// ----------------- bwd transpose: g_yt (B,H,L) -> gelu -> bf16 splits -------
__global__ void transpose_bwd_kernel(){
  __shared__ float tile[32][33];
  int b  = blockIdx.z;
  int h0 = blockIdx.x*32;
  int l0 = blockIdx.y*32;
  int tx = threadIdx.x, ty = threadIdx.y;
  const float* in = g_yt + (size_t)b*Hdim*Lseq;
  #pragma unroll
  for (int j = 0; j < 32; j += 8)
    tile[ty+j][tx] = in[(size_t)(h0+ty+j)*Lseq + l0 + tx];
  __syncthreads();
  size_t boff = (size_t)b*Lseq*Hdim;
  #pragma unroll
  for (int j = 0; j < 32; j += 8){
    size_t idx = boff + (size_t)(l0+ty+j)*Hdim + h0 + tx;
    float g = gelu_f(tile[tx][ty+j]);
    __nv_bfloat16 hi = __float2bfloat16_rn(g);
    float r = g - __bfloat162float(hi);
    g_a0[idx] = hi;
    g_a1[idx] = __float2bfloat16_rn(r);
  }
}

// ----------------- weight transpose + split ----------------------------------
__global__ void wprep_kernel(const float* __restrict__ W, int widx){
  __shared__ float tile[32][33];
  int n0 = blockIdx.x*32, k0 = blockIdx.y*32;
  int tx = threadIdx.x, ty = threadIdx.y;
  #pragma unroll
  for (int j = 0; j < 32; j += 8)
    tile[ty+j][tx] = W[(size_t)(k0+ty+j)*Hdim + n0 + tx];
  __syncthreads();
  size_t base = (size_t)widx*HH;
  #pragma unroll
  for (int j = 0; j < 32; j += 8){
    float a = tile[tx][ty+j];
    size_t o = base + (size_t)(n0+ty+j)*Hdim + k0 + tx;
    __nv_bfloat16 hi = __float2bfloat16_rn(a);
    g_wt0[o] = hi;
    g_wt1[o] = __float2bfloat16_rn(a - __bfloat162float(hi));
  }
}

// ----------------- Cauchy kernel (prep fused in) -----------------------------
__global__ __launch_bounds__(256) void cauchy_kernel(
    const float* __restrict__ Lre, const float* __restrict__ Lim,
    const float* __restrict__ Pre, const float* __restrict__ Pim,
    const float* __restrict__ Bre, const float* __restrict__ Bim,
    const float* __restrict__ Cre, const float* __restrict__ Cim,
    const float* __restrict__ logstep){
  __shared__ float4 spk01[Nst];
  __shared__ float4 spk23[Nst];
  __shared__ float2 slam [Nst];
  __shared__ float  s2step;
  int tid = threadIdx.x;
  int h = blockIdx.y;
  int l = blockIdx.x*256 + tid;
  if (tid < Nst){
    int i = h*Nst + tid;
    float pr = Pre[i], pi = Pim[i];
    float br = Bre[i], bi = Bim[i];
    float cr = Cre[i], ci = Cim[i];
    spk01[tid] = make_float4(cr*br + ci*bi, cr*bi - ci*br,
                             cr*pr + ci*pi, cr*pi - ci*pr);
    spk23[tid] = make_float4(pr*br + pi*bi, pr*bi - pi*br,
                             pr*pr + pi*pi, 0.f);
    slam [tid] = make_float2(fminf(Lre[i], -1e-4f), Lim[i]);
  }
  if (tid == 0) s2step = 2.f*expf(-logstep[h]);
  __syncthreads();
  float t   = tanf((float)(3.141592653589793/2048.0)*(float)l);
  float gim = s2step*t;
  float k00r=0.f,k00i=0.f,k01r=0.f,k01i=0.f,k10r=0.f,k10i=0.f,k11r=0.f,k11i=0.f;
  #pragma unroll 8
  for (int n = 0; n < Nst; n++){
    float2 lam = slam[n];
    float dre = -lam.x;
    float dim = gim - lam.y;
    float inv = frcp_fast(dre*dre + dim*dim);
    float ir  =  dre*inv;
    float ii  = -dim*inv;
    float4 w01 = spk01[n];
    float4 w23 = spk23[n];
    k00r += w01.x*ir - w01.y*ii;  k00i += w01.x*ii + w01.y*ir;
    k01r += w01.z*ir - w01.w*ii;  k01i += w01.z*ii + w01.w*ir;
    k10r += w23.x*ir - w23.y*ii;  k10i += w23.x*ii + w23.y*ir;
    k11r += w23.z*ir;             k11i += w23.z*ii;
  }
  float denr = 1.f + k11r, deni = k11i;
  float dinv = frcp_fast(denr*denr + deni*deni);
  float qr = denr*dinv, qi = -deni*dinv;
  float mr = k01r*k10r - k01i*k10i;
  float mi = k01r*k10i + k01i*k10r;
  float cr = mr*qr - mi*qi, ci2 = mr*qi + mi*qr;
  float ar = k00r - cr, ai = k00i - ci2;
  g_ar[(size_t)h*Lseq + l] = make_float2(ar - t*ai, ai + t*ar);
}

// ----------------- shared-mem radix-8 Stockham FFT(2048) ---------------------
template<bool INV, bool ZTOP, bool HALFOUT>
__device__ __forceinline__ float2* fft2048_r8(float2* buf0, float2* buf1,
                                              const float2* __restrict__ stw, int tid){
  const float C2 = 0.7071067811865476f;
  float2* src = buf0; float2* dst = buf1;
  #pragma unroll
  for (int st = 0; st < 3; st++){
    int s = 1 << (3*st);            // 1, 8, 64
    __syncthreads();
    int idx = tid;
    int sp  = idx & ~(s-1);
    float2 e0, e1, e2, e3, o0, o1, o2, o3;
    if (ZTOP && st == 0){
      float2 a0 = src[idx      ];
      float2 a1 = src[idx + 256];
      float2 a2 = src[idx + 512];
      float2 a3 = src[idx + 768];
      e0 = cadd(a0,a2); e2 = csub(a0,a2);
      o0 = cadd(a1,a3); o2 = csub(a1,a3);
      if (!INV){
        e1 = make_float2(a0.x + a2.y, a0.y - a2.x);
        e3 = make_float2(a0.x - a2.y, a0.y + a2.x);
        o1 = make_float2(a1.x + a3.y, a1.y - a3.x);
        o3 = make_float2(a1.x - a3.y, a1.y + a3.x);
      } else {
        e1 = make_float2(a0.x - a2.y, a0.y + a2.x);
        e3 = make_float2(a0.x + a2.y, a0.y - a2.x);
        o1 = make_float2(a1.x - a3.y, a1.y + a3.x);
        o3 = make_float2(a1.x + a3.y, a1.y - a3.x);
      }
    } else {
      float2 a0 = src[idx       ];
      float2 a1 = src[idx +  256];
      float2 a2 = src[idx +  512];
      float2 a3 = src[idx +  768];
      float2 a4 = src[idx + 1024];
      float2 a5 = src[idx + 1280];
      float2 a6 = src[idx + 1536];
      float2 a7 = src[idx + 1792];
      float2 t0 = cadd(a0,a4), t1 = csub(a0,a4);
      float2 t2 = cadd(a2,a6), t3 = csub(a2,a6);
      e0 = cadd(t0,t2); e2 = csub(t0,t2);
      float2 u0 = cadd(a1,a5), u1 = csub(a1,a5);
      float2 u2 = cadd(a3,a7), u3 = csub(a3,a7);
      o0 = cadd(u0,u2); o2 = csub(u0,u2);
      if (!INV){
        e1 = make_float2(t1.x + t3.y, t1.y - t3.x);
        e3 = make_float2(t1.x - t3.y, t1.y + t3.x);
        o1 = make_float2(u1.x + u3.y, u1.y - u3.x);
        o3 = make_float2(u1.x - u3.y, u1.y + u3.x);
      } else {
        e1 = make_float2(t1.x - t3.y, t1.y + t3.x);
        e3 = make_float2(t1.x + t3.y, t1.y - t3.x);
        o1 = make_float2(u1.x - u3.y, u1.y + u3.x);
        o3 = make_float2(u1.x + u3.y, u1.y - u3.x);
      }
    }
    float2 m1, m2, m3;
    if (!INV){
      m1 = make_float2(C2*(o1.x + o1.y), C2*(o1.y - o1.x));
      m2 = make_float2(o2.y, -o2.x);
      m3 = make_float2(C2*(o3.y - o3.x), -C2*(o3.x + o3.y));
    } else {
      m1 = make_float2(C2*(o1.x - o1.y), C2*(o1.x + o1.y));
      m2 = make_float2(-o2.y, o2.x);
      m3 = make_float2(-C2*(o3.x + o3.y), C2*(o3.x - o3.y));
    }
    float2 B0 = cadd(e0,o0), B4 = csub(e0,o0);
    float2 B1 = cadd(e1,m1), B5 = csub(e1,m1);
    float2 B2 = cadd(e2,m2), B6 = csub(e2,m2);
    float2 B3 = cadd(e3,m3), B7 = csub(e3,m3);
    float2 w1 = stw[sp], w2 = stw[2*sp], w4 = stw[4*sp];
    if (INV){ w1.y = -w1.y; w2.y = -w2.y; w4.y = -w4.y; }
    float2 w3 = cmul(w1,w2);
    float2 w5 = cmul(w1,w4);
    float2 w6 = cmul(w2,w4);
    float2 w7 = cmul(w3,w4);
    int j = idx + 7*sp;
    dst[j      ] = B0;
    dst[j +   s] = cmul(B1,w1);
    dst[j + 2*s] = cmul(B2,w2);
    dst[j + 3*s] = cmul(B3,w3);
    dst[j + 4*s] = cmul(B4,w4);
    dst[j + 5*s] = cmul(B5,w5);
    dst[j + 6*s] = cmul(B6,w6);
    dst[j + 7*s] = cmul(B7,w7);
    float2* tp = src; src = dst; dst = tp;
  }
  __syncthreads();
  #pragma unroll
  for (int i = 0; i < 2; i++){
    int idx = tid + 256*i;
    float2 a0 = src[idx];
    float2 a1 = src[idx + 512];
    float2 a2 = src[idx + 1024];
    float2 a3 = src[idx + 1536];
    float2 t0 = cadd(a0,a2), t1 = csub(a0,a2);
    float2 t2 = cadd(a1,a3), t3 = csub(a1,a3);
    float2 b0 = cadd(t0,t2);
    dst[idx] = b0;
    float2 b1;
    if (!INV) b1 = make_float2(t1.x + t3.y, t1.y - t3.x);
    else      b1 = make_float2(t1.x - t3.y, t1.y + t3.x);
    dst[idx + 512] = b1;
    if (!HALFOUT){
      float2 b2 = csub(t0,t2);
      float2 b3;
      if (!INV) b3 = make_float2(t1.x - t3.y, t1.y + t3.x);
      else      b3 = make_float2(t1.x + t3.y, t1.y - t3.x);
      dst[idx + 1024] = b2;
      dst[idx + 1536] = b3;
    }
  }
  float2* tp = src; src = dst; dst = tp;
  __syncthreads();
  return src;
}

// ----------------- Kd kernel ------------------------------------------------
__global__ __launch_bounds__(256) void kd_kernel(float2* __restrict__ Kd){
  __shared__ float2 sA[2048];
  __shared__ float2 sB[2048];
  int tid = threadIdx.x;
  int h = blockIdx.x;
  const float2* ar = g_ar + (size_t)h*Lseq;
  #pragma unroll
  for (int i = 0; i < 8; i++){ int k = tid + 256*i; sA[k] = ar[k]; }
  float2* K = fft2048_r8<true,false,false>(sA, sB, g_twA, tid);
  float2* Ob = (K == sA) ? sB : sA;
  const float sc = 1.f/2048.f;
  #pragma unroll
  for (int i = 0; i < 4; i++){
    int n = tid + 256*i;
    Ob[n] = make_float2(K[2*n].x*sc, K[2*n+1].x*sc);
  }
  float2* Zp = fft2048_r8<false,true,false>(Ob, K, g_twA, tid);
  float2* outKd = Kd + (size_t)h*2049;
  #pragma unroll
  for (int i = 0; i < 8; i++){
    int k  = tid + 256*i;
    int kc = (2048 - k) & 2047;
    float2 zk = Zp[k], zc = Zp[kc];
    float2 E  = make_float2(0.5f*(zk.x+zc.x),  0.5f*(zk.y-zc.y));
    float2 Od = make_float2(0.5f*(zk.y+zc.y), -0.5f*(zk.x-zc.x));
    outKd[k] = cadd(E, cmul(g_twB[k], Od));
  }
  if (tid == 0){
    float2 z0 = Zp[0];
    outKd[2048] = make_float2(z0.x - z0.y, 0.f);
  }
}

// ----------------- conv kernel (fused untangle*Kd*retangle, fused D) ---------
__global__ __launch_bounds__(256) void conv_kernel(const float2* __restrict__ Kdbase,
                                                   const float* __restrict__ Dp){
  __shared__ float2 sA[2048];
  __shared__ float2 sB[2048];
  int tid = threadIdx.x;
  int h = blockIdx.x;
  int b = blockIdx.y;
  const float* u = g_ht + ((size_t)b*Hdim + h)*Lseq;
  float ur[8];
  #pragma unroll
  for (int i = 0; i < 4; i++){
    int n = tid + 256*i;
    float u0 = u[2*n], u1 = u[2*n+1];
    ur[2*i] = u0; ur[2*i+1] = u1;
    sA[n] = make_float2(u0, u1);
  }
  float2* Z = fft2048_r8<false,true,false>(sA, sB, g_twA, tid);
  float2* O = (Z == sA) ? sB : sA;
  const float2* kd = Kdbase + (size_t)h*2049;
  #pragma unroll
  for (int i = 0; i < 4; i++){
    int k = tid + 256*i;
    if (k == 0){
      float2 z0 = Z[0];
      float U0 = z0.x + z0.y;
      float U2 = z0.x - z0.y;
      float2 k0 = kd[0], k2 = kd[2048];
      float2 Y0 = make_float2(U0*k0.x, U0*k0.y);
      float2 Y2 = make_float2(U2*k2.x, U2*k2.y);
      float2 Ey = make_float2(0.5f*(Y0.x+Y2.x), 0.5f*(Y0.y-Y2.y));
      float2 Dm = make_float2(0.5f*(Y0.x-Y2.x), 0.5f*(Y0.y+Y2.y));
      O[0] = make_float2(Ey.x - Dm.y, Ey.y + Dm.x);
      float2 zm = Z[1024];
      float2 Um = make_float2(zm.x, -zm.y);
      float2 Ym = cmul(Um, kd[1024]);
      O[1024] = make_float2(Ym.x, -Ym.y);
    } else {
      int kc = 2048 - k;
      float2 zk = Z[k], zc = Z[kc];
      float2 E  = make_float2(0.5f*(zk.x+zc.x),  0.5f*(zk.y-zc.y));
      float2 Od = make_float2(0.5f*(zk.y+zc.y), -0.5f*(zk.x-zc.x));
      float2 tk = g_twB[k];
      float2 P  = cmul(tk, Od);
      float2 Uk = cadd(E, P);
      float2 EmP = csub(E, P);
      float2 Uc = make_float2(EmP.x, -EmP.y);
      float2 Yk = cmul(Uk, kd[k]);
      float2 Yc = cmul(Uc, kd[kc]);
      float2 Ey = make_float2(0.5f*(Yk.x+Yc.x), 0.5f*(Yk.y-Yc.y));
      float2 Dm = make_float2(0.5f*(Yk.x-Yc.x), 0.5f*(Yk.y+Yc.y));
      float2 Oy = cmul(Dm, make_float2(tk.x, -tk.y));
      O[k]  = make_float2(Ey.x - Oy.y,  Ey.y + Oy.x);
      O[kc] = make_float2(Ey.x + Oy.y, -Ey.y + Oy.x);
    }
  }
  float2* w = fft2048_r8<true,false,true>(O, Z, g_twA, tid);
  float* out = g_yt + ((size_t)b*Hdim + h)*Lseq;
  const float sc = 1.f/2048.f;
  float Dh = Dp[h];
  #pragma unroll
  for (int i = 0; i < 4; i++){
    int n = tid + 256*i;
    float2 v = w[n];
    out[2*n]   = v.x*sc + Dh*ur[2*i];
    out[2*n+1] = v.y*sc + Dh*ur[2*i+1];
  }
}

// ----------------- HMMA GEMM common pieces -----------------------------------
#define TROW    80
#define TBYTES  (128*TROW)
#define STAGEB  (4*TBYTES)
#define SMEM_GEMM (2*STAGEB)            // 81920
#define SMEM_GLU  (2*STAGEB + 128*128*4)  // +64KB sig = 147456

// shared chunk-loop body: accumulates A*B^T over K=512 into acc
__device__ __forceinline__ void hgemm_loop(
    uint32_t sb, int tid, int mw, int nw,
    int lrow, int lc0, int arow, int aoff, int brow, int boff,
    int bm, int bn,
    const __nv_bfloat16* __restrict__ A0g, const __nv_bfloat16* __restrict__ A1g,
    const __nv_bfloat16* __restrict__ B0g, const __nv_bfloat16* __restrict__ B1g,
    float acc[2][8][4])
{
  #pragma unroll
  for (int j = 0; j < 2; j++){
    int c = lc0 + 2*j;
    uint32_t so = (uint32_t)lrow*TROW + (uint32_t)c*16;
    size_t ga = (size_t)(bm + lrow)*Hdim + c*8;
    size_t gb = (size_t)(bn + lrow)*Hdim + c*8;
    cp16(sb + so,             A0g + ga);
    cp16(sb + TBYTES   + so,  A1g + ga);
    cp16(sb + 2*TBYTES + so,  B0g + gb);
    cp16(sb + 3*TBYTES + so,  B1g + gb);
  }
  CP_COMMIT();

  for (int ch = 0; ch < 16; ch++){
    int st = ch & 1;
    if (ch < 15){
      uint32_t sbase = sb + (st^1)*STAGEB;
      int k0 = (ch+1)*32;
      #pragma unroll
      for (int j = 0; j < 2; j++){
        int c = lc0 + 2*j;
        uint32_t so = (uint32_t)lrow*TROW + (uint32_t)c*16;
        size_t ga = (size_t)(bm + lrow)*Hdim + k0 + c*8;
        size_t gb = (size_t)(bn + lrow)*Hdim + k0 + c*8;
        cp16(sbase + so,             A0g + ga);
        cp16(sbase + TBYTES   + so,  A1g + ga);
        cp16(sbase + 2*TBYTES + so,  B0g + gb);
        cp16(sbase + 3*TBYTES + so,  B1g + gb);
      }
      CP_COMMIT();
      asm volatile("cp.async.wait_group 1;" ::: "memory");
    } else {
      asm volatile("cp.async.wait_group 0;" ::: "memory");
    }
    __syncthreads();

    uint32_t sA0 = sb + st*STAGEB;
    uint32_t sA1 = sA0 + TBYTES;
    uint32_t sB0 = sA0 + 2*TBYTES;
    uint32_t sB1 = sA0 + 3*TBYTES;
    #pragma unroll
    for (int ks = 0; ks < 2; ks++){
      int kb = ks*32;
      uint32_t a0f[2][4], a1f[2][4], b0f[4][4], b1f[4][4];
      #pragma unroll
      for (int mi = 0; mi < 2; mi++){
        uint32_t ro = (uint32_t)(mw*32 + mi*16 + arow)*TROW + kb + aoff;
        ldsm4(a0f[mi], sA0 + ro);
        ldsm4(a1f[mi], sA1 + ro);
      }
      #pragma unroll
      for (int nj = 0; nj < 4; nj++){
        uint32_t ro = (uint32_t)(nw*64 + nj*16 + brow)*TROW + kb + boff;
        ldsm4(b0f[nj], sB0 + ro);
        ldsm4(b1f[nj], sB1 + ro);
      }
      #pragma unroll
      for (int mi = 0; mi < 2; mi++){
        #pragma unroll
        for (int nt = 0; nt < 8; nt++){
          int nj = nt >> 1, sub = (nt & 1)*2;
          mma16816(acc[mi][nt], a0f[mi], &b0f[nj][sub]);
          mma16816(acc[mi][nt], a1f[mi], &b0f[nj][sub]);
          mma16816(acc[mi][nt], a0f[mi], &b1f[nj][sub]);
        }
      }
    }
    __syncthreads();
  }
}

// ----------------- generic GEMM (FFN path): modes 1,3 ------------------------
// mode 1: gelu(acc+bias) -> splits only (no C store)   mode 3: C = resid + acc+bias
__global__ __launch_bounds__(256) void hgemm_kernel(
    const __nv_bfloat16* __restrict__ A0g, const __nv_bfloat16* __restrict__ A1g,
    const __nv_bfloat16* __restrict__ B0g, const __nv_bfloat16* __restrict__ B1g,
    const float* __restrict__ bias,
    const float* __restrict__ resid,
    float* __restrict__ C, int mode,
    __nv_bfloat16* __restrict__ S0, __nv_bfloat16* __restrict__ S1)
{
  extern __shared__ char smem[];
  uint32_t sb = smem_u32(smem);
  int tid = threadIdx.x, wid = tid >> 5, lid = tid & 31;
  int bn = blockIdx.x*128, bm = blockIdx.y*128;
  int mw = wid & 3, nw = wid >> 2;
  int lrow = tid >> 1, lc0 = tid & 1;
  int arow = lid & 15;
  int aoff = (lid >> 4) * 16;
  int brow = ((lid >> 4) << 3) + (lid & 7);
  int boff = ((lid >> 3) & 1) * 16;

  float acc[2][8][4];
  #pragma unroll
  for (int i = 0; i < 2; i++)
    #pragma unroll
    for (int j = 0; j < 8; j++)
      #pragma unroll
      for (int q = 0; q < 4; q++) acc[i][j][q] = 0.f;

  hgemm_loop(sb, tid, mw, nw, lrow, lc0, arow, aoff, brow, boff,
             bm, bn, A0g, A1g, B0g, B1g, acc);

  int qr = lid >> 2, qc = (lid & 3)*2;
  #pragma unroll
  for (int mi = 0; mi < 2; mi++){
    #pragma unroll
    for (int hf = 0; hf < 2; hf++){
      int row = bm + mw*32 + mi*16 + hf*8 + qr;
      float* crow = C + (size_t)row*Hdim;
      const float* rrow = resid + (size_t)row*Hdim;
      #pragma unroll
      for (int nt = 0; nt < 8; nt++){
        int col = bn + nw*64 + nt*8 + qc;
        float2 bv = *(const float2*)(bias + col);
        float v0 = acc[mi][nt][hf*2+0] + bv.x;
        float v1 = acc[mi][nt][hf*2+1] + bv.y;
        float2 o;
        if (mode == 1){
          o = make_float2(gelu_f(v0), gelu_f(v1));
        } else {
          float2 rv = *(const float2*)(rrow + col);
          o = make_float2(rv.x + v0, rv.y + v1);
        }
        if (mode != 1) *(float2*)(crow + col) = o;   // mode-1 fp32 store is dead
        if (S0){
          size_t gi = (size_t)row*Hdim + col;
          __nv_bfloat16 h0 = __float2bfloat16_rn(o.x);
          __nv_bfloat16 h1 = __float2bfloat16_rn(o.y);
          __nv_bfloat162 p; p.x = h0; p.y = h1;
          *(__nv_bfloat162*)(S0 + gi) = p;
          __nv_bfloat162 q;
          q.x = __float2bfloat16_rn(o.x - __bfloat162float(h0));
          q.y = __float2bfloat16_rn(o.y - __bfloat162float(h1));
          *(__nv_bfloat162*)(S1 + gi) = q;
        }
      }
    }
  }
}

// ----------------- fused GLU GEMM: x = resid + (A@W1+b1)*sigmoid(A@W2+b2) ----
__global__ __launch_bounds__(256) void hgemm_glu_kernel(
    const __nv_bfloat16* __restrict__ A0g, const __nv_bfloat16* __restrict__ A1g,
    const __nv_bfloat16* __restrict__ W10, const __nv_bfloat16* __restrict__ W11,
    const __nv_bfloat16* __restrict__ W20, const __nv_bfloat16* __restrict__ W21,
    const float* __restrict__ b1, const float* __restrict__ b2,
    const float* __restrict__ resid, float* __restrict__ C)
{
  extern __shared__ char smem[];
  uint32_t sb = smem_u32(smem);
  float* sig = (float*)(smem + 2*STAGEB);   // [128][128] fp32
  int tid = threadIdx.x, wid = tid >> 5, lid = tid & 31;
  int bn = blockIdx.x*128, bm = blockIdx.y*128;
  int mw = wid & 3, nw = wid >> 2;
  int lrow = tid >> 1, lc0 = tid & 1;
  int arow = lid & 15;
  int aoff = (lid >> 4) * 16;
  int brow = ((lid >> 4) << 3) + (lid & 7);
  int boff = ((lid >> 3) & 1) * 16;
  int qr = lid >> 2, qc = (lid & 3)*2;

  float acc[2][8][4];

  // ---- pass 1: z2 = A@W2 -> sig = sigmoid(z2+b2) in smem ----
  #pragma unroll
  for (int i = 0; i < 2; i++)
    #pragma unroll
    for (int j = 0; j < 8; j++)
      #pragma unroll
      for (int q = 0; q < 4; q++) acc[i][j][q] = 0.f;
  hgemm_loop(sb, tid, mw, nw, lrow, lc0, arow, aoff, brow, boff,
             bm, bn, A0g, A1g, W20, W21, acc);
  #pragma unroll
  for (int mi = 0; mi < 2; mi++){
    #pragma unroll
    for (int hf = 0; hf < 2; hf++){
      int rl = mw*32 + mi*16 + hf*8 + qr;
      #pragma unroll
      for (int nt = 0; nt < 8; nt++){
        int cl = nw*64 + nt*8 + qc;
        float2 bv = *(const float2*)(b2 + bn + cl);
        float v0 = acc[mi][nt][hf*2+0] + bv.x;
        float v1 = acc[mi][nt][hf*2+1] + bv.y;
        *(float2*)(sig + rl*128 + cl) = make_float2(sigm_f(v0), sigm_f(v1));
      }
    }
  }

  // ---- pass 2: z1 = A@W1 -> C = resid + (z1+b1)*sig ----
  #pragma unroll
  for (int i = 0; i < 2; i++)
    #pragma unroll
    for (int j = 0; j < 8; j++)
      #pragma unroll
      for (int q = 0; q < 4; q++) acc[i][j][q] = 0.f;
  hgemm_loop(sb, tid, mw, nw, lrow, lc0, arow, aoff, brow, boff,
             bm, bn, A0g, A1g, W10, W11, acc);
  #pragma unroll
  for (int mi = 0; mi < 2; mi++){
    #pragma unroll
    for (int hf = 0; hf < 2; hf++){
      int rl = mw*32 + mi*16 + hf*8 + qr;
      int row = bm + rl;
      float* crow = C + (size_t)row*Hdim;
      const float* rrow = resid + (size_t)row*Hdim;
      #pragma unroll
      for (int nt = 0; nt < 8; nt++){
        int cl = nw*64 + nt*8 + qc;
        int col = bn + cl;
        float2 bv = *(const float2*)(b1 + col);
        float2 sv = *(const float2*)(sig + rl*128 + cl);
        float2 rv = *(const float2*)(rrow + col);
        float v0 = acc[mi][nt][hf*2+0] + bv.x;
        float v1 = acc[mi][nt][hf*2+1] + bv.y;
        float2 o = make_float2(rv.x + v0*sv.x, rv.y + v1*sv.y);
        *(float2*)(crow + col) = o;
      }
    }
  }
}

// ----------------- host driver ----------------------------------------------
extern "C" void kernel_launch(void* const* d_in, const int* in_sizes, int n_in,
                              void* d_out, int out_size){
  (void)in_sizes; (void)n_in; (void)out_size;
  const float* x     = (const float*)d_in[0];
  const float* sLre  = (const float*)d_in[1];
  const float* sLim  = (const float*)d_in[2];
  const float* sPre  = (const float*)d_in[3];
  const float* sPim  = (const float*)d_in[4];
  const float* sBre  = (const float*)d_in[5];
  const float* sBim  = (const float*)d_in[6];
  const float* sCre  = (const float*)d_in[7];
  const float* sCim  = (const float*)d_in[8];
  const float* sD    = (const float*)d_in[9];
  const float* sLog  = (const float*)d_in[10];
  const float* sb_ls = (const float*)d_in[11];
  const float* sb_lb = (const float*)d_in[12];
  const float* sb_W1 = (const float*)d_in[13];
  const float* sb_b1 = (const float*)d_in[14];
  const float* sb_W2 = (const float*)d_in[15];
  const float* sb_b2 = (const float*)d_in[16];
  const float* bk_ls = (const float*)d_in[17];
  const float* bk_lb = (const float*)d_in[18];
  const float* bk_W1 = (const float*)d_in[19];
  const float* bk_b1 = (const float*)d_in[20];
  const float* bk_W2 = (const float*)d_in[21];
  const float* bk_b2 = (const float*)d_in[22];
  float* out = (float*)d_out;

  float *p_x, *p_z1;
  float2* p_kd;
  __nv_bfloat16 *p_a0, *p_a1, *p_b0, *p_b1, *p_wt0, *p_wt1;
  cudaGetSymbolAddress((void**)&p_x,   g_x);
  cudaGetSymbolAddress((void**)&p_z1,  g_z1);
  cudaGetSymbolAddress((void**)&p_kd,  g_KdL);
  cudaGetSymbolAddress((void**)&p_a0,  g_a0);
  cudaGetSymbolAddress((void**)&p_a1,  g_a1);
  cudaGetSymbolAddress((void**)&p_b0,  g_b0);
  cudaGetSymbolAddress((void**)&p_b1,  g_b1);
  cudaGetSymbolAddress((void**)&p_wt0, g_wt0);
  cudaGetSymbolAddress((void**)&p_wt1, g_wt1);

  cudaFuncSetAttribute(hgemm_kernel,     cudaFuncAttributeMaxDynamicSharedMemorySize, SMEM_GEMM);
  cudaFuncSetAttribute(hgemm_glu_kernel, cudaFuncAttributeMaxDynamicSharedMemorySize, SMEM_GLU);
  cudaFuncSetAttribute(lnT_kernel,       cudaFuncAttributeMaxDynamicSharedMemorySize, LNT_SMEM);

  cudaStream_t s2;
  cudaStreamCreateWithFlags(&s2, cudaStreamNonBlocking);
  cudaEvent_t evStart, evKd[4], evW[4], evWB[2];
  cudaEventCreateWithFlags(&evStart, cudaEventDisableTiming);
  for (int i = 0; i < 4; i++){
    cudaEventCreateWithFlags(&evKd[i], cudaEventDisableTiming);
    cudaEventCreateWithFlags(&evW[i],  cudaEventDisableTiming);
  }
  for (int b = 0; b < 2; b++) cudaEventCreateWithFlags(&evWB[b], cudaEventDisableTiming);

  dim3 wgrid(16, 16);
  dim3 tblk(32, 8);
  dim3 tgrid(Hdim/32, Lseq/32, Bsz);
  dim3 lgrid(Lseq/32, Bsz);
  dim3 ggrid(Hdim/128, NROW/128);

  init_tw_kernel<<<8, 256>>>();
  cudaEventRecord(evStart, 0);
  cudaStreamWaitEvent(s2, evStart, 0);

  cauchy_kernel<<<dim3(Lseq/256, Hdim), 256, 0, s2>>>(
      sLre, sLim, sPre, sPim, sBre, sBim, sCre, sCim, sLog);
  lnT_kernel<<<lgrid, 256, LNT_SMEM>>>(x, sb_ls, sb_lb);
  kd_kernel<<<Hdim, 256, 0, s2>>>(p_kd);
  cudaEventRecord(evKd[0], s2);
  wprep_kernel<<<wgrid, tblk, 0, s2>>>(sb_W1, 0);
  wprep_kernel<<<wgrid, tblk, 0, s2>>>(sb_W2, 4);
  cudaEventRecord(evW[0], s2);
  for (int i = 1; i < 4; i++){
    cauchy_kernel<<<dim3(Lseq/256, Hdim), 256, 0, s2>>>(
        sLre + i*HN, sLim + i*HN, sPre + i*HN, sPim + i*HN,
        sBre + i*HN, sBim + i*HN, sCre + i*HN, sCim + i*HN, sLog + i*Hdim);
    kd_kernel<<<Hdim, 256, 0, s2>>>(p_kd + (size_t)i*KDSZ);
    cudaEventRecord(evKd[i], s2);
    wprep_kernel<<<wgrid, tblk, 0, s2>>>(sb_W1 + (size_t)i*HH, i);
    wprep_kernel<<<wgrid, tblk, 0, s2>>>(sb_W2 + (size_t)i*HH, 4 + i);
    cudaEventRecord(evW[i], s2);
  }
  for (int b = 0; b < 2; b++){
    wprep_kernel<<<wgrid, tblk, 0, s2>>>(bk_W1 + (size_t)b*HH, 8 + b);
    wprep_kernel<<<wgrid, tblk, 0, s2>>>(bk_W2 + (size_t)b*HH, 10 + b);
    cudaEventRecord(evWB[b], s2);
  }

  for (int b = 0; b < 2; b++){
    for (int li = 0; li < 2; li++){
      int i = b*2 + li;
      if (i > 0)
        lnT_kernel<<<lgrid, 256, LNT_SMEM>>>(p_x, sb_ls + i*Hdim, sb_lb + i*Hdim);
      cudaStreamWaitEvent(0, evKd[i], 0);
      conv_kernel<<<dim3(Hdim, Bsz), 256>>>(p_kd + (size_t)i*KDSZ, sD + i*Hdim);
      transpose_bwd_kernel<<<tgrid, tblk>>>();
      cudaStreamWaitEvent(0, evW[i], 0);
      const float* res = (i == 0) ? x : p_x;
      hgemm_glu_kernel<<<ggrid, 256, SMEM_GLU>>>(p_a0, p_a1,
          p_wt0 + (size_t)i*HH,     p_wt1 + (size_t)i*HH,      // W1 split
          p_wt0 + (size_t)(4+i)*HH, p_wt1 + (size_t)(4+i)*HH,  // W2 split
          sb_b1 + i*Hdim, sb_b2 + i*Hdim, res, p_x);
    }
    ln_kernel<<<NROW/8, 256>>>(p_x, bk_ls + b*Hdim, bk_lb + b*Hdim);
    cudaStreamWaitEvent(0, evWB[b], 0);
    hgemm_kernel<<<ggrid, 256, SMEM_GEMM>>>(p_a0, p_a1,
        p_wt0 + (size_t)(8+b)*HH, p_wt1 + (size_t)(8+b)*HH,
        bk_b1 + b*Hdim, p_z1, p_z1, 1, p_b0, p_b1);
    float* Cfinal = (b == 1) ? out : p_x;
    hgemm_kernel<<<ggrid, 256, SMEM_GEMM>>>(p_b0, p_b1,
        p_wt0 + (size_t)(10+b)*HH, p_wt1 + (size_t)(10+b)*HH,
        bk_b2 + b*Hdim, p_x, Cfinal, 3, nullptr, nullptr);
  }
}